// round 8
// baseline (speedup 1.0000x reference)
#include <cuda_runtime.h>
#include <cuda_bf16.h>
#include <math.h>
#include <stdint.h>

#define TSEQ   2048
#define DMODEL 2048
#define NH     16
#define DHEAD  128
#define DROPE  64
#define DCONT  64
#define SCALE_ATT 0.08838834764831845f  /* 1/sqrt(128) */

/* ------------------------------------------------------------------ */
/* Scratch (device globals)                                            */
/* ------------------------------------------------------------------ */
__device__ float g_qc[TSEQ * 1024];
__device__ float g_qr[TSEQ * 1024];
__device__ float g_kc[TSEQ * 1024];
__device__ float g_kr[TSEQ * 1024];
__device__ float g_cosT[TSEQ * 32];
__device__ float g_sinT[TSEQ * 32];

/* attention operands, bf16 hi/lo, [h][t][d] */
__device__ __nv_bfloat16 g_Qh[NH * TSEQ * DHEAD], g_Ql[NH * TSEQ * DHEAD];
__device__ __nv_bfloat16 g_Kh[NH * TSEQ * DHEAD], g_Kl[NH * TSEQ * DHEAD];
__device__ __nv_bfloat16 g_Vh[NH * TSEQ * DHEAD], g_Vl[NH * TSEQ * DHEAD];

/* bf16 hi/lo split operands for GEMMs */
__device__ __nv_bfloat16 g_xh[TSEQ * 2048],  g_xl[TSEQ * 2048];
__device__ __nv_bfloat16 g_qdh[TSEQ * 512],  g_qdl[TSEQ * 512];
__device__ __nv_bfloat16 g_kvh[TSEQ * 512],  g_kvl[TSEQ * 512];
__device__ __nv_bfloat16 g_Oh[TSEQ * 2048],  g_Ol[TSEQ * 2048];
__device__ __nv_bfloat16 g_wqdh[2048 * 512], g_wqdl[2048 * 512];
__device__ __nv_bfloat16 g_wquh[512 * 1024], g_wqul[512 * 1024];
__device__ __nv_bfloat16 g_wqrh[2048 * 1024],g_wqrl[2048 * 1024];
__device__ __nv_bfloat16 g_wkdh[2048 * 512], g_wkdl[2048 * 512];
__device__ __nv_bfloat16 g_wkuh[512 * 1024], g_wkul[512 * 1024];
__device__ __nv_bfloat16 g_wvuh[512 * 2048], g_wvul[512 * 2048];
__device__ __nv_bfloat16 g_wkrh[2048 * 1024],g_wkrl[2048 * 1024];
__device__ __nv_bfloat16 g_woh[2048 * 2048], g_wol[2048 * 2048];

/* ------------------------------------------------------------------ */
/* asm helpers                                                         */
/* ------------------------------------------------------------------ */
#define CPA16(dst, src)                                                    \
    asm volatile("cp.async.cg.shared.global [%0], [%1], 16;"               \
                 :: "r"(dst), "l"(src))
#define CPA_COMMIT() asm volatile("cp.async.commit_group;")
#define CPA_WAIT1()  asm volatile("cp.async.wait_group 1;")
#define CPA_WAIT0()  asm volatile("cp.async.wait_group 0;")

#define LDSM4(r0, r1, r2, r3, addr)                                        \
    asm volatile("ldmatrix.sync.aligned.m8n8.x4.shared.b16 {%0,%1,%2,%3}, [%4];" \
                 : "=r"(r0), "=r"(r1), "=r"(r2), "=r"(r3) : "r"(addr))
#define LDSM4T(r0, r1, r2, r3, addr)                                       \
    asm volatile("ldmatrix.sync.aligned.m8n8.x4.trans.shared.b16 {%0,%1,%2,%3}, [%4];" \
                 : "=r"(r0), "=r"(r1), "=r"(r2), "=r"(r3) : "r"(addr))
#define MMA_BF16(c, a, b0, b1)                                             \
    asm volatile("mma.sync.aligned.m16n8k16.row.col.f32.bf16.bf16.f32 "    \
                 "{%0,%1,%2,%3}, {%4,%5,%6,%7}, {%8,%9}, {%0,%1,%2,%3};"   \
                 : "+f"(c[0]), "+f"(c[1]), "+f"(c[2]), "+f"(c[3])          \
                 : "r"(a[0]), "r"(a[1]), "r"(a[2]), "r"(a[3]),             \
                   "r"(b0), "r"(b1))

__device__ __forceinline__ uint32_t bf2pack(float a, float b)
{
    return (uint32_t)__bfloat16_as_ushort(__float2bfloat16_rn(a)) |
           ((uint32_t)__bfloat16_as_ushort(__float2bfloat16_rn(b)) << 16);
}

/* ------------------------------------------------------------------ */
/* RoPE table                                                          */
/* ------------------------------------------------------------------ */
__global__ void __launch_bounds__(256) rope_table()
{
    const int idx = blockIdx.x * 256 + threadIdx.x;
    if (idx >= TSEQ * 32) return;
    const int t = idx >> 5, i = idx & 31;
    const double inv = pow(10000.0, -(double)i / 32.0);
    double sd, cd;
    sincos((double)t * inv, &sd, &cd);
    g_cosT[idx] = (float)cd;
    g_sinT[idx] = (float)sd;
}

/* ------------------------------------------------------------------ */
/* Batched fp32 -> bf16 hi/lo split                                    */
/* ------------------------------------------------------------------ */
struct SplitJob { const float* src; __nv_bfloat16 *h, *l; int n; };
struct SplitJobs { SplitJob j[9]; };

__global__ void __launch_bounds__(256) split_many(SplitJobs js)
{
    const SplitJob J = js.j[blockIdx.y];
    const int i = (blockIdx.x * 256 + threadIdx.x) << 2;
    if (i >= J.n) return;
    float4 v = *(const float4*)(J.src + i);
    float h0 = __bfloat162float(__float2bfloat16_rn(v.x));
    float h1 = __bfloat162float(__float2bfloat16_rn(v.y));
    float h2 = __bfloat162float(__float2bfloat16_rn(v.z));
    float h3 = __bfloat162float(__float2bfloat16_rn(v.w));
    uint2 hp, lp;
    hp.x = bf2pack(v.x, v.y);          hp.y = bf2pack(v.z, v.w);
    lp.x = bf2pack(v.x - h0, v.y - h1); lp.y = bf2pack(v.z - h2, v.w - h3);
    *(uint2*)(J.h + i) = hp;
    *(uint2*)(J.l + i) = lp;
}

/* ------------------------------------------------------------------ */
/* Fused multi-segment split-bf16 tensor-core GEMM.                    */
/* BM=BN=128, BK=64, 512 threads / 16 warps (8x2), warp tile 16x64.    */
/* 2-stage cp.async, 128KB smem.                                       */
/* ------------------------------------------------------------------ */
struct GSeg {
    const __nv_bfloat16 *Ah, *Al;
    int lda;
    const __nv_bfloat16 *Bh, *Bl;
    float* Cf;
    __nv_bfloat16 *Ch, *Cl;
    int N, K, tile0, vperm;
};
struct GSegs { GSeg s[4]; int n; };

#define G_STAGE 65536
#define GA_LO   16384
#define GB_HI   32768
#define GB_LO   49152

/* A tile: 128 rows x 8 chunks(16B) = 128x64 bf16 */
__device__ __forceinline__ uint32_t offA64(int r, int c)
{ return (uint32_t)(((r << 3) + (c ^ (r & 7))) << 4); }
/* B tile: 64 rows x 16 chunks(16B) = 64x128 bf16 */
__device__ __forceinline__ uint32_t offB(int r, int c)
{ return (uint32_t)(((r << 4) + (c ^ (r & 7))) << 4); }

__global__ void __launch_bounds__(512) gemm_fused(GSegs segs)
{
    extern __shared__ char dsm[];
    const uint32_t sb = (uint32_t)__cvta_generic_to_shared(dsm);

    const int tid  = threadIdx.x;
    const int lane = tid & 31;
    const int warp = tid >> 5;           /* 0..15 */
    const int wm   = (warp >> 1) << 4;   /* 0..112 step 16 */
    const int wn   = (warp & 1) << 6;    /* 0 / 64 */
    const int bm   = blockIdx.y << 7;

    GSeg sg = segs.s[0];
#pragma unroll
    for (int i = 1; i < 4; i++)
        if (i < segs.n && (int)blockIdx.x >= segs.s[i].tile0) sg = segs.s[i];
    const int bn  = ((int)blockIdx.x - sg.tile0) << 7;
    const int lda = sg.lda, ldb = sg.N, K = sg.K;

    /* staging indices (512 threads):
       A: 64 rows/pass x 8 chunks, passes rows +0/+64
       B: 32 rows/pass x 16 chunks, passes rows +0/+32 */
    const int ar = tid >> 3, ac = tid & 7;
    const int br = tid >> 4, bc = tid & 15;

    const __nv_bfloat16* gAh = sg.Ah + (size_t)(bm + ar) * lda + ac * 8;
    const __nv_bfloat16* gAl = sg.Al + (size_t)(bm + ar) * lda + ac * 8;
    const __nv_bfloat16* gBh = sg.Bh + (size_t)br * ldb + bn + bc * 8;
    const __nv_bfloat16* gBl = sg.Bl + (size_t)br * ldb + bn + bc * 8;

    float acc[8][4];
#pragma unroll
    for (int nt = 0; nt < 8; nt++)
#pragma unroll
        for (int i = 0; i < 4; i++) acc[nt][i] = 0.f;

    const int nk = K >> 6;

    auto load_stage = [&](int st, int k0) {
        const uint32_t s0 = sb + st * G_STAGE;
        const __nv_bfloat16* pAh = gAh + k0;
        const __nv_bfloat16* pAl = gAl + k0;
#pragma unroll
        for (int p = 0; p < 2; p++) {
            const uint32_t ao = offA64(ar + (p << 6), ac);
            CPA16(s0 + ao,         pAh + (size_t)(p << 6) * lda);
            CPA16(s0 + GA_LO + ao, pAl + (size_t)(p << 6) * lda);
        }
        const __nv_bfloat16* pBh = gBh + (size_t)k0 * ldb;
        const __nv_bfloat16* pBl = gBl + (size_t)k0 * ldb;
#pragma unroll
        for (int p = 0; p < 2; p++) {
            const uint32_t bo = offB(br + (p << 5), bc);
            CPA16(s0 + GB_HI + bo, pBh + (size_t)(p << 5) * ldb);
            CPA16(s0 + GB_LO + bo, pBl + (size_t)(p << 5) * ldb);
        }
    };

    load_stage(0, 0);
    CPA_COMMIT();

    for (int it = 0; it < nk; it++) {
        if (it + 1 < nk) { load_stage((it + 1) & 1, (it + 1) << 6); CPA_COMMIT(); }
        if (it + 1 < nk) CPA_WAIT1(); else CPA_WAIT0();
        __syncthreads();

        const uint32_t s0 = sb + (it & 1) * G_STAGE;
#pragma unroll
        for (int ks = 0; ks < 4; ks++) {
            uint32_t ah[4], al_[4];
            {
                const int rowA   = wm + (lane & 15);
                const int chunkA = (ks << 1) + (lane >> 4);
                const uint32_t ad = s0 + offA64(rowA, chunkA);
                LDSM4(ah[0], ah[1], ah[2], ah[3], ad);
                LDSM4(al_[0], al_[1], al_[2], al_[3], ad + GA_LO);
            }
            uint32_t bhf[8][2], blf[8][2];
#pragma unroll
            for (int np = 0; np < 4; np++) {
                const int rowB   = (ks << 4) + (lane & 15);
                const int chunkB = (wn >> 3) + (lane >> 4) + (np << 1);
                const uint32_t bd = s0 + GB_HI + offB(rowB, chunkB);
                uint32_t r0, r1, r2, r3;
                LDSM4T(r0, r1, r2, r3, bd);
                bhf[2 * np][0] = r0; bhf[2 * np][1] = r1;
                bhf[2 * np + 1][0] = r2; bhf[2 * np + 1][1] = r3;
                LDSM4T(r0, r1, r2, r3, bd + 16384);
                blf[2 * np][0] = r0; blf[2 * np][1] = r1;
                blf[2 * np + 1][0] = r2; blf[2 * np + 1][1] = r3;
            }
#pragma unroll
            for (int nt = 0; nt < 8; nt++) {
                MMA_BF16(acc[nt], ah,  bhf[nt][0], bhf[nt][1]);
                MMA_BF16(acc[nt], ah,  blf[nt][0], blf[nt][1]);
                MMA_BF16(acc[nt], al_, bhf[nt][0], bhf[nt][1]);
            }
        }
        __syncthreads();
    }

    const int erow = lane >> 2;
    const int ecol = (lane & 3) << 1;
    if (sg.Cf) {
#pragma unroll
        for (int nt = 0; nt < 8; nt++) {
            const int r = bm + wm + erow;
            const int c = bn + wn + (nt << 3) + ecol;
            *(float2*)(sg.Cf + (size_t)r * ldb + c) =
                make_float2(acc[nt][0], acc[nt][1]);
            *(float2*)(sg.Cf + (size_t)(r + 8) * ldb + c) =
                make_float2(acc[nt][2], acc[nt][3]);
        }
    } else {
#pragma unroll
        for (int nt = 0; nt < 8; nt++) {
            const int r = bm + wm + erow;
            const int c = bn + wn + (nt << 3) + ecol;
#pragma unroll
            for (int hh = 0; hh < 2; hh++) {
                const float v0 = acc[nt][2 * hh];
                const float v1 = acc[nt][2 * hh + 1];
                const float h0 = __bfloat162float(__float2bfloat16_rn(v0));
                const float h1 = __bfloat162float(__float2bfloat16_rn(v1));
                const int rr = r + 8 * hh;
                size_t idx;
                if (sg.vperm)
                    idx = ((size_t)(c >> 7) * TSEQ + rr) * DHEAD + (c & 127);
                else
                    idx = (size_t)rr * ldb + c;
                *(uint32_t*)(sg.Ch + idx) = bf2pack(v0, v1);
                *(uint32_t*)(sg.Cl + idx) = bf2pack(v0 - h0, v1 - h1);
            }
        }
    }
}

/* ------------------------------------------------------------------ */
/* Pack + RoPE -> Qh/Ql (pre-scaled), Kh/Kl in [h][t][d].              */
/* ------------------------------------------------------------------ */
__global__ void __launch_bounds__(64) pack_kernel()
{
    const int t = blockIdx.x;
    const int h = blockIdx.y;
    const int d2 = threadIdx.x << 1;
    const size_t o = ((size_t)h * TSEQ + t) * DHEAD + d2;

    float q0, q1, k0, k1;
    if (d2 < DCONT) {
        const size_t b = (size_t)t * 1024 + h * DCONT + d2;
        q0 = g_qc[b];     q1 = g_qc[b + 1];
        k0 = g_kc[b];     k1 = g_kc[b + 1];
    } else {
        const int i = d2 - DCONT;
        const int ip = (i < 32) ? i : i - 32;
        const float c0 = g_cosT[t * 32 + ip],     s0 = g_sinT[t * 32 + ip];
        const float c1 = g_cosT[t * 32 + ip + 1], s1 = g_sinT[t * 32 + ip + 1];
        const size_t b = (size_t)t * 1024 + h * DROPE;
        const float qa0 = g_qr[b + ip],      qa1 = g_qr[b + ip + 1];
        const float qb0 = g_qr[b + 32 + ip], qb1 = g_qr[b + 32 + ip + 1];
        const float ka0 = g_kr[b + ip],      ka1 = g_kr[b + ip + 1];
        const float kb0 = g_kr[b + 32 + ip], kb1 = g_kr[b + 32 + ip + 1];
        if (i < 32) {
            q0 = qa0 * c0 - qb0 * s0;  q1 = qa1 * c1 - qb1 * s1;
            k0 = ka0 * c0 - kb0 * s0;  k1 = ka1 * c1 - kb1 * s1;
        } else {
            q0 = qa0 * s0 + qb0 * c0;  q1 = qa1 * s1 + qb1 * c1;
            k0 = ka0 * s0 + kb0 * c0;  k1 = ka1 * s1 + kb1 * c1;
        }
    }
    q0 *= SCALE_ATT; q1 *= SCALE_ATT;

    const float qh0 = __bfloat162float(__float2bfloat16_rn(q0));
    const float qh1 = __bfloat162float(__float2bfloat16_rn(q1));
    const float kh0 = __bfloat162float(__float2bfloat16_rn(k0));
    const float kh1 = __bfloat162float(__float2bfloat16_rn(k1));
    *(uint32_t*)(g_Qh + o) = bf2pack(q0, q1);
    *(uint32_t*)(g_Ql + o) = bf2pack(q0 - qh0, q1 - qh1);
    *(uint32_t*)(g_Kh + o) = bf2pack(k0, k1);
    *(uint32_t*)(g_Kl + o) = bf2pack(k0 - kh0, k1 - kh1);
}

/* ------------------------------------------------------------------ */
/* Tensor-core causal flash attention (split bf16).                    */
/* ------------------------------------------------------------------ */
__device__ __forceinline__ uint32_t offV(int r, int c)
{ return (uint32_t)(((r << 4) + (c ^ (r & 7))) << 4); }   /* 16 chunks/row */

#define SM_KH 0
#define SM_KL 16384
#define SM_VH 32768
#define SM_VL 49152

__global__ void __launch_bounds__(128) attn_mma()
{
    extern __shared__ char dsm[];
    const uint32_t sb = (uint32_t)__cvta_generic_to_shared(dsm);

    const int h    = blockIdx.y;
    const int qblk = 31 - (int)blockIdx.x;       /* long CTAs first */
    const int qb   = qblk << 6;
    const int tid  = threadIdx.x;
    const int lane = tid & 31;
    const int warp = tid >> 5;
    const int w16  = warp << 4;

    const __nv_bfloat16* Qhb = g_Qh + (size_t)h * TSEQ * DHEAD;
    const __nv_bfloat16* Qlb = g_Ql + (size_t)h * TSEQ * DHEAD;
    const __nv_bfloat16* Khb = g_Kh + (size_t)h * TSEQ * DHEAD;
    const __nv_bfloat16* Klb = g_Kl + (size_t)h * TSEQ * DHEAD;
    const __nv_bfloat16* Vhb = g_Vh + (size_t)h * TSEQ * DHEAD;
    const __nv_bfloat16* Vlb = g_Vl + (size_t)h * TSEQ * DHEAD;

    const int sr = tid >> 4;            /* 0..7  */
    const int sc = tid & 15;            /* 0..15 */

    /* ---- stage Q (64 rows), LDSM into regs ---- */
#pragma unroll
    for (int p = 0; p < 8; p++) {
        const int r = sr + (p << 3);
        CPA16(sb + SM_KH + offV(r, sc), Qhb + (size_t)(qb + r) * DHEAD + sc * 8);
        CPA16(sb + SM_KL + offV(r, sc), Qlb + (size_t)(qb + r) * DHEAD + sc * 8);
    }
    CPA_COMMIT(); CPA_WAIT0();
    __syncthreads();

    uint32_t qh[8][4], ql[8][4];
#pragma unroll
    for (int ks = 0; ks < 8; ks++) {
        const uint32_t ad = offV(w16 + (lane & 15), (ks << 1) + (lane >> 4));
        LDSM4(qh[ks][0], qh[ks][1], qh[ks][2], qh[ks][3], sb + SM_KH + ad);
        LDSM4(ql[ks][0], ql[ks][1], ql[ks][2], ql[ks][3], sb + SM_KL + ad);
    }
    __syncthreads();

    float O[16][4];
#pragma unroll
    for (int nt = 0; nt < 16; nt++)
#pragma unroll
        for (int i = 0; i < 4; i++) O[nt][i] = 0.f;
    float m0 = -1e30f, m1 = -1e30f, l0 = 0.f, l1 = 0.f;

    const int ntiles = qblk + 1;
    const int row0 = qb + w16 + (lane >> 2);
    const int row1 = row0 + 8;

    for (int kt = 0; kt < ntiles; kt++) {
        const int kb = kt << 6;

        /* stage K (group A), then V (group B) */
#pragma unroll
        for (int p = 0; p < 8; p++) {
            const int r = sr + (p << 3);
            const size_t gi = (size_t)(kb + r) * DHEAD + sc * 8;
            const uint32_t so = offV(r, sc);
            CPA16(sb + SM_KH + so, Khb + gi);
            CPA16(sb + SM_KL + so, Klb + gi);
        }
        CPA_COMMIT();
#pragma unroll
        for (int p = 0; p < 8; p++) {
            const int r = sr + (p << 3);
            const size_t gi = (size_t)(kb + r) * DHEAD + sc * 8;
            const uint32_t so = offV(r, sc);
            CPA16(sb + SM_VH + so, Vhb + gi);
            CPA16(sb + SM_VL + so, Vlb + gi);
        }
        CPA_COMMIT();
        CPA_WAIT1();                      /* K ready; V still in flight */
        __syncthreads();

        /* ---- scores S = Q K^T ---- */
        float S[8][4];
#pragma unroll
        for (int nt = 0; nt < 8; nt++)
#pragma unroll
            for (int i = 0; i < 4; i++) S[nt][i] = 0.f;

#pragma unroll
        for (int ntp = 0; ntp < 4; ntp++) {
#pragma unroll
            for (int ks = 0; ks < 8; ks++) {
                const uint32_t ad = offV((ntp << 4) + (lane & 15),
                                         (ks << 1) + (lane >> 4));
                uint32_t kh0, kh1, kh2, kh3, kl0, kl1, kl2, kl3;
                LDSM4(kh0, kh1, kh2, kh3, sb + SM_KH + ad);
                LDSM4(kl0, kl1, kl2, kl3, sb + SM_KL + ad);
                MMA_BF16(S[2 * ntp],     qh[ks], kh0, kh2);
                MMA_BF16(S[2 * ntp],     qh[ks], kl0, kl2);
                MMA_BF16(S[2 * ntp],     ql[ks], kh0, kh2);
                MMA_BF16(S[2 * ntp + 1], qh[ks], kh1, kh3);
                MMA_BF16(S[2 * ntp + 1], qh[ks], kl1, kl3);
                MMA_BF16(S[2 * ntp + 1], ql[ks], kh1, kh3);
            }
        }

        /* ---- causal mask on diagonal tile ---- */
        if (kb == qb) {
#pragma unroll
            for (int nt = 0; nt < 8; nt++) {
                const int key = kb + (nt << 3) + ((lane & 3) << 1);
                if (key > row0)     S[nt][0] = -1e30f;
                if (key + 1 > row0) S[nt][1] = -1e30f;
                if (key > row1)     S[nt][2] = -1e30f;
                if (key + 1 > row1) S[nt][3] = -1e30f;
            }
        }

        /* ---- online softmax ---- */
        float mx0 = -1e30f, mx1 = -1e30f;
#pragma unroll
        for (int nt = 0; nt < 8; nt++) {
            mx0 = fmaxf(mx0, fmaxf(S[nt][0], S[nt][1]));
            mx1 = fmaxf(mx1, fmaxf(S[nt][2], S[nt][3]));
        }
        mx0 = fmaxf(mx0, __shfl_xor_sync(0xffffffffu, mx0, 1));
        mx0 = fmaxf(mx0, __shfl_xor_sync(0xffffffffu, mx0, 2));
        mx1 = fmaxf(mx1, __shfl_xor_sync(0xffffffffu, mx1, 1));
        mx1 = fmaxf(mx1, __shfl_xor_sync(0xffffffffu, mx1, 2));

        const float m0n = fmaxf(m0, mx0), m1n = fmaxf(m1, mx1);
        const float a0 = __expf(m0 - m0n), a1 = __expf(m1 - m1n);
        m0 = m0n; m1 = m1n;

        uint32_t aH[4][4], aL[4][4];
        float ps0 = 0.f, ps1 = 0.f;
#pragma unroll
        for (int nt = 0; nt < 8; nt++) {
            const float p0 = __expf(S[nt][0] - m0n);
            const float p1 = __expf(S[nt][1] - m0n);
            const float p2 = __expf(S[nt][2] - m1n);
            const float p3 = __expf(S[nt][3] - m1n);
            ps0 += p0 + p1; ps1 += p2 + p3;
            const float h0 = __bfloat162float(__float2bfloat16_rn(p0));
            const float h1 = __bfloat162float(__float2bfloat16_rn(p1));
            const float h2 = __bfloat162float(__float2bfloat16_rn(p2));
            const float h3 = __bfloat162float(__float2bfloat16_rn(p3));
            const int kk = nt >> 1;
            const int e  = (nt & 1) << 1;
            aH[kk][e]     = bf2pack(p0, p1);
            aH[kk][e + 1] = bf2pack(p2, p3);
            aL[kk][e]     = bf2pack(p0 - h0, p1 - h1);
            aL[kk][e + 1] = bf2pack(p2 - h2, p3 - h3);
        }
        ps0 += __shfl_xor_sync(0xffffffffu, ps0, 1);
        ps0 += __shfl_xor_sync(0xffffffffu, ps0, 2);
        ps1 += __shfl_xor_sync(0xffffffffu, ps1, 1);
        ps1 += __shfl_xor_sync(0xffffffffu, ps1, 2);
        l0 = l0 * a0 + ps0;
        l1 = l1 * a1 + ps1;

#pragma unroll
        for (int nt = 0; nt < 16; nt++) {
            O[nt][0] *= a0; O[nt][1] *= a0;
            O[nt][2] *= a1; O[nt][3] *= a1;
        }

        CPA_WAIT0();                      /* V ready */
        __syncthreads();

        /* ---- O += P V ---- */
#pragma unroll
        for (int kk = 0; kk < 4; kk++) {
#pragma unroll
            for (int ntp = 0; ntp < 8; ntp++) {
                const uint32_t ad = offV((kk << 4) + (lane & 15),
                                         (ntp << 1) + (lane >> 4));
                uint32_t vh0, vh1, vh2, vh3, vl0, vl1, vl2, vl3;
                LDSM4T(vh0, vh1, vh2, vh3, sb + SM_VH + ad);
                LDSM4T(vl0, vl1, vl2, vl3, sb + SM_VL + ad);
                MMA_BF16(O[2 * ntp],     aH[kk], vh0, vh1);
                MMA_BF16(O[2 * ntp],     aH[kk], vl0, vl1);
                MMA_BF16(O[2 * ntp],     aL[kk], vh0, vh1);
                MMA_BF16(O[2 * ntp + 1], aH[kk], vh2, vh3);
                MMA_BF16(O[2 * ntp + 1], aH[kk], vl2, vl3);
                MMA_BF16(O[2 * ntp + 1], aL[kk], vh2, vh3);
            }
        }
        __syncthreads();
    }

    /* ---- epilogue ---- */
    const float inv0 = 1.0f / l0, inv1 = 1.0f / l1;
#pragma unroll
    for (int nt = 0; nt < 16; nt++) {
        const int d = (nt << 3) + ((lane & 3) << 1);
        const float v0 = O[nt][0] * inv0, v1 = O[nt][1] * inv0;
        const float v2 = O[nt][2] * inv1, v3 = O[nt][3] * inv1;
        const float h0 = __bfloat162float(__float2bfloat16_rn(v0));
        const float h1 = __bfloat162float(__float2bfloat16_rn(v1));
        const float h2 = __bfloat162float(__float2bfloat16_rn(v2));
        const float h3 = __bfloat162float(__float2bfloat16_rn(v3));
        const size_t i0 = (size_t)row0 * DMODEL + h * DHEAD + d;
        const size_t i1 = (size_t)row1 * DMODEL + h * DHEAD + d;
        *(uint32_t*)(g_Oh + i0) = bf2pack(v0, v1);
        *(uint32_t*)(g_Ol + i0) = bf2pack(v0 - h0, v1 - h1);
        *(uint32_t*)(g_Oh + i1) = bf2pack(v2, v3);
        *(uint32_t*)(g_Ol + i1) = bf2pack(v2 - h2, v3 - h3);
    }
}

/* ------------------------------------------------------------------ */
extern "C" void kernel_launch(void* const* d_in, const int* in_sizes, int n_in,
                              void* d_out, int out_size)
{
    const float* x        = (const float*)d_in[0];
    const float* Wq_down  = (const float*)d_in[1];
    const float* Wq_up    = (const float*)d_in[2];
    const float* Wq_rope  = (const float*)d_in[3];
    const float* Wkv_down = (const float*)d_in[4];
    const float* Wk_up    = (const float*)d_in[5];
    const float* Wv_up    = (const float*)d_in[6];
    const float* Wk_rope  = (const float*)d_in[7];
    const float* Wo       = (const float*)d_in[8];
    float* out = (float*)d_out;

    float *qc, *qr, *kc, *kr;
    cudaGetSymbolAddress((void**)&qc, g_qc);
    cudaGetSymbolAddress((void**)&qr, g_qr);
    cudaGetSymbolAddress((void**)&kc, g_kc);
    cudaGetSymbolAddress((void**)&kr, g_kr);

    __nv_bfloat16 *xh, *xl, *qdh, *qdl, *kvh, *kvl, *Oh, *Ol, *Vh, *Vl;
    __nv_bfloat16 *wqdh, *wqdl, *wquh, *wqul, *wqrh, *wqrl, *wkdh, *wkdl;
    __nv_bfloat16 *wkuh, *wkul, *wvuh, *wvul, *wkrh, *wkrl, *woh, *wol;
    cudaGetSymbolAddress((void**)&xh, g_xh);   cudaGetSymbolAddress((void**)&xl, g_xl);
    cudaGetSymbolAddress((void**)&qdh, g_qdh); cudaGetSymbolAddress((void**)&qdl, g_qdl);
    cudaGetSymbolAddress((void**)&kvh, g_kvh); cudaGetSymbolAddress((void**)&kvl, g_kvl);
    cudaGetSymbolAddress((void**)&Oh, g_Oh);   cudaGetSymbolAddress((void**)&Ol, g_Ol);
    cudaGetSymbolAddress((void**)&Vh, g_Vh);   cudaGetSymbolAddress((void**)&Vl, g_Vl);
    cudaGetSymbolAddress((void**)&wqdh, g_wqdh); cudaGetSymbolAddress((void**)&wqdl, g_wqdl);
    cudaGetSymbolAddress((void**)&wquh, g_wquh); cudaGetSymbolAddress((void**)&wqul, g_wqul);
    cudaGetSymbolAddress((void**)&wqrh, g_wqrh); cudaGetSymbolAddress((void**)&wqrl, g_wqrl);
    cudaGetSymbolAddress((void**)&wkdh, g_wkdh); cudaGetSymbolAddress((void**)&wkdl, g_wkdl);
    cudaGetSymbolAddress((void**)&wkuh, g_wkuh); cudaGetSymbolAddress((void**)&wkul, g_wkul);
    cudaGetSymbolAddress((void**)&wvuh, g_wvuh); cudaGetSymbolAddress((void**)&wvul, g_wvul);
    cudaGetSymbolAddress((void**)&wkrh, g_wkrh); cudaGetSymbolAddress((void**)&wkrl, g_wkrl);
    cudaGetSymbolAddress((void**)&woh, g_woh);   cudaGetSymbolAddress((void**)&wol, g_wol);

    cudaFuncSetAttribute(gemm_fused,
                         cudaFuncAttributeMaxDynamicSharedMemorySize, 131072);
    cudaFuncSetAttribute(attn_mma,
                         cudaFuncAttributeMaxDynamicSharedMemorySize, 65536);

    /* 0. rope table */
    rope_table<<<256, 256>>>();

    /* 1. split inputs + weights */
    SplitJobs js;
    js.j[0] = { x,        xh,   xl,   TSEQ * 2048 };
    js.j[1] = { Wq_down,  wqdh, wqdl, 2048 * 512  };
    js.j[2] = { Wq_up,    wquh, wqul, 512 * 1024  };
    js.j[3] = { Wq_rope,  wqrh, wqrl, 2048 * 1024 };
    js.j[4] = { Wkv_down, wkdh, wkdl, 2048 * 512  };
    js.j[5] = { Wk_up,    wkuh, wkul, 512 * 1024  };
    js.j[6] = { Wv_up,    wvuh, wvul, 512 * 2048  };
    js.j[7] = { Wk_rope,  wkrh, wkrl, 2048 * 1024 };
    js.j[8] = { Wo,       woh,  wol,  2048 * 2048 };
    split_many<<<dim3(4096, 9), 256>>>(js);

    /* 2. GEMM1: x @ [Wq_down | Wkv_down | Wq_rope | Wk_rope] */
    {
        GSegs g; g.n = 4;
        g.s[0] = { xh, xl, 2048, wqdh, wqdl, nullptr, qdh, qdl,  512, 2048, 0,  0 };
        g.s[1] = { xh, xl, 2048, wkdh, wkdl, nullptr, kvh, kvl,  512, 2048, 4,  0 };
        g.s[2] = { xh, xl, 2048, wqrh, wqrl, qr, nullptr, nullptr, 1024, 2048, 8,  0 };
        g.s[3] = { xh, xl, 2048, wkrh, wkrl, kr, nullptr, nullptr, 1024, 2048, 16, 0 };
        gemm_fused<<<dim3(24, 16), 512, 131072>>>(g);
    }

    /* 3. GEMM2: qd @ Wq_up ; kv @ [Wk_up | Wv_up (-> Vh/Vl permuted)] */
    {
        GSegs g; g.n = 3;
        g.s[0] = { qdh, qdl, 512, wquh, wqul, qc, nullptr, nullptr, 1024, 512, 0,  0 };
        g.s[1] = { kvh, kvl, 512, wkuh, wkul, kc, nullptr, nullptr, 1024, 512, 8,  0 };
        g.s[2] = { kvh, kvl, 512, wvuh, wvul, nullptr, Vh, Vl,      2048, 512, 16, 1 };
        g.s[3] = g.s[0];
        gemm_fused<<<dim3(32, 16), 512, 131072>>>(g);
    }

    /* 4. rope + pack Q/K */
    pack_kernel<<<dim3(TSEQ, NH), 64>>>();

    /* 5. tensor-core causal attention */
    attn_mma<<<dim3(32, NH), 128, 65536>>>();

    /* 6. GEMM3: O @ Wo -> out */
    {
        GSegs g; g.n = 1;
        g.s[0] = { Oh, Ol, 2048, woh, wol, out, nullptr, nullptr, 2048, 2048, 0, 0 };
        g.s[1] = g.s[0]; g.s[2] = g.s[0]; g.s[3] = g.s[0];
        gemm_fused<<<dim3(16, 16), 512, 131072>>>(g);
    }
}

// round 9
// speedup vs baseline: 1.0117x; 1.0117x over previous
#include <cuda_runtime.h>
#include <cuda_bf16.h>
#include <math.h>
#include <stdint.h>

#define TSEQ   2048
#define DMODEL 2048
#define NH     16
#define DHEAD  128
#define DROPE  64
#define DCONT  64
#define SCALE_ATT 0.08838834764831845f  /* 1/sqrt(128) */

/* ------------------------------------------------------------------ */
/* Scratch (device globals)                                            */
/* ------------------------------------------------------------------ */
__device__ float g_qc[TSEQ * 1024];
__device__ float g_qr[TSEQ * 1024];
__device__ float g_kc[TSEQ * 1024];
__device__ float g_kr[TSEQ * 1024];
__device__ float g_cosT[TSEQ * 32];
__device__ float g_sinT[TSEQ * 32];

/* attention operands, bf16 hi/lo, [h][t][d] */
__device__ __nv_bfloat16 g_Qh[NH * TSEQ * DHEAD], g_Ql[NH * TSEQ * DHEAD];
__device__ __nv_bfloat16 g_Kh[NH * TSEQ * DHEAD], g_Kl[NH * TSEQ * DHEAD];
__device__ __nv_bfloat16 g_Vh[NH * TSEQ * DHEAD], g_Vl[NH * TSEQ * DHEAD];

/* bf16 hi/lo split operands for GEMMs */
__device__ __nv_bfloat16 g_xh[TSEQ * 2048],  g_xl[TSEQ * 2048];
__device__ __nv_bfloat16 g_qdh[TSEQ * 512],  g_qdl[TSEQ * 512];
__device__ __nv_bfloat16 g_kvh[TSEQ * 512],  g_kvl[TSEQ * 512];
__device__ __nv_bfloat16 g_Oh[TSEQ * 2048],  g_Ol[TSEQ * 2048];
__device__ __nv_bfloat16 g_wqdh[2048 * 512], g_wqdl[2048 * 512];
__device__ __nv_bfloat16 g_wquh[512 * 1024], g_wqul[512 * 1024];
__device__ __nv_bfloat16 g_wqrh[2048 * 1024],g_wqrl[2048 * 1024];
__device__ __nv_bfloat16 g_wkdh[2048 * 512], g_wkdl[2048 * 512];
__device__ __nv_bfloat16 g_wkuh[512 * 1024], g_wkul[512 * 1024];
__device__ __nv_bfloat16 g_wvuh[512 * 2048], g_wvul[512 * 2048];
__device__ __nv_bfloat16 g_wkrh[2048 * 1024],g_wkrl[2048 * 1024];
__device__ __nv_bfloat16 g_woh[2048 * 2048], g_wol[2048 * 2048];

/* ------------------------------------------------------------------ */
/* asm helpers                                                         */
/* ------------------------------------------------------------------ */
#define CPA16(dst, src)                                                    \
    asm volatile("cp.async.cg.shared.global [%0], [%1], 16;"               \
                 :: "r"(dst), "l"(src))
#define CPA_COMMIT() asm volatile("cp.async.commit_group;")
#define CPA_WAIT1()  asm volatile("cp.async.wait_group 1;")
#define CPA_WAIT0()  asm volatile("cp.async.wait_group 0;")

#define LDSM4(r0, r1, r2, r3, addr)                                        \
    asm volatile("ldmatrix.sync.aligned.m8n8.x4.shared.b16 {%0,%1,%2,%3}, [%4];" \
                 : "=r"(r0), "=r"(r1), "=r"(r2), "=r"(r3) : "r"(addr))
#define LDSM4T(r0, r1, r2, r3, addr)                                       \
    asm volatile("ldmatrix.sync.aligned.m8n8.x4.trans.shared.b16 {%0,%1,%2,%3}, [%4];" \
                 : "=r"(r0), "=r"(r1), "=r"(r2), "=r"(r3) : "r"(addr))
#define MMA_BF16(c, a, b0, b1)                                             \
    asm volatile("mma.sync.aligned.m16n8k16.row.col.f32.bf16.bf16.f32 "    \
                 "{%0,%1,%2,%3}, {%4,%5,%6,%7}, {%8,%9}, {%0,%1,%2,%3};"   \
                 : "+f"(c[0]), "+f"(c[1]), "+f"(c[2]), "+f"(c[3])          \
                 : "r"(a[0]), "r"(a[1]), "r"(a[2]), "r"(a[3]),             \
                   "r"(b0), "r"(b1))

__device__ __forceinline__ uint32_t bf2pack(float a, float b)
{
    return (uint32_t)__bfloat16_as_ushort(__float2bfloat16_rn(a)) |
           ((uint32_t)__bfloat16_as_ushort(__float2bfloat16_rn(b)) << 16);
}

/* ------------------------------------------------------------------ */
/* RoPE table                                                          */
/* ------------------------------------------------------------------ */
__global__ void __launch_bounds__(256) rope_table()
{
    const int idx = blockIdx.x * 256 + threadIdx.x;
    if (idx >= TSEQ * 32) return;
    const int t = idx >> 5, i = idx & 31;
    const double inv = pow(10000.0, -(double)i / 32.0);
    double sd, cd;
    sincos((double)t * inv, &sd, &cd);
    g_cosT[idx] = (float)cd;
    g_sinT[idx] = (float)sd;
}

/* ------------------------------------------------------------------ */
/* Batched fp32 -> bf16 hi/lo split                                    */
/* ------------------------------------------------------------------ */
struct SplitJob { const float* src; __nv_bfloat16 *h, *l; int n; };
struct SplitJobs { SplitJob j[9]; };

__global__ void __launch_bounds__(256) split_many(SplitJobs js)
{
    const SplitJob J = js.j[blockIdx.y];
    const int i = (blockIdx.x * 256 + threadIdx.x) << 2;
    if (i >= J.n) return;
    float4 v = *(const float4*)(J.src + i);
    float h0 = __bfloat162float(__float2bfloat16_rn(v.x));
    float h1 = __bfloat162float(__float2bfloat16_rn(v.y));
    float h2 = __bfloat162float(__float2bfloat16_rn(v.z));
    float h3 = __bfloat162float(__float2bfloat16_rn(v.w));
    uint2 hp, lp;
    hp.x = bf2pack(v.x, v.y);          hp.y = bf2pack(v.z, v.w);
    lp.x = bf2pack(v.x - h0, v.y - h1); lp.y = bf2pack(v.z - h2, v.w - h3);
    *(uint2*)(J.h + i) = hp;
    *(uint2*)(J.l + i) = lp;
}

/* ------------------------------------------------------------------ */
/* Fused multi-segment split-bf16 tensor-core GEMM.                    */
/* BM=BN=128, BK=32, 256 threads (8 warps 4x2, warp tile 32x64).       */
/* 2-stage cp.async, 64KB smem -> 2 CTAs per SM (cross-CTA overlap).   */
/* ------------------------------------------------------------------ */
struct GSeg {
    const __nv_bfloat16 *Ah, *Al;
    int lda;
    const __nv_bfloat16 *Bh, *Bl;
    float* Cf;
    __nv_bfloat16 *Ch, *Cl;
    int N, K, tile0, vperm;
};
struct GSegs { GSeg s[4]; int n; };

#define STAGE_BYTES 32768
#define A_LO_OFF    8192
#define B_HI_OFF    16384
#define B_LO_OFF    24576

/* A tile: 128 rows x 4 chunks(16B) = 128x32 bf16 */
__device__ __forceinline__ uint32_t offA(int r, int c)
{ return (uint32_t)(((r << 2) + (c ^ ((r >> 1) & 3))) << 4); }
/* B tile: 32 rows x 16 chunks(16B) = 32x128 bf16 */
__device__ __forceinline__ uint32_t offB(int r, int c)
{ return (uint32_t)(((r << 4) + (c ^ (r & 7))) << 4); }

__global__ void __launch_bounds__(256, 2) gemm_fused(GSegs segs)
{
    extern __shared__ char dsm[];
    const uint32_t sb = (uint32_t)__cvta_generic_to_shared(dsm);

    const int tid  = threadIdx.x;
    const int lane = tid & 31;
    const int warp = tid >> 5;
    const int wm   = (warp >> 1) << 5;   /* 0..96 */
    const int wn   = (warp & 1) << 6;    /* 0/64  */
    const int bm   = blockIdx.y << 7;

    GSeg sg = segs.s[0];
#pragma unroll
    for (int i = 1; i < 4; i++)
        if (i < segs.n && (int)blockIdx.x >= segs.s[i].tile0) sg = segs.s[i];
    const int bn  = ((int)blockIdx.x - sg.tile0) << 7;
    const int lda = sg.lda, ldb = sg.N, K = sg.K;

    /* staging: A 64 rows/pass x 4 chunks; B 32 rows x 8 chunks x2 */
    const int ar = tid >> 2, ac = tid & 3;
    const int br = tid >> 3, bc = tid & 7;
    const uint32_t aoff0 = offA(ar, ac), aoff1 = offA(ar + 64, ac);
    const uint32_t boff0 = offB(br, bc), boff1 = offB(br, bc + 8);

    const __nv_bfloat16* gAh = sg.Ah + (size_t)(bm + ar) * lda + ac * 8;
    const __nv_bfloat16* gAl = sg.Al + (size_t)(bm + ar) * lda + ac * 8;
    const __nv_bfloat16* gBh = sg.Bh + (size_t)br * ldb + bn + bc * 8;
    const __nv_bfloat16* gBl = sg.Bl + (size_t)br * ldb + bn + bc * 8;

    float acc[2][8][4];
#pragma unroll
    for (int mt = 0; mt < 2; mt++)
#pragma unroll
        for (int nt = 0; nt < 8; nt++)
#pragma unroll
            for (int i = 0; i < 4; i++) acc[mt][nt][i] = 0.f;

    const int nk = K >> 5;

    auto load_stage = [&](int st, int k0) {
        const uint32_t s0 = sb + st * STAGE_BYTES;
        const __nv_bfloat16* pAh = gAh + k0;
        const __nv_bfloat16* pAl = gAl + k0;
        CPA16(s0 + aoff0, pAh);
        CPA16(s0 + aoff1, pAh + (size_t)64 * lda);
        CPA16(s0 + A_LO_OFF + aoff0, pAl);
        CPA16(s0 + A_LO_OFF + aoff1, pAl + (size_t)64 * lda);
        const __nv_bfloat16* pBh = gBh + (size_t)k0 * ldb;
        const __nv_bfloat16* pBl = gBl + (size_t)k0 * ldb;
        CPA16(s0 + B_HI_OFF + boff0, pBh);
        CPA16(s0 + B_HI_OFF + boff1, pBh + 64);
        CPA16(s0 + B_LO_OFF + boff0, pBl);
        CPA16(s0 + B_LO_OFF + boff1, pBl + 64);
    };

    load_stage(0, 0);
    CPA_COMMIT();

    for (int it = 0; it < nk; it++) {
        if (it + 1 < nk) { load_stage((it + 1) & 1, (it + 1) << 5); CPA_COMMIT(); }
        if (it + 1 < nk) CPA_WAIT1(); else CPA_WAIT0();
        __syncthreads();

        const uint32_t s0 = sb + (it & 1) * STAGE_BYTES;
#pragma unroll
        for (int ks = 0; ks < 2; ks++) {
            uint32_t ah[2][4], al_[2][4];
#pragma unroll
            for (int mt = 0; mt < 2; mt++) {
                const int rowA   = wm + (mt << 4) + (lane & 15);
                const int chunkA = (ks << 1) + (lane >> 4);
                const uint32_t ad = s0 + offA(rowA, chunkA);
                LDSM4(ah[mt][0], ah[mt][1], ah[mt][2], ah[mt][3], ad);
                LDSM4(al_[mt][0], al_[mt][1], al_[mt][2], al_[mt][3], ad + A_LO_OFF);
            }
            /* B fragments consumed immediately: only 8 live B regs */
#pragma unroll
            for (int np = 0; np < 4; np++) {
                const int rowB   = (ks << 4) + (lane & 15);
                const int chunkB = (wn >> 3) + (lane >> 4) + (np << 1);
                const uint32_t bd = s0 + B_HI_OFF + offB(rowB, chunkB);
                uint32_t h0, h1, h2, h3, l0, l1, l2, l3;
                LDSM4T(h0, h1, h2, h3, bd);
                LDSM4T(l0, l1, l2, l3, bd + 8192);
#pragma unroll
                for (int mt = 0; mt < 2; mt++) {
                    MMA_BF16(acc[mt][2 * np],     ah[mt],  h0, h1);
                    MMA_BF16(acc[mt][2 * np],     ah[mt],  l0, l1);
                    MMA_BF16(acc[mt][2 * np],     al_[mt], h0, h1);
                    MMA_BF16(acc[mt][2 * np + 1], ah[mt],  h2, h3);
                    MMA_BF16(acc[mt][2 * np + 1], ah[mt],  l2, l3);
                    MMA_BF16(acc[mt][2 * np + 1], al_[mt], h2, h3);
                }
            }
        }
        __syncthreads();
    }

    const int erow = lane >> 2;
    const int ecol = (lane & 3) << 1;
    if (sg.Cf) {
#pragma unroll
        for (int mt = 0; mt < 2; mt++)
#pragma unroll
            for (int nt = 0; nt < 8; nt++) {
                const int r = bm + wm + (mt << 4) + erow;
                const int c = bn + wn + (nt << 3) + ecol;
                *(float2*)(sg.Cf + (size_t)r * ldb + c) =
                    make_float2(acc[mt][nt][0], acc[mt][nt][1]);
                *(float2*)(sg.Cf + (size_t)(r + 8) * ldb + c) =
                    make_float2(acc[mt][nt][2], acc[mt][nt][3]);
            }
    } else {
#pragma unroll
        for (int mt = 0; mt < 2; mt++)
#pragma unroll
            for (int nt = 0; nt < 8; nt++) {
                const int r = bm + wm + (mt << 4) + erow;
                const int c = bn + wn + (nt << 3) + ecol;
#pragma unroll
                for (int hh = 0; hh < 2; hh++) {
                    const float v0 = acc[mt][nt][2 * hh];
                    const float v1 = acc[mt][nt][2 * hh + 1];
                    const float h0 = __bfloat162float(__float2bfloat16_rn(v0));
                    const float h1 = __bfloat162float(__float2bfloat16_rn(v1));
                    const int rr = r + 8 * hh;
                    size_t idx;
                    if (sg.vperm)
                        idx = ((size_t)(c >> 7) * TSEQ + rr) * DHEAD + (c & 127);
                    else
                        idx = (size_t)rr * ldb + c;
                    *(uint32_t*)(sg.Ch + idx) = bf2pack(v0, v1);
                    *(uint32_t*)(sg.Cl + idx) = bf2pack(v0 - h0, v1 - h1);
                }
            }
    }
}

/* ------------------------------------------------------------------ */
/* Pack + RoPE -> Qh/Ql (pre-scaled), Kh/Kl in [h][t][d].              */
/* ------------------------------------------------------------------ */
__global__ void __launch_bounds__(64) pack_kernel()
{
    const int t = blockIdx.x;
    const int h = blockIdx.y;
    const int d2 = threadIdx.x << 1;
    const size_t o = ((size_t)h * TSEQ + t) * DHEAD + d2;

    float q0, q1, k0, k1;
    if (d2 < DCONT) {
        const size_t b = (size_t)t * 1024 + h * DCONT + d2;
        q0 = g_qc[b];     q1 = g_qc[b + 1];
        k0 = g_kc[b];     k1 = g_kc[b + 1];
    } else {
        const int i = d2 - DCONT;
        const int ip = (i < 32) ? i : i - 32;
        const float c0 = g_cosT[t * 32 + ip],     s0 = g_sinT[t * 32 + ip];
        const float c1 = g_cosT[t * 32 + ip + 1], s1 = g_sinT[t * 32 + ip + 1];
        const size_t b = (size_t)t * 1024 + h * DROPE;
        const float qa0 = g_qr[b + ip],      qa1 = g_qr[b + ip + 1];
        const float qb0 = g_qr[b + 32 + ip], qb1 = g_qr[b + 32 + ip + 1];
        const float ka0 = g_kr[b + ip],      ka1 = g_kr[b + ip + 1];
        const float kb0 = g_kr[b + 32 + ip], kb1 = g_kr[b + 32 + ip + 1];
        if (i < 32) {
            q0 = qa0 * c0 - qb0 * s0;  q1 = qa1 * c1 - qb1 * s1;
            k0 = ka0 * c0 - kb0 * s0;  k1 = ka1 * c1 - kb1 * s1;
        } else {
            q0 = qa0 * s0 + qb0 * c0;  q1 = qa1 * s1 + qb1 * c1;
            k0 = ka0 * s0 + kb0 * c0;  k1 = ka1 * s1 + kb1 * c1;
        }
    }
    q0 *= SCALE_ATT; q1 *= SCALE_ATT;

    const float qh0 = __bfloat162float(__float2bfloat16_rn(q0));
    const float qh1 = __bfloat162float(__float2bfloat16_rn(q1));
    const float kh0 = __bfloat162float(__float2bfloat16_rn(k0));
    const float kh1 = __bfloat162float(__float2bfloat16_rn(k1));
    *(uint32_t*)(g_Qh + o) = bf2pack(q0, q1);
    *(uint32_t*)(g_Ql + o) = bf2pack(q0 - qh0, q1 - qh1);
    *(uint32_t*)(g_Kh + o) = bf2pack(k0, k1);
    *(uint32_t*)(g_Kl + o) = bf2pack(k0 - kh0, k1 - kh1);
}

/* ------------------------------------------------------------------ */
/* Tensor-core causal flash attention (split bf16).                    */
/* ------------------------------------------------------------------ */
__device__ __forceinline__ uint32_t offV(int r, int c)
{ return (uint32_t)(((r << 4) + (c ^ (r & 7))) << 4); }   /* 16 chunks/row */

#define SM_KH 0
#define SM_KL 16384
#define SM_VH 32768
#define SM_VL 49152

__global__ void __launch_bounds__(128) attn_mma()
{
    extern __shared__ char dsm[];
    const uint32_t sb = (uint32_t)__cvta_generic_to_shared(dsm);

    const int h    = blockIdx.y;
    const int qblk = 31 - (int)blockIdx.x;       /* long CTAs first */
    const int qb   = qblk << 6;
    const int tid  = threadIdx.x;
    const int lane = tid & 31;
    const int warp = tid >> 5;
    const int w16  = warp << 4;

    const __nv_bfloat16* Qhb = g_Qh + (size_t)h * TSEQ * DHEAD;
    const __nv_bfloat16* Qlb = g_Ql + (size_t)h * TSEQ * DHEAD;
    const __nv_bfloat16* Khb = g_Kh + (size_t)h * TSEQ * DHEAD;
    const __nv_bfloat16* Klb = g_Kl + (size_t)h * TSEQ * DHEAD;
    const __nv_bfloat16* Vhb = g_Vh + (size_t)h * TSEQ * DHEAD;
    const __nv_bfloat16* Vlb = g_Vl + (size_t)h * TSEQ * DHEAD;

    const int sr = tid >> 4;            /* 0..7  */
    const int sc = tid & 15;            /* 0..15 */

    /* ---- stage Q (64 rows), LDSM into regs ---- */
#pragma unroll
    for (int p = 0; p < 8; p++) {
        const int r = sr + (p << 3);
        CPA16(sb + SM_KH + offV(r, sc), Qhb + (size_t)(qb + r) * DHEAD + sc * 8);
        CPA16(sb + SM_KL + offV(r, sc), Qlb + (size_t)(qb + r) * DHEAD + sc * 8);
    }
    CPA_COMMIT(); CPA_WAIT0();
    __syncthreads();

    uint32_t qh[8][4], ql[8][4];
#pragma unroll
    for (int ks = 0; ks < 8; ks++) {
        const uint32_t ad = offV(w16 + (lane & 15), (ks << 1) + (lane >> 4));
        LDSM4(qh[ks][0], qh[ks][1], qh[ks][2], qh[ks][3], sb + SM_KH + ad);
        LDSM4(ql[ks][0], ql[ks][1], ql[ks][2], ql[ks][3], sb + SM_KL + ad);
    }
    __syncthreads();

    float O[16][4];
#pragma unroll
    for (int nt = 0; nt < 16; nt++)
#pragma unroll
        for (int i = 0; i < 4; i++) O[nt][i] = 0.f;
    float m0 = -1e30f, m1 = -1e30f, l0 = 0.f, l1 = 0.f;

    const int ntiles = qblk + 1;
    const int row0 = qb + w16 + (lane >> 2);
    const int row1 = row0 + 8;

    for (int kt = 0; kt < ntiles; kt++) {
        const int kb = kt << 6;

        /* stage K (group A), then V (group B) */
#pragma unroll
        for (int p = 0; p < 8; p++) {
            const int r = sr + (p << 3);
            const size_t gi = (size_t)(kb + r) * DHEAD + sc * 8;
            const uint32_t so = offV(r, sc);
            CPA16(sb + SM_KH + so, Khb + gi);
            CPA16(sb + SM_KL + so, Klb + gi);
        }
        CPA_COMMIT();
#pragma unroll
        for (int p = 0; p < 8; p++) {
            const int r = sr + (p << 3);
            const size_t gi = (size_t)(kb + r) * DHEAD + sc * 8;
            const uint32_t so = offV(r, sc);
            CPA16(sb + SM_VH + so, Vhb + gi);
            CPA16(sb + SM_VL + so, Vlb + gi);
        }
        CPA_COMMIT();
        CPA_WAIT1();                      /* K ready; V still in flight */
        __syncthreads();

        /* ---- scores S = Q K^T ---- */
        float S[8][4];
#pragma unroll
        for (int nt = 0; nt < 8; nt++)
#pragma unroll
            for (int i = 0; i < 4; i++) S[nt][i] = 0.f;

#pragma unroll
        for (int ntp = 0; ntp < 4; ntp++) {
#pragma unroll
            for (int ks = 0; ks < 8; ks++) {
                const uint32_t ad = offV((ntp << 4) + (lane & 15),
                                         (ks << 1) + (lane >> 4));
                uint32_t kh0, kh1, kh2, kh3, kl0, kl1, kl2, kl3;
                LDSM4(kh0, kh1, kh2, kh3, sb + SM_KH + ad);
                LDSM4(kl0, kl1, kl2, kl3, sb + SM_KL + ad);
                MMA_BF16(S[2 * ntp],     qh[ks], kh0, kh2);
                MMA_BF16(S[2 * ntp],     qh[ks], kl0, kl2);
                MMA_BF16(S[2 * ntp],     ql[ks], kh0, kh2);
                MMA_BF16(S[2 * ntp + 1], qh[ks], kh1, kh3);
                MMA_BF16(S[2 * ntp + 1], qh[ks], kl1, kl3);
                MMA_BF16(S[2 * ntp + 1], ql[ks], kh1, kh3);
            }
        }

        /* ---- causal mask on diagonal tile ---- */
        if (kb == qb) {
#pragma unroll
            for (int nt = 0; nt < 8; nt++) {
                const int key = kb + (nt << 3) + ((lane & 3) << 1);
                if (key > row0)     S[nt][0] = -1e30f;
                if (key + 1 > row0) S[nt][1] = -1e30f;
                if (key > row1)     S[nt][2] = -1e30f;
                if (key + 1 > row1) S[nt][3] = -1e30f;
            }
        }

        /* ---- online softmax ---- */
        float mx0 = -1e30f, mx1 = -1e30f;
#pragma unroll
        for (int nt = 0; nt < 8; nt++) {
            mx0 = fmaxf(mx0, fmaxf(S[nt][0], S[nt][1]));
            mx1 = fmaxf(mx1, fmaxf(S[nt][2], S[nt][3]));
        }
        mx0 = fmaxf(mx0, __shfl_xor_sync(0xffffffffu, mx0, 1));
        mx0 = fmaxf(mx0, __shfl_xor_sync(0xffffffffu, mx0, 2));
        mx1 = fmaxf(mx1, __shfl_xor_sync(0xffffffffu, mx1, 1));
        mx1 = fmaxf(mx1, __shfl_xor_sync(0xffffffffu, mx1, 2));

        const float m0n = fmaxf(m0, mx0), m1n = fmaxf(m1, mx1);
        const float a0 = __expf(m0 - m0n), a1 = __expf(m1 - m1n);
        m0 = m0n; m1 = m1n;

        uint32_t aH[4][4], aL[4][4];
        float ps0 = 0.f, ps1 = 0.f;
#pragma unroll
        for (int nt = 0; nt < 8; nt++) {
            const float p0 = __expf(S[nt][0] - m0n);
            const float p1 = __expf(S[nt][1] - m0n);
            const float p2 = __expf(S[nt][2] - m1n);
            const float p3 = __expf(S[nt][3] - m1n);
            ps0 += p0 + p1; ps1 += p2 + p3;
            const float h0 = __bfloat162float(__float2bfloat16_rn(p0));
            const float h1 = __bfloat162float(__float2bfloat16_rn(p1));
            const float h2 = __bfloat162float(__float2bfloat16_rn(p2));
            const float h3 = __bfloat162float(__float2bfloat16_rn(p3));
            const int kk = nt >> 1;
            const int e  = (nt & 1) << 1;
            aH[kk][e]     = bf2pack(p0, p1);
            aH[kk][e + 1] = bf2pack(p2, p3);
            aL[kk][e]     = bf2pack(p0 - h0, p1 - h1);
            aL[kk][e + 1] = bf2pack(p2 - h2, p3 - h3);
        }
        ps0 += __shfl_xor_sync(0xffffffffu, ps0, 1);
        ps0 += __shfl_xor_sync(0xffffffffu, ps0, 2);
        ps1 += __shfl_xor_sync(0xffffffffu, ps1, 1);
        ps1 += __shfl_xor_sync(0xffffffffu, ps1, 2);
        l0 = l0 * a0 + ps0;
        l1 = l1 * a1 + ps1;

#pragma unroll
        for (int nt = 0; nt < 16; nt++) {
            O[nt][0] *= a0; O[nt][1] *= a0;
            O[nt][2] *= a1; O[nt][3] *= a1;
        }

        CPA_WAIT0();                      /* V ready */
        __syncthreads();

        /* ---- O += P V ---- */
#pragma unroll
        for (int kk = 0; kk < 4; kk++) {
#pragma unroll
            for (int ntp = 0; ntp < 8; ntp++) {
                const uint32_t ad = offV((kk << 4) + (lane & 15),
                                         (ntp << 1) + (lane >> 4));
                uint32_t vh0, vh1, vh2, vh3, vl0, vl1, vl2, vl3;
                LDSM4T(vh0, vh1, vh2, vh3, sb + SM_VH + ad);
                LDSM4T(vl0, vl1, vl2, vl3, sb + SM_VL + ad);
                MMA_BF16(O[2 * ntp],     aH[kk], vh0, vh1);
                MMA_BF16(O[2 * ntp],     aH[kk], vl0, vl1);
                MMA_BF16(O[2 * ntp],     aL[kk], vh0, vh1);
                MMA_BF16(O[2 * ntp + 1], aH[kk], vh2, vh3);
                MMA_BF16(O[2 * ntp + 1], aH[kk], vl2, vl3);
                MMA_BF16(O[2 * ntp + 1], aL[kk], vh2, vh3);
            }
        }
        __syncthreads();
    }

    /* ---- epilogue ---- */
    const float inv0 = 1.0f / l0, inv1 = 1.0f / l1;
#pragma unroll
    for (int nt = 0; nt < 16; nt++) {
        const int d = (nt << 3) + ((lane & 3) << 1);
        const float v0 = O[nt][0] * inv0, v1 = O[nt][1] * inv0;
        const float v2 = O[nt][2] * inv1, v3 = O[nt][3] * inv1;
        const float h0 = __bfloat162float(__float2bfloat16_rn(v0));
        const float h1 = __bfloat162float(__float2bfloat16_rn(v1));
        const float h2 = __bfloat162float(__float2bfloat16_rn(v2));
        const float h3 = __bfloat162float(__float2bfloat16_rn(v3));
        const size_t i0 = (size_t)row0 * DMODEL + h * DHEAD + d;
        const size_t i1 = (size_t)row1 * DMODEL + h * DHEAD + d;
        *(uint32_t*)(g_Oh + i0) = bf2pack(v0, v1);
        *(uint32_t*)(g_Ol + i0) = bf2pack(v0 - h0, v1 - h1);
        *(uint32_t*)(g_Oh + i1) = bf2pack(v2, v3);
        *(uint32_t*)(g_Ol + i1) = bf2pack(v2 - h2, v3 - h3);
    }
}

/* ------------------------------------------------------------------ */
extern "C" void kernel_launch(void* const* d_in, const int* in_sizes, int n_in,
                              void* d_out, int out_size)
{
    const float* x        = (const float*)d_in[0];
    const float* Wq_down  = (const float*)d_in[1];
    const float* Wq_up    = (const float*)d_in[2];
    const float* Wq_rope  = (const float*)d_in[3];
    const float* Wkv_down = (const float*)d_in[4];
    const float* Wk_up    = (const float*)d_in[5];
    const float* Wv_up    = (const float*)d_in[6];
    const float* Wk_rope  = (const float*)d_in[7];
    const float* Wo       = (const float*)d_in[8];
    float* out = (float*)d_out;

    float *qc, *qr, *kc, *kr;
    cudaGetSymbolAddress((void**)&qc, g_qc);
    cudaGetSymbolAddress((void**)&qr, g_qr);
    cudaGetSymbolAddress((void**)&kc, g_kc);
    cudaGetSymbolAddress((void**)&kr, g_kr);

    __nv_bfloat16 *xh, *xl, *qdh, *qdl, *kvh, *kvl, *Oh, *Ol, *Vh, *Vl;
    __nv_bfloat16 *wqdh, *wqdl, *wquh, *wqul, *wqrh, *wqrl, *wkdh, *wkdl;
    __nv_bfloat16 *wkuh, *wkul, *wvuh, *wvul, *wkrh, *wkrl, *woh, *wol;
    cudaGetSymbolAddress((void**)&xh, g_xh);   cudaGetSymbolAddress((void**)&xl, g_xl);
    cudaGetSymbolAddress((void**)&qdh, g_qdh); cudaGetSymbolAddress((void**)&qdl, g_qdl);
    cudaGetSymbolAddress((void**)&kvh, g_kvh); cudaGetSymbolAddress((void**)&kvl, g_kvl);
    cudaGetSymbolAddress((void**)&Oh, g_Oh);   cudaGetSymbolAddress((void**)&Ol, g_Ol);
    cudaGetSymbolAddress((void**)&Vh, g_Vh);   cudaGetSymbolAddress((void**)&Vl, g_Vl);
    cudaGetSymbolAddress((void**)&wqdh, g_wqdh); cudaGetSymbolAddress((void**)&wqdl, g_wqdl);
    cudaGetSymbolAddress((void**)&wquh, g_wquh); cudaGetSymbolAddress((void**)&wqul, g_wqul);
    cudaGetSymbolAddress((void**)&wqrh, g_wqrh); cudaGetSymbolAddress((void**)&wqrl, g_wqrl);
    cudaGetSymbolAddress((void**)&wkdh, g_wkdh); cudaGetSymbolAddress((void**)&wkdl, g_wkdl);
    cudaGetSymbolAddress((void**)&wkuh, g_wkuh); cudaGetSymbolAddress((void**)&wkul, g_wkul);
    cudaGetSymbolAddress((void**)&wvuh, g_wvuh); cudaGetSymbolAddress((void**)&wvul, g_wvul);
    cudaGetSymbolAddress((void**)&wkrh, g_wkrh); cudaGetSymbolAddress((void**)&wkrl, g_wkrl);
    cudaGetSymbolAddress((void**)&woh, g_woh);   cudaGetSymbolAddress((void**)&wol, g_wol);

    cudaFuncSetAttribute(gemm_fused,
                         cudaFuncAttributeMaxDynamicSharedMemorySize, 65536);
    cudaFuncSetAttribute(attn_mma,
                         cudaFuncAttributeMaxDynamicSharedMemorySize, 65536);

    /* 0. rope table */
    rope_table<<<256, 256>>>();

    /* 1. split inputs + weights */
    SplitJobs js;
    js.j[0] = { x,        xh,   xl,   TSEQ * 2048 };
    js.j[1] = { Wq_down,  wqdh, wqdl, 2048 * 512  };
    js.j[2] = { Wq_up,    wquh, wqul, 512 * 1024  };
    js.j[3] = { Wq_rope,  wqrh, wqrl, 2048 * 1024 };
    js.j[4] = { Wkv_down, wkdh, wkdl, 2048 * 512  };
    js.j[5] = { Wk_up,    wkuh, wkul, 512 * 1024  };
    js.j[6] = { Wv_up,    wvuh, wvul, 512 * 2048  };
    js.j[7] = { Wk_rope,  wkrh, wkrl, 2048 * 1024 };
    js.j[8] = { Wo,       woh,  wol,  2048 * 2048 };
    split_many<<<dim3(4096, 9), 256>>>(js);

    /* 2. GEMM1: x @ [Wq_down | Wkv_down | Wq_rope | Wk_rope] */
    {
        GSegs g; g.n = 4;
        g.s[0] = { xh, xl, 2048, wqdh, wqdl, nullptr, qdh, qdl,  512, 2048, 0,  0 };
        g.s[1] = { xh, xl, 2048, wkdh, wkdl, nullptr, kvh, kvl,  512, 2048, 4,  0 };
        g.s[2] = { xh, xl, 2048, wqrh, wqrl, qr, nullptr, nullptr, 1024, 2048, 8,  0 };
        g.s[3] = { xh, xl, 2048, wkrh, wkrl, kr, nullptr, nullptr, 1024, 2048, 16, 0 };
        gemm_fused<<<dim3(24, 16), 256, 65536>>>(g);
    }

    /* 3. GEMM2: qd @ Wq_up ; kv @ [Wk_up | Wv_up (-> Vh/Vl permuted)] */
    {
        GSegs g; g.n = 3;
        g.s[0] = { qdh, qdl, 512, wquh, wqul, qc, nullptr, nullptr, 1024, 512, 0,  0 };
        g.s[1] = { kvh, kvl, 512, wkuh, wkul, kc, nullptr, nullptr, 1024, 512, 8,  0 };
        g.s[2] = { kvh, kvl, 512, wvuh, wvul, nullptr, Vh, Vl,      2048, 512, 16, 1 };
        g.s[3] = g.s[0];
        gemm_fused<<<dim3(32, 16), 256, 65536>>>(g);
    }

    /* 4. rope + pack Q/K */
    pack_kernel<<<dim3(TSEQ, NH), 64>>>();

    /* 5. tensor-core causal attention */
    attn_mma<<<dim3(32, NH), 128, 65536>>>();

    /* 6. GEMM3: O @ Wo -> out */
    {
        GSegs g; g.n = 1;
        g.s[0] = { Oh, Ol, 2048, woh, wol, out, nullptr, nullptr, 2048, 2048, 0, 0 };
        g.s[1] = g.s[0]; g.s[2] = g.s[0]; g.s[3] = g.s[0];
        gemm_fused<<<dim3(16, 16), 256, 65536>>>(g);
    }
}

// round 11
// speedup vs baseline: 1.2358x; 1.2214x over previous
#include <cuda_runtime.h>
#include <cuda_bf16.h>
#include <cuda_fp16.h>
#include <math.h>
#include <stdint.h>

#define TSEQ   2048
#define DMODEL 2048
#define NH     16
#define DHEAD  128
#define DROPE  64
#define DCONT  64
#define SCALE_ATT 0.08838834764831845f  /* 1/sqrt(128) */

/* ------------------------------------------------------------------ */
/* Scratch (device globals)                                            */
/* ------------------------------------------------------------------ */
__device__ float g_qc[TSEQ * 1024];
__device__ float g_qr[TSEQ * 1024];
__device__ float g_kc[TSEQ * 1024];
__device__ float g_kr[TSEQ * 1024];
__device__ float g_cosT[TSEQ * 32];
__device__ float g_sinT[TSEQ * 32];

/* attention operands, bf16 hi/lo, [h][t][d] */
__device__ __nv_bfloat16 g_Qh[NH * TSEQ * DHEAD], g_Ql[NH * TSEQ * DHEAD];
__device__ __nv_bfloat16 g_Kh[NH * TSEQ * DHEAD], g_Kl[NH * TSEQ * DHEAD];
__device__ __nv_bfloat16 g_Vh[NH * TSEQ * DHEAD], g_Vl[NH * TSEQ * DHEAD];

/* fp16 GEMM operands: activations hi/lo, weights hi only              */
__device__ __half g_xh[TSEQ * 2048],  g_xl[TSEQ * 2048];
__device__ __half g_qdh[TSEQ * 512],  g_qdl[TSEQ * 512];
__device__ __half g_kvh[TSEQ * 512],  g_kvl[TSEQ * 512];
__device__ __half g_Oh[TSEQ * 2048],  g_Ol[TSEQ * 2048];
__device__ __half g_wqd[2048 * 512];
__device__ __half g_wqu[512 * 1024];
__device__ __half g_wqr[2048 * 1024];
__device__ __half g_wkd[2048 * 512];
__device__ __half g_wku[512 * 1024];
__device__ __half g_wvu[512 * 2048];
__device__ __half g_wkr[2048 * 1024];
__device__ __half g_wo [2048 * 2048];

/* ------------------------------------------------------------------ */
/* asm helpers                                                         */
/* ------------------------------------------------------------------ */
#define CPA16(dst, src)                                                    \
    asm volatile("cp.async.cg.shared.global [%0], [%1], 16;"               \
                 :: "r"(dst), "l"(src))
#define CPA_COMMIT() asm volatile("cp.async.commit_group;")
#define CPA_WAIT1()  asm volatile("cp.async.wait_group 1;")
#define CPA_WAIT0()  asm volatile("cp.async.wait_group 0;")

#define LDSM4(r0, r1, r2, r3, addr)                                        \
    asm volatile("ldmatrix.sync.aligned.m8n8.x4.shared.b16 {%0,%1,%2,%3}, [%4];" \
                 : "=r"(r0), "=r"(r1), "=r"(r2), "=r"(r3) : "r"(addr))
#define LDSM4T(r0, r1, r2, r3, addr)                                       \
    asm volatile("ldmatrix.sync.aligned.m8n8.x4.trans.shared.b16 {%0,%1,%2,%3}, [%4];" \
                 : "=r"(r0), "=r"(r1), "=r"(r2), "=r"(r3) : "r"(addr))
#define MMA_BF16(c, a, b0, b1)                                             \
    asm volatile("mma.sync.aligned.m16n8k16.row.col.f32.bf16.bf16.f32 "    \
                 "{%0,%1,%2,%3}, {%4,%5,%6,%7}, {%8,%9}, {%0,%1,%2,%3};"   \
                 : "+f"(c[0]), "+f"(c[1]), "+f"(c[2]), "+f"(c[3])          \
                 : "r"(a[0]), "r"(a[1]), "r"(a[2]), "r"(a[3]),             \
                   "r"(b0), "r"(b1))
#define MMA_F16(c, a, b0, b1)                                              \
    asm volatile("mma.sync.aligned.m16n8k16.row.col.f32.f16.f16.f32 "      \
                 "{%0,%1,%2,%3}, {%4,%5,%6,%7}, {%8,%9}, {%0,%1,%2,%3};"   \
                 : "+f"(c[0]), "+f"(c[1]), "+f"(c[2]), "+f"(c[3])          \
                 : "r"(a[0]), "r"(a[1]), "r"(a[2]), "r"(a[3]),             \
                   "r"(b0), "r"(b1))

__device__ __forceinline__ uint32_t bf2pack(float a, float b)
{
    return (uint32_t)__bfloat16_as_ushort(__float2bfloat16_rn(a)) |
           ((uint32_t)__bfloat16_as_ushort(__float2bfloat16_rn(b)) << 16);
}
__device__ __forceinline__ uint32_t hf2pack(float a, float b)
{
    return (uint32_t)__half_as_ushort(__float2half_rn(a)) |
           ((uint32_t)__half_as_ushort(__float2half_rn(b)) << 16);
}

/* ------------------------------------------------------------------ */
/* RoPE table                                                          */
/* ------------------------------------------------------------------ */
__global__ void __launch_bounds__(256) rope_table()
{
    const int idx = blockIdx.x * 256 + threadIdx.x;
    if (idx >= TSEQ * 32) return;
    const int t = idx >> 5, i = idx & 31;
    const double inv = pow(10000.0, -(double)i / 32.0);
    double sd, cd;
    sincos((double)t * inv, &sd, &cd);
    g_cosT[idx] = (float)cd;
    g_sinT[idx] = (float)sd;
}

/* ------------------------------------------------------------------ */
/* Batched fp32 -> fp16 split; l==null -> hi only                      */
/* ------------------------------------------------------------------ */
struct SplitJob { const float* src; __half *h, *l; int n; };
struct SplitJobs { SplitJob j[9]; };

__global__ void __launch_bounds__(256) split_many(SplitJobs js)
{
    const SplitJob J = js.j[blockIdx.y];
    const int i = (blockIdx.x * 256 + threadIdx.x) << 2;
    if (i >= J.n) return;
    float4 v = *(const float4*)(J.src + i);
    uint2 hp;
    hp.x = hf2pack(v.x, v.y);  hp.y = hf2pack(v.z, v.w);
    *(uint2*)(J.h + i) = hp;
    if (J.l) {
        const float h0 = __half2float(__float2half_rn(v.x));
        const float h1 = __half2float(__float2half_rn(v.y));
        const float h2 = __half2float(__float2half_rn(v.z));
        const float h3 = __half2float(__float2half_rn(v.w));
        uint2 lp;
        lp.x = hf2pack(v.x - h0, v.y - h1);
        lp.y = hf2pack(v.z - h2, v.w - h3);
        *(uint2*)(J.l + i) = lp;
    }
}

/* ------------------------------------------------------------------ */
/* Fused multi-segment fp16 tensor-core GEMM.                          */
/* C = (Ah+Al) @ B ;  A split fp16 hi/lo, B single fp16.               */
/* BM=BN=128, BK=32, 256 threads (8 warps 4x2, warp tile 32x64).       */
/* 2-stage cp.async, 48KB smem -> 2 CTAs per SM.                       */
/* ------------------------------------------------------------------ */
struct GSeg {
    const __half *Ah, *Al;
    int lda;
    const __half *Bh;          /* [K,N] row-major fp16 */
    float* Cf;                 /* fp32 out, or null */
    void *Ch, *Cl;             /* split out: fp16 (vperm=0) or bf16 (vperm=1) */
    int N, K, tile0, vperm;
};
struct GSegs { GSeg s[4]; int n; };

#define STAGE_BYTES 24576
#define A_LO_OFF    8192
#define B_HI_OFF    16384

/* A tile: 128 rows x 4 chunks(16B) = 128x32 fp16 */
__device__ __forceinline__ uint32_t offA(int r, int c)
{ return (uint32_t)(((r << 2) + (c ^ ((r >> 1) & 3))) << 4); }
/* B tile: 32 rows x 16 chunks(16B) = 32x128 fp16 */
__device__ __forceinline__ uint32_t offB(int r, int c)
{ return (uint32_t)(((r << 4) + (c ^ (r & 7))) << 4); }

__global__ void __launch_bounds__(256, 2) gemm_fused(GSegs segs)
{
    extern __shared__ char dsm[];
    const uint32_t sb = (uint32_t)__cvta_generic_to_shared(dsm);

    const int tid  = threadIdx.x;
    const int lane = tid & 31;
    const int warp = tid >> 5;
    const int wm   = (warp >> 1) << 5;
    const int wn   = (warp & 1) << 6;
    const int bm   = blockIdx.y << 7;

    GSeg sg = segs.s[0];
#pragma unroll
    for (int i = 1; i < 4; i++)
        if (i < segs.n && (int)blockIdx.x >= segs.s[i].tile0) sg = segs.s[i];
    const int bn  = ((int)blockIdx.x - sg.tile0) << 7;
    const int lda = sg.lda, ldb = sg.N, K = sg.K;

    const int ar = tid >> 2, ac = tid & 3;
    const int br = tid >> 3, bc = tid & 7;
    const uint32_t aoff0 = offA(ar, ac), aoff1 = offA(ar + 64, ac);
    const uint32_t boff0 = offB(br, bc), boff1 = offB(br, bc + 8);

    const __half* gAh = sg.Ah + (size_t)(bm + ar) * lda + ac * 8;
    const __half* gAl = sg.Al + (size_t)(bm + ar) * lda + ac * 8;
    const __half* gBh = sg.Bh + (size_t)br * ldb + bn + bc * 8;

    float acc[2][8][4];
#pragma unroll
    for (int mt = 0; mt < 2; mt++)
#pragma unroll
        for (int nt = 0; nt < 8; nt++)
#pragma unroll
            for (int i = 0; i < 4; i++) acc[mt][nt][i] = 0.f;

    const int nk = K >> 5;

    auto load_stage = [&](int st, int k0) {
        const uint32_t s0 = sb + st * STAGE_BYTES;
        const __half* pAh = gAh + k0;
        const __half* pAl = gAl + k0;
        CPA16(s0 + aoff0, pAh);
        CPA16(s0 + aoff1, pAh + (size_t)64 * lda);
        CPA16(s0 + A_LO_OFF + aoff0, pAl);
        CPA16(s0 + A_LO_OFF + aoff1, pAl + (size_t)64 * lda);
        const __half* pBh = gBh + (size_t)k0 * ldb;
        CPA16(s0 + B_HI_OFF + boff0, pBh);
        CPA16(s0 + B_HI_OFF + boff1, pBh + 64);
    };

    load_stage(0, 0);
    CPA_COMMIT();

    for (int it = 0; it < nk; it++) {
        if (it + 1 < nk) { load_stage((it + 1) & 1, (it + 1) << 5); CPA_COMMIT(); }
        if (it + 1 < nk) CPA_WAIT1(); else CPA_WAIT0();
        __syncthreads();

        const uint32_t s0 = sb + (it & 1) * STAGE_BYTES;
#pragma unroll
        for (int ks = 0; ks < 2; ks++) {
            uint32_t ah[2][4], al_[2][4];
#pragma unroll
            for (int mt = 0; mt < 2; mt++) {
                const int rowA   = wm + (mt << 4) + (lane & 15);
                const int chunkA = (ks << 1) + (lane >> 4);
                const uint32_t ad = s0 + offA(rowA, chunkA);
                LDSM4(ah[mt][0], ah[mt][1], ah[mt][2], ah[mt][3], ad);
                LDSM4(al_[mt][0], al_[mt][1], al_[mt][2], al_[mt][3], ad + A_LO_OFF);
            }
#pragma unroll
            for (int np = 0; np < 4; np++) {
                const int rowB   = (ks << 4) + (lane & 15);
                const int chunkB = (wn >> 3) + (lane >> 4) + (np << 1);
                const uint32_t bd = s0 + B_HI_OFF + offB(rowB, chunkB);
                uint32_t h0, h1, h2, h3;
                LDSM4T(h0, h1, h2, h3, bd);
#pragma unroll
                for (int mt = 0; mt < 2; mt++) {
                    MMA_F16(acc[mt][2 * np],     ah[mt],  h0, h1);
                    MMA_F16(acc[mt][2 * np],     al_[mt], h0, h1);
                    MMA_F16(acc[mt][2 * np + 1], ah[mt],  h2, h3);
                    MMA_F16(acc[mt][2 * np + 1], al_[mt], h2, h3);
                }
            }
        }
        __syncthreads();
    }

    const int erow = lane >> 2;
    const int ecol = (lane & 3) << 1;
    if (sg.Cf) {
#pragma unroll
        for (int mt = 0; mt < 2; mt++)
#pragma unroll
            for (int nt = 0; nt < 8; nt++) {
                const int r = bm + wm + (mt << 4) + erow;
                const int c = bn + wn + (nt << 3) + ecol;
                *(float2*)(sg.Cf + (size_t)r * ldb + c) =
                    make_float2(acc[mt][nt][0], acc[mt][nt][1]);
                *(float2*)(sg.Cf + (size_t)(r + 8) * ldb + c) =
                    make_float2(acc[mt][nt][2], acc[mt][nt][3]);
            }
    } else if (sg.vperm) {
        /* bf16 hi/lo split out, remapped [t][h*128+d] -> [h][t][d] (V) */
        __nv_bfloat16* Ch = (__nv_bfloat16*)sg.Ch;
        __nv_bfloat16* Cl = (__nv_bfloat16*)sg.Cl;
#pragma unroll
        for (int mt = 0; mt < 2; mt++)
#pragma unroll
            for (int nt = 0; nt < 8; nt++) {
                const int r = bm + wm + (mt << 4) + erow;
                const int c = bn + wn + (nt << 3) + ecol;
#pragma unroll
                for (int hh = 0; hh < 2; hh++) {
                    const float v0 = acc[mt][nt][2 * hh];
                    const float v1 = acc[mt][nt][2 * hh + 1];
                    const float h0 = __bfloat162float(__float2bfloat16_rn(v0));
                    const float h1 = __bfloat162float(__float2bfloat16_rn(v1));
                    const int rr = r + 8 * hh;
                    const size_t idx =
                        ((size_t)(c >> 7) * TSEQ + rr) * DHEAD + (c & 127);
                    *(uint32_t*)(Ch + idx) = bf2pack(v0, v1);
                    *(uint32_t*)(Cl + idx) = bf2pack(v0 - h0, v1 - h1);
                }
            }
    } else {
        /* fp16 hi/lo split out (qd, kv) */
        __half* Ch = (__half*)sg.Ch;
        __half* Cl = (__half*)sg.Cl;
#pragma unroll
        for (int mt = 0; mt < 2; mt++)
#pragma unroll
            for (int nt = 0; nt < 8; nt++) {
                const int r = bm + wm + (mt << 4) + erow;
                const int c = bn + wn + (nt << 3) + ecol;
#pragma unroll
                for (int hh = 0; hh < 2; hh++) {
                    const float v0 = acc[mt][nt][2 * hh];
                    const float v1 = acc[mt][nt][2 * hh + 1];
                    const float h0 = __half2float(__float2half_rn(v0));
                    const float h1 = __half2float(__float2half_rn(v1));
                    const size_t idx = (size_t)(r + 8 * hh) * ldb + c;
                    *(uint32_t*)(Ch + idx) = hf2pack(v0, v1);
                    *(uint32_t*)(Cl + idx) = hf2pack(v0 - h0, v1 - h1);
                }
            }
    }
}

/* ------------------------------------------------------------------ */
/* Pack + RoPE -> Qh/Ql (pre-scaled), Kh/Kl bf16 in [h][t][d].         */
/* ------------------------------------------------------------------ */
__global__ void __launch_bounds__(64) pack_kernel()
{
    const int t = blockIdx.x;
    const int h = blockIdx.y;
    const int d2 = threadIdx.x << 1;
    const size_t o = ((size_t)h * TSEQ + t) * DHEAD + d2;

    float q0, q1, k0, k1;
    if (d2 < DCONT) {
        const size_t b = (size_t)t * 1024 + h * DCONT + d2;
        q0 = g_qc[b];     q1 = g_qc[b + 1];
        k0 = g_kc[b];     k1 = g_kc[b + 1];
    } else {
        const int i = d2 - DCONT;
        const int ip = (i < 32) ? i : i - 32;
        const float c0 = g_cosT[t * 32 + ip],     s0 = g_sinT[t * 32 + ip];
        const float c1 = g_cosT[t * 32 + ip + 1], s1 = g_sinT[t * 32 + ip + 1];
        const size_t b = (size_t)t * 1024 + h * DROPE;
        const float qa0 = g_qr[b + ip],      qa1 = g_qr[b + ip + 1];
        const float qb0 = g_qr[b + 32 + ip], qb1 = g_qr[b + 32 + ip + 1];
        const float ka0 = g_kr[b + ip],      ka1 = g_kr[b + ip + 1];
        const float kb0 = g_kr[b + 32 + ip], kb1 = g_kr[b + 32 + ip + 1];
        if (i < 32) {
            q0 = qa0 * c0 - qb0 * s0;  q1 = qa1 * c1 - qb1 * s1;
            k0 = ka0 * c0 - kb0 * s0;  k1 = ka1 * c1 - kb1 * s1;
        } else {
            q0 = qa0 * s0 + qb0 * c0;  q1 = qa1 * s1 + qb1 * c1;
            k0 = ka0 * s0 + kb0 * c0;  k1 = ka1 * s1 + kb1 * c1;
        }
    }
    q0 *= SCALE_ATT; q1 *= SCALE_ATT;

    const float qh0 = __bfloat162float(__float2bfloat16_rn(q0));
    const float qh1 = __bfloat162float(__float2bfloat16_rn(q1));
    const float kh0 = __bfloat162float(__float2bfloat16_rn(k0));
    const float kh1 = __bfloat162float(__float2bfloat16_rn(k1));
    *(uint32_t*)(g_Qh + o) = bf2pack(q0, q1);
    *(uint32_t*)(g_Ql + o) = bf2pack(q0 - qh0, q1 - qh1);
    *(uint32_t*)(g_Kh + o) = bf2pack(k0, k1);
    *(uint32_t*)(g_Kl + o) = bf2pack(k0 - kh0, k1 - kh1);
}

/* ------------------------------------------------------------------ */
/* Tensor-core causal flash attention (split bf16, unchanged core).    */
/* Epilogue writes O as fp16 hi/lo for the fp16 GEMM3.                 */
/* ------------------------------------------------------------------ */
__device__ __forceinline__ uint32_t offV(int r, int c)
{ return (uint32_t)(((r << 4) + (c ^ (r & 7))) << 4); }   /* 16 chunks/row */

#define SM_KH 0
#define SM_KL 16384
#define SM_VH 32768
#define SM_VL 49152

__global__ void __launch_bounds__(128) attn_mma()
{
    extern __shared__ char dsm[];
    const uint32_t sb = (uint32_t)__cvta_generic_to_shared(dsm);

    const int h    = blockIdx.y;
    const int qblk = 31 - (int)blockIdx.x;
    const int qb   = qblk << 6;
    const int tid  = threadIdx.x;
    const int lane = tid & 31;
    const int warp = tid >> 5;
    const int w16  = warp << 4;

    const __nv_bfloat16* Qhb = g_Qh + (size_t)h * TSEQ * DHEAD;
    const __nv_bfloat16* Qlb = g_Ql + (size_t)h * TSEQ * DHEAD;
    const __nv_bfloat16* Khb = g_Kh + (size_t)h * TSEQ * DHEAD;
    const __nv_bfloat16* Klb = g_Kl + (size_t)h * TSEQ * DHEAD;
    const __nv_bfloat16* Vhb = g_Vh + (size_t)h * TSEQ * DHEAD;
    const __nv_bfloat16* Vlb = g_Vl + (size_t)h * TSEQ * DHEAD;

    const int sr = tid >> 4;
    const int sc = tid & 15;

#pragma unroll
    for (int p = 0; p < 8; p++) {
        const int r = sr + (p << 3);
        CPA16(sb + SM_KH + offV(r, sc), Qhb + (size_t)(qb + r) * DHEAD + sc * 8);
        CPA16(sb + SM_KL + offV(r, sc), Qlb + (size_t)(qb + r) * DHEAD + sc * 8);
    }
    CPA_COMMIT(); CPA_WAIT0();
    __syncthreads();

    uint32_t qh[8][4], ql[8][4];
#pragma unroll
    for (int ks = 0; ks < 8; ks++) {
        const uint32_t ad = offV(w16 + (lane & 15), (ks << 1) + (lane >> 4));
        LDSM4(qh[ks][0], qh[ks][1], qh[ks][2], qh[ks][3], sb + SM_KH + ad);
        LDSM4(ql[ks][0], ql[ks][1], ql[ks][2], ql[ks][3], sb + SM_KL + ad);
    }
    __syncthreads();

    float O[16][4];
#pragma unroll
    for (int nt = 0; nt < 16; nt++)
#pragma unroll
        for (int i = 0; i < 4; i++) O[nt][i] = 0.f;
    float m0 = -1e30f, m1 = -1e30f, l0 = 0.f, l1 = 0.f;

    const int ntiles = qblk + 1;
    const int row0 = qb + w16 + (lane >> 2);
    const int row1 = row0 + 8;

    for (int kt = 0; kt < ntiles; kt++) {
        const int kb = kt << 6;
#pragma unroll
        for (int p = 0; p < 8; p++) {
            const int r = sr + (p << 3);
            const size_t gi = (size_t)(kb + r) * DHEAD + sc * 8;
            const uint32_t so = offV(r, sc);
            CPA16(sb + SM_KH + so, Khb + gi);
            CPA16(sb + SM_KL + so, Klb + gi);
        }
        CPA_COMMIT();
#pragma unroll
        for (int p = 0; p < 8; p++) {
            const int r = sr + (p << 3);
            const size_t gi = (size_t)(kb + r) * DHEAD + sc * 8;
            const uint32_t so = offV(r, sc);
            CPA16(sb + SM_VH + so, Vhb + gi);
            CPA16(sb + SM_VL + so, Vlb + gi);
        }
        CPA_COMMIT();
        CPA_WAIT1();
        __syncthreads();

        float S[8][4];
#pragma unroll
        for (int nt = 0; nt < 8; nt++)
#pragma unroll
            for (int i = 0; i < 4; i++) S[nt][i] = 0.f;

#pragma unroll
        for (int ntp = 0; ntp < 4; ntp++) {
#pragma unroll
            for (int ks = 0; ks < 8; ks++) {
                const uint32_t ad = offV((ntp << 4) + (lane & 15),
                                         (ks << 1) + (lane >> 4));
                uint32_t kh0, kh1, kh2, kh3, kl0, kl1, kl2, kl3;
                LDSM4(kh0, kh1, kh2, kh3, sb + SM_KH + ad);
                LDSM4(kl0, kl1, kl2, kl3, sb + SM_KL + ad);
                MMA_BF16(S[2 * ntp],     qh[ks], kh0, kh2);
                MMA_BF16(S[2 * ntp],     qh[ks], kl0, kl2);
                MMA_BF16(S[2 * ntp],     ql[ks], kh0, kh2);
                MMA_BF16(S[2 * ntp + 1], qh[ks], kh1, kh3);
                MMA_BF16(S[2 * ntp + 1], qh[ks], kl1, kl3);
                MMA_BF16(S[2 * ntp + 1], ql[ks], kh1, kh3);
            }
        }

        if (kb == qb) {
#pragma unroll
            for (int nt = 0; nt < 8; nt++) {
                const int key = kb + (nt << 3) + ((lane & 3) << 1);
                if (key > row0)     S[nt][0] = -1e30f;
                if (key + 1 > row0) S[nt][1] = -1e30f;
                if (key > row1)     S[nt][2] = -1e30f;
                if (key + 1 > row1) S[nt][3] = -1e30f;
            }
        }

        float mx0 = -1e30f, mx1 = -1e30f;
#pragma unroll
        for (int nt = 0; nt < 8; nt++) {
            mx0 = fmaxf(mx0, fmaxf(S[nt][0], S[nt][1]));
            mx1 = fmaxf(mx1, fmaxf(S[nt][2], S[nt][3]));
        }
        mx0 = fmaxf(mx0, __shfl_xor_sync(0xffffffffu, mx0, 1));
        mx0 = fmaxf(mx0, __shfl_xor_sync(0xffffffffu, mx0, 2));
        mx1 = fmaxf(mx1, __shfl_xor_sync(0xffffffffu, mx1, 1));
        mx1 = fmaxf(mx1, __shfl_xor_sync(0xffffffffu, mx1, 2));

        const float m0n = fmaxf(m0, mx0), m1n = fmaxf(m1, mx1);
        const float a0 = __expf(m0 - m0n), a1 = __expf(m1 - m1n);
        m0 = m0n; m1 = m1n;

        uint32_t aH[4][4], aL[4][4];
        float ps0 = 0.f, ps1 = 0.f;
#pragma unroll
        for (int nt = 0; nt < 8; nt++) {
            const float p0 = __expf(S[nt][0] - m0n);
            const float p1 = __expf(S[nt][1] - m0n);
            const float p2 = __expf(S[nt][2] - m1n);
            const float p3 = __expf(S[nt][3] - m1n);
            ps0 += p0 + p1; ps1 += p2 + p3;
            const float h0 = __bfloat162float(__float2bfloat16_rn(p0));
            const float h1 = __bfloat162float(__float2bfloat16_rn(p1));
            const float h2 = __bfloat162float(__float2bfloat16_rn(p2));
            const float h3 = __bfloat162float(__float2bfloat16_rn(p3));
            const int kk = nt >> 1;
            const int e  = (nt & 1) << 1;
            aH[kk][e]     = bf2pack(p0, p1);
            aH[kk][e + 1] = bf2pack(p2, p3);
            aL[kk][e]     = bf2pack(p0 - h0, p1 - h1);
            aL[kk][e + 1] = bf2pack(p2 - h2, p3 - h3);
        }
        ps0 += __shfl_xor_sync(0xffffffffu, ps0, 1);
        ps0 += __shfl_xor_sync(0xffffffffu, ps0, 2);
        ps1 += __shfl_xor_sync(0xffffffffu, ps1, 1);
        ps1 += __shfl_xor_sync(0xffffffffu, ps1, 2);
        l0 = l0 * a0 + ps0;
        l1 = l1 * a1 + ps1;

#pragma unroll
        for (int nt = 0; nt < 16; nt++) {
            O[nt][0] *= a0; O[nt][1] *= a0;
            O[nt][2] *= a1; O[nt][3] *= a1;
        }

        CPA_WAIT0();
        __syncthreads();

#pragma unroll
        for (int kk = 0; kk < 4; kk++) {
#pragma unroll
            for (int ntp = 0; ntp < 8; ntp++) {
                const uint32_t ad = offV((kk << 4) + (lane & 15),
                                         (ntp << 1) + (lane >> 4));
                uint32_t vh0, vh1, vh2, vh3, vl0, vl1, vl2, vl3;
                LDSM4T(vh0, vh1, vh2, vh3, sb + SM_VH + ad);
                LDSM4T(vl0, vl1, vl2, vl3, sb + SM_VL + ad);
                MMA_BF16(O[2 * ntp],     aH[kk], vh0, vh1);
                MMA_BF16(O[2 * ntp],     aH[kk], vl0, vl1);
                MMA_BF16(O[2 * ntp],     aL[kk], vh0, vh1);
                MMA_BF16(O[2 * ntp + 1], aH[kk], vh2, vh3);
                MMA_BF16(O[2 * ntp + 1], aH[kk], vl2, vl3);
                MMA_BF16(O[2 * ntp + 1], aL[kk], vh2, vh3);
            }
        }
        __syncthreads();
    }

    /* ---- epilogue: normalize, write fp16 hi/lo [t][h*128+d] ---- */
    const float inv0 = 1.0f / l0, inv1 = 1.0f / l1;
#pragma unroll
    for (int nt = 0; nt < 16; nt++) {
        const int d = (nt << 3) + ((lane & 3) << 1);
        const float v0 = O[nt][0] * inv0, v1 = O[nt][1] * inv0;
        const float v2 = O[nt][2] * inv1, v3 = O[nt][3] * inv1;
        const float h0 = __half2float(__float2half_rn(v0));
        const float h1 = __half2float(__float2half_rn(v1));
        const float h2 = __half2float(__float2half_rn(v2));
        const float h3 = __half2float(__float2half_rn(v3));
        const size_t i0 = (size_t)row0 * DMODEL + h * DHEAD + d;
        const size_t i1 = (size_t)row1 * DMODEL + h * DHEAD + d;
        *(uint32_t*)(g_Oh + i0) = hf2pack(v0, v1);
        *(uint32_t*)(g_Ol + i0) = hf2pack(v0 - h0, v1 - h1);
        *(uint32_t*)(g_Oh + i1) = hf2pack(v2, v3);
        *(uint32_t*)(g_Ol + i1) = hf2pack(v2 - h2, v3 - h3);
    }
}

/* ------------------------------------------------------------------ */
extern "C" void kernel_launch(void* const* d_in, const int* in_sizes, int n_in,
                              void* d_out, int out_size)
{
    const float* x        = (const float*)d_in[0];
    const float* Wq_down  = (const float*)d_in[1];
    const float* Wq_up    = (const float*)d_in[2];
    const float* Wq_rope  = (const float*)d_in[3];
    const float* Wkv_down = (const float*)d_in[4];
    const float* Wk_up    = (const float*)d_in[5];
    const float* Wv_up    = (const float*)d_in[6];
    const float* Wk_rope  = (const float*)d_in[7];
    const float* Wo       = (const float*)d_in[8];
    float* out = (float*)d_out;

    float *qc, *qr, *kc, *kr;
    cudaGetSymbolAddress((void**)&qc, g_qc);
    cudaGetSymbolAddress((void**)&qr, g_qr);
    cudaGetSymbolAddress((void**)&kc, g_kc);
    cudaGetSymbolAddress((void**)&kr, g_kr);

    __half *xh, *xl, *qdh, *qdl, *kvh, *kvl, *Oh, *Ol;
    __half *wqd, *wqu, *wqr, *wkd, *wku, *wvu, *wkr, *wo;
    __nv_bfloat16 *Vh, *Vl;
    cudaGetSymbolAddress((void**)&xh, g_xh);   cudaGetSymbolAddress((void**)&xl, g_xl);
    cudaGetSymbolAddress((void**)&qdh, g_qdh); cudaGetSymbolAddress((void**)&qdl, g_qdl);
    cudaGetSymbolAddress((void**)&kvh, g_kvh); cudaGetSymbolAddress((void**)&kvl, g_kvl);
    cudaGetSymbolAddress((void**)&Oh, g_Oh);   cudaGetSymbolAddress((void**)&Ol, g_Ol);
    cudaGetSymbolAddress((void**)&Vh, g_Vh);   cudaGetSymbolAddress((void**)&Vl, g_Vl);
    cudaGetSymbolAddress((void**)&wqd, g_wqd); cudaGetSymbolAddress((void**)&wqu, g_wqu);
    cudaGetSymbolAddress((void**)&wqr, g_wqr); cudaGetSymbolAddress((void**)&wkd, g_wkd);
    cudaGetSymbolAddress((void**)&wku, g_wku); cudaGetSymbolAddress((void**)&wvu, g_wvu);
    cudaGetSymbolAddress((void**)&wkr, g_wkr); cudaGetSymbolAddress((void**)&wo,  g_wo);

    cudaFuncSetAttribute(gemm_fused,
                         cudaFuncAttributeMaxDynamicSharedMemorySize, 49152);
    cudaFuncSetAttribute(attn_mma,
                         cudaFuncAttributeMaxDynamicSharedMemorySize, 65536);

    /* 0. rope table */
    rope_table<<<256, 256>>>();

    /* 1. split: x hi/lo; weights hi only */
    SplitJobs js;
    js.j[0] = { x,        xh,  xl,      TSEQ * 2048 };
    js.j[1] = { Wq_down,  wqd, nullptr, 2048 * 512  };
    js.j[2] = { Wq_up,    wqu, nullptr, 512 * 1024  };
    js.j[3] = { Wq_rope,  wqr, nullptr, 2048 * 1024 };
    js.j[4] = { Wkv_down, wkd, nullptr, 2048 * 512  };
    js.j[5] = { Wk_up,    wku, nullptr, 512 * 1024  };
    js.j[6] = { Wv_up,    wvu, nullptr, 512 * 2048  };
    js.j[7] = { Wk_rope,  wkr, nullptr, 2048 * 1024 };
    js.j[8] = { Wo,       wo,  nullptr, 2048 * 2048 };
    split_many<<<dim3(4096, 9), 256>>>(js);

    /* 2. GEMM1: x @ [Wq_down | Wkv_down | Wq_rope | Wk_rope] */
    {
        GSegs g; g.n = 4;
        g.s[0] = { xh, xl, 2048, wqd, nullptr, qdh, qdl,  512, 2048, 0,  0 };
        g.s[1] = { xh, xl, 2048, wkd, nullptr, kvh, kvl,  512, 2048, 4,  0 };
        g.s[2] = { xh, xl, 2048, wqr, qr, nullptr, nullptr, 1024, 2048, 8,  0 };
        g.s[3] = { xh, xl, 2048, wkr, kr, nullptr, nullptr, 1024, 2048, 16, 0 };
        gemm_fused<<<dim3(24, 16), 256, 49152>>>(g);
    }

    /* 3. GEMM2: qd @ Wq_up ; kv @ [Wk_up | Wv_up (-> Vh/Vl bf16 perm)] */
    {
        GSegs g; g.n = 3;
        g.s[0] = { qdh, qdl, 512, wqu, qc, nullptr, nullptr, 1024, 512, 0,  0 };
        g.s[1] = { kvh, kvl, 512, wku, kc, nullptr, nullptr, 1024, 512, 8,  0 };
        g.s[2] = { kvh, kvl, 512, wvu, nullptr, Vh, Vl,      2048, 512, 16, 1 };
        g.s[3] = g.s[0];
        gemm_fused<<<dim3(32, 16), 256, 49152>>>(g);
    }

    /* 4. rope + pack Q/K (bf16 for attention) */
    pack_kernel<<<dim3(TSEQ, NH), 64>>>();

    /* 5. tensor-core causal attention (bf16 3-MMA, fp16 O out) */
    attn_mma<<<dim3(32, NH), 128, 65536>>>();

    /* 6. GEMM3: O @ Wo -> out */
    {
        GSegs g; g.n = 1;
        g.s[0] = { Oh, Ol, 2048, wo, out, nullptr, nullptr, 2048, 2048, 0, 0 };
        g.s[1] = g.s[0]; g.s[2] = g.s[0]; g.s[3] = g.s[0];
        gemm_fused<<<dim3(16, 16), 256, 49152>>>(g);
    }
}

// round 12
// speedup vs baseline: 1.3828x; 1.1190x over previous
#include <cuda_runtime.h>
#include <cuda_bf16.h>
#include <cuda_fp16.h>
#include <math.h>
#include <stdint.h>

#define TSEQ   2048
#define DMODEL 2048
#define NH     16
#define DHEAD  128
#define DROPE  64
#define DCONT  64
#define SCALE_ATT 0.08838834764831845f  /* 1/sqrt(128) */

/* ------------------------------------------------------------------ */
/* Scratch (device globals)                                            */
/* ------------------------------------------------------------------ */
__device__ float g_qc[TSEQ * 1024];
__device__ float g_qr[TSEQ * 1024];
__device__ float g_kc[TSEQ * 1024];
__device__ float g_kr[TSEQ * 1024];
__device__ float g_cosT[TSEQ * 32];
__device__ float g_sinT[TSEQ * 32];

/* attention operands (fp16), [h][t][d]: Q split hi/lo, K/V single */
__device__ __half g_Qh[NH * TSEQ * DHEAD], g_Ql[NH * TSEQ * DHEAD];
__device__ __half g_K [NH * TSEQ * DHEAD];
__device__ __half g_V [NH * TSEQ * DHEAD];

/* fp16 GEMM operands: activations hi/lo, weights hi only              */
__device__ __half g_xh[TSEQ * 2048],  g_xl[TSEQ * 2048];
__device__ __half g_qdh[TSEQ * 512],  g_qdl[TSEQ * 512];
__device__ __half g_kvh[TSEQ * 512],  g_kvl[TSEQ * 512];
__device__ __half g_Oh[TSEQ * 2048],  g_Ol[TSEQ * 2048];
__device__ __half g_wqd[2048 * 512];
__device__ __half g_wqu[512 * 1024];
__device__ __half g_wqr[2048 * 1024];
__device__ __half g_wkd[2048 * 512];
__device__ __half g_wku[512 * 1024];
__device__ __half g_wvu[512 * 2048];
__device__ __half g_wkr[2048 * 1024];
__device__ __half g_wo [2048 * 2048];

/* ------------------------------------------------------------------ */
/* asm helpers                                                         */
/* ------------------------------------------------------------------ */
#define CPA16(dst, src)                                                    \
    asm volatile("cp.async.cg.shared.global [%0], [%1], 16;"               \
                 :: "r"(dst), "l"(src))
#define CPA_COMMIT() asm volatile("cp.async.commit_group;")
#define CPA_WAIT1()  asm volatile("cp.async.wait_group 1;")
#define CPA_WAIT0()  asm volatile("cp.async.wait_group 0;")

#define LDSM4(r0, r1, r2, r3, addr)                                        \
    asm volatile("ldmatrix.sync.aligned.m8n8.x4.shared.b16 {%0,%1,%2,%3}, [%4];" \
                 : "=r"(r0), "=r"(r1), "=r"(r2), "=r"(r3) : "r"(addr))
#define LDSM4T(r0, r1, r2, r3, addr)                                       \
    asm volatile("ldmatrix.sync.aligned.m8n8.x4.trans.shared.b16 {%0,%1,%2,%3}, [%4];" \
                 : "=r"(r0), "=r"(r1), "=r"(r2), "=r"(r3) : "r"(addr))
#define MMA_F16(c, a, b0, b1)                                              \
    asm volatile("mma.sync.aligned.m16n8k16.row.col.f32.f16.f16.f32 "      \
                 "{%0,%1,%2,%3}, {%4,%5,%6,%7}, {%8,%9}, {%0,%1,%2,%3};"   \
                 : "+f"(c[0]), "+f"(c[1]), "+f"(c[2]), "+f"(c[3])          \
                 : "r"(a[0]), "r"(a[1]), "r"(a[2]), "r"(a[3]),             \
                   "r"(b0), "r"(b1))

__device__ __forceinline__ uint32_t hf2pack(float a, float b)
{
    return (uint32_t)__half_as_ushort(__float2half_rn(a)) |
           ((uint32_t)__half_as_ushort(__float2half_rn(b)) << 16);
}

/* ------------------------------------------------------------------ */
/* RoPE table                                                          */
/* ------------------------------------------------------------------ */
__global__ void __launch_bounds__(256) rope_table()
{
    const int idx = blockIdx.x * 256 + threadIdx.x;
    if (idx >= TSEQ * 32) return;
    const int t = idx >> 5, i = idx & 31;
    const double inv = pow(10000.0, -(double)i / 32.0);
    double sd, cd;
    sincos((double)t * inv, &sd, &cd);
    g_cosT[idx] = (float)cd;
    g_sinT[idx] = (float)sd;
}

/* ------------------------------------------------------------------ */
/* Batched fp32 -> fp16 split; l==null -> hi only                      */
/* ------------------------------------------------------------------ */
struct SplitJob { const float* src; __half *h, *l; int n; };
struct SplitJobs { SplitJob j[9]; };

__global__ void __launch_bounds__(256) split_many(SplitJobs js)
{
    const SplitJob J = js.j[blockIdx.y];
    const int i = (blockIdx.x * 256 + threadIdx.x) << 2;
    if (i >= J.n) return;
    float4 v = *(const float4*)(J.src + i);
    uint2 hp;
    hp.x = hf2pack(v.x, v.y);  hp.y = hf2pack(v.z, v.w);
    *(uint2*)(J.h + i) = hp;
    if (J.l) {
        const float h0 = __half2float(__float2half_rn(v.x));
        const float h1 = __half2float(__float2half_rn(v.y));
        const float h2 = __half2float(__float2half_rn(v.z));
        const float h3 = __half2float(__float2half_rn(v.w));
        uint2 lp;
        lp.x = hf2pack(v.x - h0, v.y - h1);
        lp.y = hf2pack(v.z - h2, v.w - h3);
        *(uint2*)(J.l + i) = lp;
    }
}

/* ------------------------------------------------------------------ */
/* Fused multi-segment fp16 tensor-core GEMM (unchanged from R11).     */
/* ------------------------------------------------------------------ */
struct GSeg {
    const __half *Ah, *Al;
    int lda;
    const __half *Bh;
    float* Cf;
    void *Ch, *Cl;             /* fp16 split out; vperm=1 -> single fp16 V perm */
    int N, K, tile0, vperm;
};
struct GSegs { GSeg s[4]; int n; };

#define STAGE_BYTES 24576
#define A_LO_OFF    8192
#define B_HI_OFF    16384

__device__ __forceinline__ uint32_t offA(int r, int c)
{ return (uint32_t)(((r << 2) + (c ^ ((r >> 1) & 3))) << 4); }
__device__ __forceinline__ uint32_t offB(int r, int c)
{ return (uint32_t)(((r << 4) + (c ^ (r & 7))) << 4); }

__global__ void __launch_bounds__(256, 2) gemm_fused(GSegs segs)
{
    extern __shared__ char dsm[];
    const uint32_t sb = (uint32_t)__cvta_generic_to_shared(dsm);

    const int tid  = threadIdx.x;
    const int lane = tid & 31;
    const int warp = tid >> 5;
    const int wm   = (warp >> 1) << 5;
    const int wn   = (warp & 1) << 6;
    const int bm   = blockIdx.y << 7;

    GSeg sg = segs.s[0];
#pragma unroll
    for (int i = 1; i < 4; i++)
        if (i < segs.n && (int)blockIdx.x >= segs.s[i].tile0) sg = segs.s[i];
    const int bn  = ((int)blockIdx.x - sg.tile0) << 7;
    const int lda = sg.lda, ldb = sg.N, K = sg.K;

    const int ar = tid >> 2, ac = tid & 3;
    const int br = tid >> 3, bc = tid & 7;
    const uint32_t aoff0 = offA(ar, ac), aoff1 = offA(ar + 64, ac);
    const uint32_t boff0 = offB(br, bc), boff1 = offB(br, bc + 8);

    const __half* gAh = sg.Ah + (size_t)(bm + ar) * lda + ac * 8;
    const __half* gAl = sg.Al + (size_t)(bm + ar) * lda + ac * 8;
    const __half* gBh = sg.Bh + (size_t)br * ldb + bn + bc * 8;

    float acc[2][8][4];
#pragma unroll
    for (int mt = 0; mt < 2; mt++)
#pragma unroll
        for (int nt = 0; nt < 8; nt++)
#pragma unroll
            for (int i = 0; i < 4; i++) acc[mt][nt][i] = 0.f;

    const int nk = K >> 5;

    auto load_stage = [&](int st, int k0) {
        const uint32_t s0 = sb + st * STAGE_BYTES;
        const __half* pAh = gAh + k0;
        const __half* pAl = gAl + k0;
        CPA16(s0 + aoff0, pAh);
        CPA16(s0 + aoff1, pAh + (size_t)64 * lda);
        CPA16(s0 + A_LO_OFF + aoff0, pAl);
        CPA16(s0 + A_LO_OFF + aoff1, pAl + (size_t)64 * lda);
        const __half* pBh = gBh + (size_t)k0 * ldb;
        CPA16(s0 + B_HI_OFF + boff0, pBh);
        CPA16(s0 + B_HI_OFF + boff1, pBh + 64);
    };

    load_stage(0, 0);
    CPA_COMMIT();

    for (int it = 0; it < nk; it++) {
        if (it + 1 < nk) { load_stage((it + 1) & 1, (it + 1) << 5); CPA_COMMIT(); }
        if (it + 1 < nk) CPA_WAIT1(); else CPA_WAIT0();
        __syncthreads();

        const uint32_t s0 = sb + (it & 1) * STAGE_BYTES;
#pragma unroll
        for (int ks = 0; ks < 2; ks++) {
            uint32_t ah[2][4], al_[2][4];
#pragma unroll
            for (int mt = 0; mt < 2; mt++) {
                const int rowA   = wm + (mt << 4) + (lane & 15);
                const int chunkA = (ks << 1) + (lane >> 4);
                const uint32_t ad = s0 + offA(rowA, chunkA);
                LDSM4(ah[mt][0], ah[mt][1], ah[mt][2], ah[mt][3], ad);
                LDSM4(al_[mt][0], al_[mt][1], al_[mt][2], al_[mt][3], ad + A_LO_OFF);
            }
#pragma unroll
            for (int np = 0; np < 4; np++) {
                const int rowB   = (ks << 4) + (lane & 15);
                const int chunkB = (wn >> 3) + (lane >> 4) + (np << 1);
                const uint32_t bd = s0 + B_HI_OFF + offB(rowB, chunkB);
                uint32_t h0, h1, h2, h3;
                LDSM4T(h0, h1, h2, h3, bd);
#pragma unroll
                for (int mt = 0; mt < 2; mt++) {
                    MMA_F16(acc[mt][2 * np],     ah[mt],  h0, h1);
                    MMA_F16(acc[mt][2 * np],     al_[mt], h0, h1);
                    MMA_F16(acc[mt][2 * np + 1], ah[mt],  h2, h3);
                    MMA_F16(acc[mt][2 * np + 1], al_[mt], h2, h3);
                }
            }
        }
        __syncthreads();
    }

    const int erow = lane >> 2;
    const int ecol = (lane & 3) << 1;
    if (sg.Cf) {
#pragma unroll
        for (int mt = 0; mt < 2; mt++)
#pragma unroll
            for (int nt = 0; nt < 8; nt++) {
                const int r = bm + wm + (mt << 4) + erow;
                const int c = bn + wn + (nt << 3) + ecol;
                *(float2*)(sg.Cf + (size_t)r * ldb + c) =
                    make_float2(acc[mt][nt][0], acc[mt][nt][1]);
                *(float2*)(sg.Cf + (size_t)(r + 8) * ldb + c) =
                    make_float2(acc[mt][nt][2], acc[mt][nt][3]);
            }
    } else if (sg.vperm) {
        /* single fp16 out, remapped [t][h*128+d] -> [h][t][d] (V) */
        __half* Ch = (__half*)sg.Ch;
#pragma unroll
        for (int mt = 0; mt < 2; mt++)
#pragma unroll
            for (int nt = 0; nt < 8; nt++) {
                const int r = bm + wm + (mt << 4) + erow;
                const int c = bn + wn + (nt << 3) + ecol;
#pragma unroll
                for (int hh = 0; hh < 2; hh++) {
                    const float v0 = acc[mt][nt][2 * hh];
                    const float v1 = acc[mt][nt][2 * hh + 1];
                    const int rr = r + 8 * hh;
                    const size_t idx =
                        ((size_t)(c >> 7) * TSEQ + rr) * DHEAD + (c & 127);
                    *(uint32_t*)(Ch + idx) = hf2pack(v0, v1);
                }
            }
    } else {
        __half* Ch = (__half*)sg.Ch;
        __half* Cl = (__half*)sg.Cl;
#pragma unroll
        for (int mt = 0; mt < 2; mt++)
#pragma unroll
            for (int nt = 0; nt < 8; nt++) {
                const int r = bm + wm + (mt << 4) + erow;
                const int c = bn + wn + (nt << 3) + ecol;
#pragma unroll
                for (int hh = 0; hh < 2; hh++) {
                    const float v0 = acc[mt][nt][2 * hh];
                    const float v1 = acc[mt][nt][2 * hh + 1];
                    const float h0 = __half2float(__float2half_rn(v0));
                    const float h1 = __half2float(__float2half_rn(v1));
                    const size_t idx = (size_t)(r + 8 * hh) * ldb + c;
                    *(uint32_t*)(Ch + idx) = hf2pack(v0, v1);
                    *(uint32_t*)(Cl + idx) = hf2pack(v0 - h0, v1 - h1);
                }
            }
    }
}

/* ------------------------------------------------------------------ */
/* Pack + RoPE -> Qh/Ql fp16 split (pre-scaled), K single fp16.        */
/* ------------------------------------------------------------------ */
__global__ void __launch_bounds__(64) pack_kernel()
{
    const int t = blockIdx.x;
    const int h = blockIdx.y;
    const int d2 = threadIdx.x << 1;
    const size_t o = ((size_t)h * TSEQ + t) * DHEAD + d2;

    float q0, q1, k0, k1;
    if (d2 < DCONT) {
        const size_t b = (size_t)t * 1024 + h * DCONT + d2;
        q0 = g_qc[b];     q1 = g_qc[b + 1];
        k0 = g_kc[b];     k1 = g_kc[b + 1];
    } else {
        const int i = d2 - DCONT;
        const int ip = (i < 32) ? i : i - 32;
        const float c0 = g_cosT[t * 32 + ip],     s0 = g_sinT[t * 32 + ip];
        const float c1 = g_cosT[t * 32 + ip + 1], s1 = g_sinT[t * 32 + ip + 1];
        const size_t b = (size_t)t * 1024 + h * DROPE;
        const float qa0 = g_qr[b + ip],      qa1 = g_qr[b + ip + 1];
        const float qb0 = g_qr[b + 32 + ip], qb1 = g_qr[b + 32 + ip + 1];
        const float ka0 = g_kr[b + ip],      ka1 = g_kr[b + ip + 1];
        const float kb0 = g_kr[b + 32 + ip], kb1 = g_kr[b + 32 + ip + 1];
        if (i < 32) {
            q0 = qa0 * c0 - qb0 * s0;  q1 = qa1 * c1 - qb1 * s1;
            k0 = ka0 * c0 - kb0 * s0;  k1 = ka1 * c1 - kb1 * s1;
        } else {
            q0 = qa0 * s0 + qb0 * c0;  q1 = qa1 * s1 + qb1 * c1;
            k0 = ka0 * s0 + kb0 * c0;  k1 = ka1 * s1 + kb1 * c1;
        }
    }
    q0 *= SCALE_ATT; q1 *= SCALE_ATT;

    const float qh0 = __half2float(__float2half_rn(q0));
    const float qh1 = __half2float(__float2half_rn(q1));
    *(uint32_t*)(g_Qh + o) = hf2pack(q0, q1);
    *(uint32_t*)(g_Ql + o) = hf2pack(q0 - qh0, q1 - qh1);
    *(uint32_t*)(g_K  + o) = hf2pack(k0, k1);
}

/* ------------------------------------------------------------------ */
/* fp16 tensor-core causal flash attention.                            */
/* Q/P split hi/lo; K/V single fp16. Double-buffered K/V tiles.        */
/* smem: [K0 | V0 | K1 | V1] 4x16KB = 64KB.                            */
/* ------------------------------------------------------------------ */
__device__ __forceinline__ uint32_t offV(int r, int c)
{ return (uint32_t)(((r << 4) + (c ^ (r & 7))) << 4); }   /* 16 chunks/row */

__global__ void __launch_bounds__(128) attn_mma()
{
    extern __shared__ char dsm[];
    const uint32_t sb = (uint32_t)__cvta_generic_to_shared(dsm);

    const int h    = blockIdx.y;
    const int qblk = 31 - (int)blockIdx.x;       /* long CTAs first */
    const int qb   = qblk << 6;
    const int tid  = threadIdx.x;
    const int lane = tid & 31;
    const int warp = tid >> 5;
    const int w16  = warp << 4;

    const __half* Qhb = g_Qh + (size_t)h * TSEQ * DHEAD;
    const __half* Qlb = g_Ql + (size_t)h * TSEQ * DHEAD;
    const __half* Kb  = g_K  + (size_t)h * TSEQ * DHEAD;
    const __half* Vb  = g_V  + (size_t)h * TSEQ * DHEAD;

    const int sr = tid >> 4;            /* 0..7  */
    const int sc = tid & 15;            /* 0..15 */

    /* ---- stage Q (64 rows) into buf0 (Qh->K0, Ql->V0), LDSM ---- */
#pragma unroll
    for (int p = 0; p < 8; p++) {
        const int r = sr + (p << 3);
        CPA16(sb + offV(r, sc),         Qhb + (size_t)(qb + r) * DHEAD + sc * 8);
        CPA16(sb + 16384 + offV(r, sc), Qlb + (size_t)(qb + r) * DHEAD + sc * 8);
    }
    CPA_COMMIT(); CPA_WAIT0();
    __syncthreads();

    uint32_t qh[8][4], ql[8][4];
#pragma unroll
    for (int ks = 0; ks < 8; ks++) {
        const uint32_t ad = offV(w16 + (lane & 15), (ks << 1) + (lane >> 4));
        LDSM4(qh[ks][0], qh[ks][1], qh[ks][2], qh[ks][3], sb + ad);
        LDSM4(ql[ks][0], ql[ks][1], ql[ks][2], ql[ks][3], sb + 16384 + ad);
    }
    __syncthreads();

    float O[16][4];
#pragma unroll
    for (int nt = 0; nt < 16; nt++)
#pragma unroll
        for (int i = 0; i < 4; i++) O[nt][i] = 0.f;
    float m0 = -1e30f, m1 = -1e30f, l0 = 0.f, l1 = 0.f;

    const int ntiles = qblk + 1;
    const int row0 = qb + w16 + (lane >> 2);
    const int row1 = row0 + 8;

    /* load K/V tile into buffer b (K at b*32768, V at b*32768+16384) */
    auto load_kv = [&](int b, int kt) {
        const int kb = kt << 6;
        const uint32_t s0 = sb + b * 32768;
#pragma unroll
        for (int p = 0; p < 8; p++) {
            const int r = sr + (p << 3);
            const size_t gi = (size_t)(kb + r) * DHEAD + sc * 8;
            const uint32_t so = offV(r, sc);
            CPA16(s0 + so,         Kb + gi);
            CPA16(s0 + 16384 + so, Vb + gi);
        }
    };

    load_kv(0, 0); CPA_COMMIT();

    for (int kt = 0; kt < ntiles; kt++) {
        const int kb = kt << 6;
        if (kt + 1 < ntiles) { load_kv((kt + 1) & 1, kt + 1); CPA_COMMIT(); }
        if (kt + 1 < ntiles) CPA_WAIT1(); else CPA_WAIT0();
        __syncthreads();

        const uint32_t kbase = sb + (kt & 1) * 32768;
        const uint32_t vbase = kbase + 16384;

        /* ---- scores S = Q K^T ---- */
        float S[8][4];
#pragma unroll
        for (int nt = 0; nt < 8; nt++)
#pragma unroll
            for (int i = 0; i < 4; i++) S[nt][i] = 0.f;

#pragma unroll
        for (int ntp = 0; ntp < 4; ntp++) {
#pragma unroll
            for (int ks = 0; ks < 8; ks++) {
                const uint32_t ad = offV((ntp << 4) + (lane & 15),
                                         (ks << 1) + (lane >> 4));
                uint32_t k0, k1, k2, k3;
                LDSM4(k0, k1, k2, k3, kbase + ad);
                MMA_F16(S[2 * ntp],     qh[ks], k0, k2);
                MMA_F16(S[2 * ntp],     ql[ks], k0, k2);
                MMA_F16(S[2 * ntp + 1], qh[ks], k1, k3);
                MMA_F16(S[2 * ntp + 1], ql[ks], k1, k3);
            }
        }

        /* ---- causal mask on diagonal tile ---- */
        if (kb == qb) {
#pragma unroll
            for (int nt = 0; nt < 8; nt++) {
                const int key = kb + (nt << 3) + ((lane & 3) << 1);
                if (key > row0)     S[nt][0] = -1e30f;
                if (key + 1 > row0) S[nt][1] = -1e30f;
                if (key > row1)     S[nt][2] = -1e30f;
                if (key + 1 > row1) S[nt][3] = -1e30f;
            }
        }

        /* ---- online softmax ---- */
        float mx0 = -1e30f, mx1 = -1e30f;
#pragma unroll
        for (int nt = 0; nt < 8; nt++) {
            mx0 = fmaxf(mx0, fmaxf(S[nt][0], S[nt][1]));
            mx1 = fmaxf(mx1, fmaxf(S[nt][2], S[nt][3]));
        }
        mx0 = fmaxf(mx0, __shfl_xor_sync(0xffffffffu, mx0, 1));
        mx0 = fmaxf(mx0, __shfl_xor_sync(0xffffffffu, mx0, 2));
        mx1 = fmaxf(mx1, __shfl_xor_sync(0xffffffffu, mx1, 1));
        mx1 = fmaxf(mx1, __shfl_xor_sync(0xffffffffu, mx1, 2));

        const float m0n = fmaxf(m0, mx0), m1n = fmaxf(m1, mx1);
        const float a0 = __expf(m0 - m0n), a1 = __expf(m1 - m1n);
        m0 = m0n; m1 = m1n;

        uint32_t aH[4][4], aL[4][4];
        float ps0 = 0.f, ps1 = 0.f;
#pragma unroll
        for (int nt = 0; nt < 8; nt++) {
            const float p0 = __expf(S[nt][0] - m0n);
            const float p1 = __expf(S[nt][1] - m0n);
            const float p2 = __expf(S[nt][2] - m1n);
            const float p3 = __expf(S[nt][3] - m1n);
            ps0 += p0 + p1; ps1 += p2 + p3;
            const float h0 = __half2float(__float2half_rn(p0));
            const float h1 = __half2float(__float2half_rn(p1));
            const float h2 = __half2float(__float2half_rn(p2));
            const float h3 = __half2float(__float2half_rn(p3));
            const int kk = nt >> 1;
            const int e  = (nt & 1) << 1;
            aH[kk][e]     = hf2pack(p0, p1);
            aH[kk][e + 1] = hf2pack(p2, p3);
            aL[kk][e]     = hf2pack(p0 - h0, p1 - h1);
            aL[kk][e + 1] = hf2pack(p2 - h2, p3 - h3);
        }
        ps0 += __shfl_xor_sync(0xffffffffu, ps0, 1);
        ps0 += __shfl_xor_sync(0xffffffffu, ps0, 2);
        ps1 += __shfl_xor_sync(0xffffffffu, ps1, 1);
        ps1 += __shfl_xor_sync(0xffffffffu, ps1, 2);
        l0 = l0 * a0 + ps0;
        l1 = l1 * a1 + ps1;

#pragma unroll
        for (int nt = 0; nt < 16; nt++) {
            O[nt][0] *= a0; O[nt][1] *= a0;
            O[nt][2] *= a1; O[nt][3] *= a1;
        }

        /* ---- O += P V ---- */
#pragma unroll
        for (int kk = 0; kk < 4; kk++) {
#pragma unroll
            for (int ntp = 0; ntp < 8; ntp++) {
                const uint32_t ad = offV((kk << 4) + (lane & 15),
                                         (ntp << 1) + (lane >> 4));
                uint32_t v0, v1, v2, v3;
                LDSM4T(v0, v1, v2, v3, vbase + ad);
                MMA_F16(O[2 * ntp],     aH[kk], v0, v1);
                MMA_F16(O[2 * ntp],     aL[kk], v0, v1);
                MMA_F16(O[2 * ntp + 1], aH[kk], v2, v3);
                MMA_F16(O[2 * ntp + 1], aL[kk], v2, v3);
            }
        }
        __syncthreads();   /* guard buffer reuse by next-next load */
    }

    /* ---- epilogue: normalize, write fp16 hi/lo [t][h*128+d] ---- */
    const float inv0 = 1.0f / l0, inv1 = 1.0f / l1;
#pragma unroll
    for (int nt = 0; nt < 16; nt++) {
        const int d = (nt << 3) + ((lane & 3) << 1);
        const float v0 = O[nt][0] * inv0, v1 = O[nt][1] * inv0;
        const float v2 = O[nt][2] * inv1, v3 = O[nt][3] * inv1;
        const float h0 = __half2float(__float2half_rn(v0));
        const float h1 = __half2float(__float2half_rn(v1));
        const float h2 = __half2float(__float2half_rn(v2));
        const float h3 = __half2float(__float2half_rn(v3));
        const size_t i0 = (size_t)row0 * DMODEL + h * DHEAD + d;
        const size_t i1 = (size_t)row1 * DMODEL + h * DHEAD + d;
        *(uint32_t*)(g_Oh + i0) = hf2pack(v0, v1);
        *(uint32_t*)(g_Ol + i0) = hf2pack(v0 - h0, v1 - h1);
        *(uint32_t*)(g_Oh + i1) = hf2pack(v2, v3);
        *(uint32_t*)(g_Ol + i1) = hf2pack(v2 - h2, v3 - h3);
    }
}

/* ------------------------------------------------------------------ */
extern "C" void kernel_launch(void* const* d_in, const int* in_sizes, int n_in,
                              void* d_out, int out_size)
{
    const float* x        = (const float*)d_in[0];
    const float* Wq_down  = (const float*)d_in[1];
    const float* Wq_up    = (const float*)d_in[2];
    const float* Wq_rope  = (const float*)d_in[3];
    const float* Wkv_down = (const float*)d_in[4];
    const float* Wk_up    = (const float*)d_in[5];
    const float* Wv_up    = (const float*)d_in[6];
    const float* Wk_rope  = (const float*)d_in[7];
    const float* Wo       = (const float*)d_in[8];
    float* out = (float*)d_out;

    float *qc, *qr, *kc, *kr;
    cudaGetSymbolAddress((void**)&qc, g_qc);
    cudaGetSymbolAddress((void**)&qr, g_qr);
    cudaGetSymbolAddress((void**)&kc, g_kc);
    cudaGetSymbolAddress((void**)&kr, g_kr);

    __half *xh, *xl, *qdh, *qdl, *kvh, *kvl, *Oh, *Ol, *Vf;
    __half *wqd, *wqu, *wqr, *wkd, *wku, *wvu, *wkr, *wo;
    cudaGetSymbolAddress((void**)&xh, g_xh);   cudaGetSymbolAddress((void**)&xl, g_xl);
    cudaGetSymbolAddress((void**)&qdh, g_qdh); cudaGetSymbolAddress((void**)&qdl, g_qdl);
    cudaGetSymbolAddress((void**)&kvh, g_kvh); cudaGetSymbolAddress((void**)&kvl, g_kvl);
    cudaGetSymbolAddress((void**)&Oh, g_Oh);   cudaGetSymbolAddress((void**)&Ol, g_Ol);
    cudaGetSymbolAddress((void**)&Vf, g_V);
    cudaGetSymbolAddress((void**)&wqd, g_wqd); cudaGetSymbolAddress((void**)&wqu, g_wqu);
    cudaGetSymbolAddress((void**)&wqr, g_wqr); cudaGetSymbolAddress((void**)&wkd, g_wkd);
    cudaGetSymbolAddress((void**)&wku, g_wku); cudaGetSymbolAddress((void**)&wvu, g_wvu);
    cudaGetSymbolAddress((void**)&wkr, g_wkr); cudaGetSymbolAddress((void**)&wo,  g_wo);

    cudaFuncSetAttribute(gemm_fused,
                         cudaFuncAttributeMaxDynamicSharedMemorySize, 49152);
    cudaFuncSetAttribute(attn_mma,
                         cudaFuncAttributeMaxDynamicSharedMemorySize, 65536);

    /* 0. rope table */
    rope_table<<<256, 256>>>();

    /* 1. split: x hi/lo; weights hi only */
    SplitJobs js;
    js.j[0] = { x,        xh,  xl,      TSEQ * 2048 };
    js.j[1] = { Wq_down,  wqd, nullptr, 2048 * 512  };
    js.j[2] = { Wq_up,    wqu, nullptr, 512 * 1024  };
    js.j[3] = { Wq_rope,  wqr, nullptr, 2048 * 1024 };
    js.j[4] = { Wkv_down, wkd, nullptr, 2048 * 512  };
    js.j[5] = { Wk_up,    wku, nullptr, 512 * 1024  };
    js.j[6] = { Wv_up,    wvu, nullptr, 512 * 2048  };
    js.j[7] = { Wk_rope,  wkr, nullptr, 2048 * 1024 };
    js.j[8] = { Wo,       wo,  nullptr, 2048 * 2048 };
    split_many<<<dim3(4096, 9), 256>>>(js);

    /* 2. GEMM1: x @ [Wq_down | Wkv_down | Wq_rope | Wk_rope] */
    {
        GSegs g; g.n = 4;
        g.s[0] = { xh, xl, 2048, wqd, nullptr, qdh, qdl,  512, 2048, 0,  0 };
        g.s[1] = { xh, xl, 2048, wkd, nullptr, kvh, kvl,  512, 2048, 4,  0 };
        g.s[2] = { xh, xl, 2048, wqr, qr, nullptr, nullptr, 1024, 2048, 8,  0 };
        g.s[3] = { xh, xl, 2048, wkr, kr, nullptr, nullptr, 1024, 2048, 16, 0 };
        gemm_fused<<<dim3(24, 16), 256, 49152>>>(g);
    }

    /* 3. GEMM2: qd @ Wq_up ; kv @ [Wk_up | Wv_up (-> V fp16 perm)] */
    {
        GSegs g; g.n = 3;
        g.s[0] = { qdh, qdl, 512, wqu, qc, nullptr, nullptr, 1024, 512, 0,  0 };
        g.s[1] = { kvh, kvl, 512, wku, kc, nullptr, nullptr, 1024, 512, 8,  0 };
        g.s[2] = { kvh, kvl, 512, wvu, nullptr, Vf, nullptr, 2048, 512, 16, 1 };
        g.s[3] = g.s[0];
        gemm_fused<<<dim3(32, 16), 256, 49152>>>(g);
    }

    /* 4. rope + pack Q (fp16 split) / K (fp16 single) */
    pack_kernel<<<dim3(TSEQ, NH), 64>>>();

    /* 5. fp16 tensor-core causal attention */
    attn_mma<<<dim3(32, NH), 128, 65536>>>();

    /* 6. GEMM3: O @ Wo -> out */
    {
        GSegs g; g.n = 1;
        g.s[0] = { Oh, Ol, 2048, wo, out, nullptr, nullptr, 2048, 2048, 0, 0 };
        g.s[1] = g.s[0]; g.s[2] = g.s[0]; g.s[3] = g.s[0];
        gemm_fused<<<dim3(16, 16), 256, 49152>>>(g);
    }
}

// round 13
// speedup vs baseline: 1.5032x; 1.0871x over previous
#include <cuda_runtime.h>
#include <cuda_bf16.h>
#include <cuda_fp16.h>
#include <math.h>
#include <stdint.h>

#define TSEQ   2048
#define DMODEL 2048
#define NH     16
#define DHEAD  128
#define DROPE  64
#define DCONT  64
#define SCALE_ATT 0.08838834764831845f  /* 1/sqrt(128) */

/* ------------------------------------------------------------------ */
/* Scratch (device globals)                                            */
/* ------------------------------------------------------------------ */
__device__ float g_qc[TSEQ * 1024];
__device__ float g_qr[TSEQ * 1024];
__device__ float g_kc[TSEQ * 1024];
__device__ float g_kr[TSEQ * 1024];
__device__ float g_cosT[TSEQ * 32];
__device__ float g_sinT[TSEQ * 32];

/* attention operands (fp16), [h][t][d]: all single fp16 */
__device__ __half g_Q[NH * TSEQ * DHEAD];
__device__ __half g_K[NH * TSEQ * DHEAD];
__device__ __half g_V[NH * TSEQ * DHEAD];

/* fp16 GEMM operands: activations hi/lo, weights hi only              */
__device__ __half g_xh[TSEQ * 2048],  g_xl[TSEQ * 2048];
__device__ __half g_qdh[TSEQ * 512],  g_qdl[TSEQ * 512];
__device__ __half g_kvh[TSEQ * 512],  g_kvl[TSEQ * 512];
__device__ __half g_Oh[TSEQ * 2048],  g_Ol[TSEQ * 2048];
__device__ __half g_wqd[2048 * 512];
__device__ __half g_wqu[512 * 1024];
__device__ __half g_wqr[2048 * 1024];
__device__ __half g_wkd[2048 * 512];
__device__ __half g_wku[512 * 1024];
__device__ __half g_wvu[512 * 2048];
__device__ __half g_wkr[2048 * 1024];
__device__ __half g_wo [2048 * 2048];

/* ------------------------------------------------------------------ */
/* asm helpers                                                         */
/* ------------------------------------------------------------------ */
#define CPA16(dst, src)                                                    \
    asm volatile("cp.async.cg.shared.global [%0], [%1], 16;"               \
                 :: "r"(dst), "l"(src))
#define CPA_COMMIT() asm volatile("cp.async.commit_group;")
#define CPA_WAIT1()  asm volatile("cp.async.wait_group 1;")
#define CPA_WAIT0()  asm volatile("cp.async.wait_group 0;")

#define LDSM4(r0, r1, r2, r3, addr)                                        \
    asm volatile("ldmatrix.sync.aligned.m8n8.x4.shared.b16 {%0,%1,%2,%3}, [%4];" \
                 : "=r"(r0), "=r"(r1), "=r"(r2), "=r"(r3) : "r"(addr))
#define LDSM4T(r0, r1, r2, r3, addr)                                       \
    asm volatile("ldmatrix.sync.aligned.m8n8.x4.trans.shared.b16 {%0,%1,%2,%3}, [%4];" \
                 : "=r"(r0), "=r"(r1), "=r"(r2), "=r"(r3) : "r"(addr))
#define MMA_F16(c, a, b0, b1)                                              \
    asm volatile("mma.sync.aligned.m16n8k16.row.col.f32.f16.f16.f32 "      \
                 "{%0,%1,%2,%3}, {%4,%5,%6,%7}, {%8,%9}, {%0,%1,%2,%3};"   \
                 : "+f"(c[0]), "+f"(c[1]), "+f"(c[2]), "+f"(c[3])          \
                 : "r"(a[0]), "r"(a[1]), "r"(a[2]), "r"(a[3]),             \
                   "r"(b0), "r"(b1))

__device__ __forceinline__ uint32_t hf2pack(float a, float b)
{
    return (uint32_t)__half_as_ushort(__float2half_rn(a)) |
           ((uint32_t)__half_as_ushort(__float2half_rn(b)) << 16);
}

/* ------------------------------------------------------------------ */
/* RoPE table                                                          */
/* ------------------------------------------------------------------ */
__global__ void __launch_bounds__(256) rope_table()
{
    const int idx = blockIdx.x * 256 + threadIdx.x;
    if (idx >= TSEQ * 32) return;
    const int t = idx >> 5, i = idx & 31;
    const double inv = pow(10000.0, -(double)i / 32.0);
    double sd, cd;
    sincos((double)t * inv, &sd, &cd);
    g_cosT[idx] = (float)cd;
    g_sinT[idx] = (float)sd;
}

/* ------------------------------------------------------------------ */
/* Batched fp32 -> fp16 split; l==null -> hi only                      */
/* ------------------------------------------------------------------ */
struct SplitJob { const float* src; __half *h, *l; int n; };
struct SplitJobs { SplitJob j[9]; };

__global__ void __launch_bounds__(256) split_many(SplitJobs js)
{
    const SplitJob J = js.j[blockIdx.y];
    const int i = (blockIdx.x * 256 + threadIdx.x) << 2;
    if (i >= J.n) return;
    float4 v = *(const float4*)(J.src + i);
    uint2 hp;
    hp.x = hf2pack(v.x, v.y);  hp.y = hf2pack(v.z, v.w);
    *(uint2*)(J.h + i) = hp;
    if (J.l) {
        const float h0 = __half2float(__float2half_rn(v.x));
        const float h1 = __half2float(__float2half_rn(v.y));
        const float h2 = __half2float(__float2half_rn(v.z));
        const float h3 = __half2float(__float2half_rn(v.w));
        uint2 lp;
        lp.x = hf2pack(v.x - h0, v.y - h1);
        lp.y = hf2pack(v.z - h2, v.w - h3);
        *(uint2*)(J.l + i) = lp;
    }
}

/* ------------------------------------------------------------------ */
/* Fused multi-segment fp16 tensor-core GEMM (unchanged from R12).     */
/* ------------------------------------------------------------------ */
struct GSeg {
    const __half *Ah, *Al;
    int lda;
    const __half *Bh;
    float* Cf;
    void *Ch, *Cl;             /* fp16 split out; vperm=1 -> single fp16 V perm */
    int N, K, tile0, vperm;
};
struct GSegs { GSeg s[4]; int n; };

#define STAGE_BYTES 24576
#define A_LO_OFF    8192
#define B_HI_OFF    16384

__device__ __forceinline__ uint32_t offA(int r, int c)
{ return (uint32_t)(((r << 2) + (c ^ ((r >> 1) & 3))) << 4); }
__device__ __forceinline__ uint32_t offB(int r, int c)
{ return (uint32_t)(((r << 4) + (c ^ (r & 7))) << 4); }

__global__ void __launch_bounds__(256, 2) gemm_fused(GSegs segs)
{
    extern __shared__ char dsm[];
    const uint32_t sb = (uint32_t)__cvta_generic_to_shared(dsm);

    const int tid  = threadIdx.x;
    const int lane = tid & 31;
    const int warp = tid >> 5;
    const int wm   = (warp >> 1) << 5;
    const int wn   = (warp & 1) << 6;
    const int bm   = blockIdx.y << 7;

    GSeg sg = segs.s[0];
#pragma unroll
    for (int i = 1; i < 4; i++)
        if (i < segs.n && (int)blockIdx.x >= segs.s[i].tile0) sg = segs.s[i];
    const int bn  = ((int)blockIdx.x - sg.tile0) << 7;
    const int lda = sg.lda, ldb = sg.N, K = sg.K;

    const int ar = tid >> 2, ac = tid & 3;
    const int br = tid >> 3, bc = tid & 7;
    const uint32_t aoff0 = offA(ar, ac), aoff1 = offA(ar + 64, ac);
    const uint32_t boff0 = offB(br, bc), boff1 = offB(br, bc + 8);

    const __half* gAh = sg.Ah + (size_t)(bm + ar) * lda + ac * 8;
    const __half* gAl = sg.Al + (size_t)(bm + ar) * lda + ac * 8;
    const __half* gBh = sg.Bh + (size_t)br * ldb + bn + bc * 8;

    float acc[2][8][4];
#pragma unroll
    for (int mt = 0; mt < 2; mt++)
#pragma unroll
        for (int nt = 0; nt < 8; nt++)
#pragma unroll
            for (int i = 0; i < 4; i++) acc[mt][nt][i] = 0.f;

    const int nk = K >> 5;

    auto load_stage = [&](int st, int k0) {
        const uint32_t s0 = sb + st * STAGE_BYTES;
        const __half* pAh = gAh + k0;
        const __half* pAl = gAl + k0;
        CPA16(s0 + aoff0, pAh);
        CPA16(s0 + aoff1, pAh + (size_t)64 * lda);
        CPA16(s0 + A_LO_OFF + aoff0, pAl);
        CPA16(s0 + A_LO_OFF + aoff1, pAl + (size_t)64 * lda);
        const __half* pBh = gBh + (size_t)k0 * ldb;
        CPA16(s0 + B_HI_OFF + boff0, pBh);
        CPA16(s0 + B_HI_OFF + boff1, pBh + 64);
    };

    load_stage(0, 0);
    CPA_COMMIT();

    for (int it = 0; it < nk; it++) {
        if (it + 1 < nk) { load_stage((it + 1) & 1, (it + 1) << 5); CPA_COMMIT(); }
        if (it + 1 < nk) CPA_WAIT1(); else CPA_WAIT0();
        __syncthreads();

        const uint32_t s0 = sb + (it & 1) * STAGE_BYTES;
#pragma unroll
        for (int ks = 0; ks < 2; ks++) {
            uint32_t ah[2][4], al_[2][4];
#pragma unroll
            for (int mt = 0; mt < 2; mt++) {
                const int rowA   = wm + (mt << 4) + (lane & 15);
                const int chunkA = (ks << 1) + (lane >> 4);
                const uint32_t ad = s0 + offA(rowA, chunkA);
                LDSM4(ah[mt][0], ah[mt][1], ah[mt][2], ah[mt][3], ad);
                LDSM4(al_[mt][0], al_[mt][1], al_[mt][2], al_[mt][3], ad + A_LO_OFF);
            }
#pragma unroll
            for (int np = 0; np < 4; np++) {
                const int rowB   = (ks << 4) + (lane & 15);
                const int chunkB = (wn >> 3) + (lane >> 4) + (np << 1);
                const uint32_t bd = s0 + B_HI_OFF + offB(rowB, chunkB);
                uint32_t h0, h1, h2, h3;
                LDSM4T(h0, h1, h2, h3, bd);
#pragma unroll
                for (int mt = 0; mt < 2; mt++) {
                    MMA_F16(acc[mt][2 * np],     ah[mt],  h0, h1);
                    MMA_F16(acc[mt][2 * np],     al_[mt], h0, h1);
                    MMA_F16(acc[mt][2 * np + 1], ah[mt],  h2, h3);
                    MMA_F16(acc[mt][2 * np + 1], al_[mt], h2, h3);
                }
            }
        }
        __syncthreads();
    }

    const int erow = lane >> 2;
    const int ecol = (lane & 3) << 1;
    if (sg.Cf) {
#pragma unroll
        for (int mt = 0; mt < 2; mt++)
#pragma unroll
            for (int nt = 0; nt < 8; nt++) {
                const int r = bm + wm + (mt << 4) + erow;
                const int c = bn + wn + (nt << 3) + ecol;
                *(float2*)(sg.Cf + (size_t)r * ldb + c) =
                    make_float2(acc[mt][nt][0], acc[mt][nt][1]);
                *(float2*)(sg.Cf + (size_t)(r + 8) * ldb + c) =
                    make_float2(acc[mt][nt][2], acc[mt][nt][3]);
            }
    } else if (sg.vperm) {
        __half* Ch = (__half*)sg.Ch;
#pragma unroll
        for (int mt = 0; mt < 2; mt++)
#pragma unroll
            for (int nt = 0; nt < 8; nt++) {
                const int r = bm + wm + (mt << 4) + erow;
                const int c = bn + wn + (nt << 3) + ecol;
#pragma unroll
                for (int hh = 0; hh < 2; hh++) {
                    const float v0 = acc[mt][nt][2 * hh];
                    const float v1 = acc[mt][nt][2 * hh + 1];
                    const int rr = r + 8 * hh;
                    const size_t idx =
                        ((size_t)(c >> 7) * TSEQ + rr) * DHEAD + (c & 127);
                    *(uint32_t*)(Ch + idx) = hf2pack(v0, v1);
                }
            }
    } else {
        __half* Ch = (__half*)sg.Ch;
        __half* Cl = (__half*)sg.Cl;
#pragma unroll
        for (int mt = 0; mt < 2; mt++)
#pragma unroll
            for (int nt = 0; nt < 8; nt++) {
                const int r = bm + wm + (mt << 4) + erow;
                const int c = bn + wn + (nt << 3) + ecol;
#pragma unroll
                for (int hh = 0; hh < 2; hh++) {
                    const float v0 = acc[mt][nt][2 * hh];
                    const float v1 = acc[mt][nt][2 * hh + 1];
                    const float h0 = __half2float(__float2half_rn(v0));
                    const float h1 = __half2float(__float2half_rn(v1));
                    const size_t idx = (size_t)(r + 8 * hh) * ldb + c;
                    *(uint32_t*)(Ch + idx) = hf2pack(v0, v1);
                    *(uint32_t*)(Cl + idx) = hf2pack(v0 - h0, v1 - h1);
                }
            }
    }
}

/* ------------------------------------------------------------------ */
/* Pack + RoPE -> Q (pre-scaled) / K, single fp16 in [h][t][d].        */
/* ------------------------------------------------------------------ */
__global__ void __launch_bounds__(64) pack_kernel()
{
    const int t = blockIdx.x;
    const int h = blockIdx.y;
    const int d2 = threadIdx.x << 1;
    const size_t o = ((size_t)h * TSEQ + t) * DHEAD + d2;

    float q0, q1, k0, k1;
    if (d2 < DCONT) {
        const size_t b = (size_t)t * 1024 + h * DCONT + d2;
        q0 = g_qc[b];     q1 = g_qc[b + 1];
        k0 = g_kc[b];     k1 = g_kc[b + 1];
    } else {
        const int i = d2 - DCONT;
        const int ip = (i < 32) ? i : i - 32;
        const float c0 = g_cosT[t * 32 + ip],     s0 = g_sinT[t * 32 + ip];
        const float c1 = g_cosT[t * 32 + ip + 1], s1 = g_sinT[t * 32 + ip + 1];
        const size_t b = (size_t)t * 1024 + h * DROPE;
        const float qa0 = g_qr[b + ip],      qa1 = g_qr[b + ip + 1];
        const float qb0 = g_qr[b + 32 + ip], qb1 = g_qr[b + 32 + ip + 1];
        const float ka0 = g_kr[b + ip],      ka1 = g_kr[b + ip + 1];
        const float kb0 = g_kr[b + 32 + ip], kb1 = g_kr[b + 32 + ip + 1];
        if (i < 32) {
            q0 = qa0 * c0 - qb0 * s0;  q1 = qa1 * c1 - qb1 * s1;
            k0 = ka0 * c0 - kb0 * s0;  k1 = ka1 * c1 - kb1 * s1;
        } else {
            q0 = qa0 * s0 + qb0 * c0;  q1 = qa1 * s1 + qb1 * c1;
            k0 = ka0 * s0 + kb0 * c0;  k1 = ka1 * s1 + kb1 * c1;
        }
    }
    q0 *= SCALE_ATT; q1 *= SCALE_ATT;

    *(uint32_t*)(g_Q + o) = hf2pack(q0, q1);
    *(uint32_t*)(g_K + o) = hf2pack(k0, k1);
}

/* ------------------------------------------------------------------ */
/* fp16 tensor-core causal flash attention. All operands single fp16.  */
/* Double-buffered K/V tiles; smem [K0|V0|K1|V1] = 64KB.                */
/* ------------------------------------------------------------------ */
__device__ __forceinline__ uint32_t offV(int r, int c)
{ return (uint32_t)(((r << 4) + (c ^ (r & 7))) << 4); }   /* 16 chunks/row */

__global__ void __launch_bounds__(128) attn_mma()
{
    extern __shared__ char dsm[];
    const uint32_t sb = (uint32_t)__cvta_generic_to_shared(dsm);

    const int h    = blockIdx.y;
    const int qblk = 31 - (int)blockIdx.x;       /* long CTAs first */
    const int qb   = qblk << 6;
    const int tid  = threadIdx.x;
    const int lane = tid & 31;
    const int warp = tid >> 5;
    const int w16  = warp << 4;

    const __half* Qb = g_Q + (size_t)h * TSEQ * DHEAD;
    const __half* Kb = g_K + (size_t)h * TSEQ * DHEAD;
    const __half* Vb = g_V + (size_t)h * TSEQ * DHEAD;

    const int sr = tid >> 4;            /* 0..7  */
    const int sc = tid & 15;            /* 0..15 */

    /* ---- stage Q (64 rows) into buf0, LDSM into regs ---- */
#pragma unroll
    for (int p = 0; p < 8; p++) {
        const int r = sr + (p << 3);
        CPA16(sb + offV(r, sc), Qb + (size_t)(qb + r) * DHEAD + sc * 8);
    }
    CPA_COMMIT(); CPA_WAIT0();
    __syncthreads();

    uint32_t qf[8][4];
#pragma unroll
    for (int ks = 0; ks < 8; ks++) {
        const uint32_t ad = offV(w16 + (lane & 15), (ks << 1) + (lane >> 4));
        LDSM4(qf[ks][0], qf[ks][1], qf[ks][2], qf[ks][3], sb + ad);
    }
    __syncthreads();

    float O[16][4];
#pragma unroll
    for (int nt = 0; nt < 16; nt++)
#pragma unroll
        for (int i = 0; i < 4; i++) O[nt][i] = 0.f;
    float m0 = -1e30f, m1 = -1e30f, l0 = 0.f, l1 = 0.f;

    const int ntiles = qblk + 1;
    const int row0 = qb + w16 + (lane >> 2);
    const int row1 = row0 + 8;

    auto load_kv = [&](int b, int kt) {
        const int kb = kt << 6;
        const uint32_t s0 = sb + b * 32768;
#pragma unroll
        for (int p = 0; p < 8; p++) {
            const int r = sr + (p << 3);
            const size_t gi = (size_t)(kb + r) * DHEAD + sc * 8;
            const uint32_t so = offV(r, sc);
            CPA16(s0 + so,         Kb + gi);
            CPA16(s0 + 16384 + so, Vb + gi);
        }
    };

    load_kv(0, 0); CPA_COMMIT();

    for (int kt = 0; kt < ntiles; kt++) {
        const int kb = kt << 6;
        if (kt + 1 < ntiles) { load_kv((kt + 1) & 1, kt + 1); CPA_COMMIT(); }
        if (kt + 1 < ntiles) CPA_WAIT1(); else CPA_WAIT0();
        __syncthreads();

        const uint32_t kbase = sb + (kt & 1) * 32768;
        const uint32_t vbase = kbase + 16384;

        /* ---- scores S = Q K^T ---- */
        float S[8][4];
#pragma unroll
        for (int nt = 0; nt < 8; nt++)
#pragma unroll
            for (int i = 0; i < 4; i++) S[nt][i] = 0.f;

#pragma unroll
        for (int ntp = 0; ntp < 4; ntp++) {
#pragma unroll
            for (int ks = 0; ks < 8; ks++) {
                const uint32_t ad = offV((ntp << 4) + (lane & 15),
                                         (ks << 1) + (lane >> 4));
                uint32_t k0, k1, k2, k3;
                LDSM4(k0, k1, k2, k3, kbase + ad);
                MMA_F16(S[2 * ntp],     qf[ks], k0, k2);
                MMA_F16(S[2 * ntp + 1], qf[ks], k1, k3);
            }
        }

        /* ---- causal mask on diagonal tile ---- */
        if (kb == qb) {
#pragma unroll
            for (int nt = 0; nt < 8; nt++) {
                const int key = kb + (nt << 3) + ((lane & 3) << 1);
                if (key > row0)     S[nt][0] = -1e30f;
                if (key + 1 > row0) S[nt][1] = -1e30f;
                if (key > row1)     S[nt][2] = -1e30f;
                if (key + 1 > row1) S[nt][3] = -1e30f;
            }
        }

        /* ---- online softmax ---- */
        float mx0 = -1e30f, mx1 = -1e30f;
#pragma unroll
        for (int nt = 0; nt < 8; nt++) {
            mx0 = fmaxf(mx0, fmaxf(S[nt][0], S[nt][1]));
            mx1 = fmaxf(mx1, fmaxf(S[nt][2], S[nt][3]));
        }
        mx0 = fmaxf(mx0, __shfl_xor_sync(0xffffffffu, mx0, 1));
        mx0 = fmaxf(mx0, __shfl_xor_sync(0xffffffffu, mx0, 2));
        mx1 = fmaxf(mx1, __shfl_xor_sync(0xffffffffu, mx1, 1));
        mx1 = fmaxf(mx1, __shfl_xor_sync(0xffffffffu, mx1, 2));

        const float m0n = fmaxf(m0, mx0), m1n = fmaxf(m1, mx1);
        const float a0 = __expf(m0 - m0n), a1 = __expf(m1 - m1n);
        m0 = m0n; m1 = m1n;

        uint32_t aP[4][4];
        float ps0 = 0.f, ps1 = 0.f;
#pragma unroll
        for (int nt = 0; nt < 8; nt++) {
            const float p0 = __expf(S[nt][0] - m0n);
            const float p1 = __expf(S[nt][1] - m0n);
            const float p2 = __expf(S[nt][2] - m1n);
            const float p3 = __expf(S[nt][3] - m1n);
            ps0 += p0 + p1; ps1 += p2 + p3;
            const int kk = nt >> 1;
            const int e  = (nt & 1) << 1;
            aP[kk][e]     = hf2pack(p0, p1);
            aP[kk][e + 1] = hf2pack(p2, p3);
        }
        ps0 += __shfl_xor_sync(0xffffffffu, ps0, 1);
        ps0 += __shfl_xor_sync(0xffffffffu, ps0, 2);
        ps1 += __shfl_xor_sync(0xffffffffu, ps1, 1);
        ps1 += __shfl_xor_sync(0xffffffffu, ps1, 2);
        l0 = l0 * a0 + ps0;
        l1 = l1 * a1 + ps1;

#pragma unroll
        for (int nt = 0; nt < 16; nt++) {
            O[nt][0] *= a0; O[nt][1] *= a0;
            O[nt][2] *= a1; O[nt][3] *= a1;
        }

        /* ---- O += P V ---- */
#pragma unroll
        for (int kk = 0; kk < 4; kk++) {
#pragma unroll
            for (int ntp = 0; ntp < 8; ntp++) {
                const uint32_t ad = offV((kk << 4) + (lane & 15),
                                         (ntp << 1) + (lane >> 4));
                uint32_t v0, v1, v2, v3;
                LDSM4T(v0, v1, v2, v3, vbase + ad);
                MMA_F16(O[2 * ntp],     aP[kk], v0, v1);
                MMA_F16(O[2 * ntp + 1], aP[kk], v2, v3);
            }
        }
        __syncthreads();   /* guard buffer reuse */
    }

    /* ---- epilogue: normalize, write fp16 hi/lo [t][h*128+d] ---- */
    const float inv0 = 1.0f / l0, inv1 = 1.0f / l1;
#pragma unroll
    for (int nt = 0; nt < 16; nt++) {
        const int d = (nt << 3) + ((lane & 3) << 1);
        const float v0 = O[nt][0] * inv0, v1 = O[nt][1] * inv0;
        const float v2 = O[nt][2] * inv1, v3 = O[nt][3] * inv1;
        const float h0 = __half2float(__float2half_rn(v0));
        const float h1 = __half2float(__float2half_rn(v1));
        const float h2 = __half2float(__float2half_rn(v2));
        const float h3 = __half2float(__float2half_rn(v3));
        const size_t i0 = (size_t)row0 * DMODEL + h * DHEAD + d;
        const size_t i1 = (size_t)row1 * DMODEL + h * DHEAD + d;
        *(uint32_t*)(g_Oh + i0) = hf2pack(v0, v1);
        *(uint32_t*)(g_Ol + i0) = hf2pack(v0 - h0, v1 - h1);
        *(uint32_t*)(g_Oh + i1) = hf2pack(v2, v3);
        *(uint32_t*)(g_Ol + i1) = hf2pack(v2 - h2, v3 - h3);
    }
}

/* ------------------------------------------------------------------ */
extern "C" void kernel_launch(void* const* d_in, const int* in_sizes, int n_in,
                              void* d_out, int out_size)
{
    const float* x        = (const float*)d_in[0];
    const float* Wq_down  = (const float*)d_in[1];
    const float* Wq_up    = (const float*)d_in[2];
    const float* Wq_rope  = (const float*)d_in[3];
    const float* Wkv_down = (const float*)d_in[4];
    const float* Wk_up    = (const float*)d_in[5];
    const float* Wv_up    = (const float*)d_in[6];
    const float* Wk_rope  = (const float*)d_in[7];
    const float* Wo       = (const float*)d_in[8];
    float* out = (float*)d_out;

    float *qc, *qr, *kc, *kr;
    cudaGetSymbolAddress((void**)&qc, g_qc);
    cudaGetSymbolAddress((void**)&qr, g_qr);
    cudaGetSymbolAddress((void**)&kc, g_kc);
    cudaGetSymbolAddress((void**)&kr, g_kr);

    __half *xh, *xl, *qdh, *qdl, *kvh, *kvl, *Oh, *Ol, *Vf;
    __half *wqd, *wqu, *wqr, *wkd, *wku, *wvu, *wkr, *wo;
    cudaGetSymbolAddress((void**)&xh, g_xh);   cudaGetSymbolAddress((void**)&xl, g_xl);
    cudaGetSymbolAddress((void**)&qdh, g_qdh); cudaGetSymbolAddress((void**)&qdl, g_qdl);
    cudaGetSymbolAddress((void**)&kvh, g_kvh); cudaGetSymbolAddress((void**)&kvl, g_kvl);
    cudaGetSymbolAddress((void**)&Oh, g_Oh);   cudaGetSymbolAddress((void**)&Ol, g_Ol);
    cudaGetSymbolAddress((void**)&Vf, g_V);
    cudaGetSymbolAddress((void**)&wqd, g_wqd); cudaGetSymbolAddress((void**)&wqu, g_wqu);
    cudaGetSymbolAddress((void**)&wqr, g_wqr); cudaGetSymbolAddress((void**)&wkd, g_wkd);
    cudaGetSymbolAddress((void**)&wku, g_wku); cudaGetSymbolAddress((void**)&wvu, g_wvu);
    cudaGetSymbolAddress((void**)&wkr, g_wkr); cudaGetSymbolAddress((void**)&wo,  g_wo);

    cudaFuncSetAttribute(gemm_fused,
                         cudaFuncAttributeMaxDynamicSharedMemorySize, 49152);
    cudaFuncSetAttribute(attn_mma,
                         cudaFuncAttributeMaxDynamicSharedMemorySize, 65536);

    /* 0. rope table */
    rope_table<<<256, 256>>>();

    /* 1. split: x hi/lo; weights hi only */
    SplitJobs js;
    js.j[0] = { x,        xh,  xl,      TSEQ * 2048 };
    js.j[1] = { Wq_down,  wqd, nullptr, 2048 * 512  };
    js.j[2] = { Wq_up,    wqu, nullptr, 512 * 1024  };
    js.j[3] = { Wq_rope,  wqr, nullptr, 2048 * 1024 };
    js.j[4] = { Wkv_down, wkd, nullptr, 2048 * 512  };
    js.j[5] = { Wk_up,    wku, nullptr, 512 * 1024  };
    js.j[6] = { Wv_up,    wvu, nullptr, 512 * 2048  };
    js.j[7] = { Wk_rope,  wkr, nullptr, 2048 * 1024 };
    js.j[8] = { Wo,       wo,  nullptr, 2048 * 2048 };
    split_many<<<dim3(4096, 9), 256>>>(js);

    /* 2. GEMM1: x @ [Wq_down | Wkv_down | Wq_rope | Wk_rope] */
    {
        GSegs g; g.n = 4;
        g.s[0] = { xh, xl, 2048, wqd, nullptr, qdh, qdl,  512, 2048, 0,  0 };
        g.s[1] = { xh, xl, 2048, wkd, nullptr, kvh, kvl,  512, 2048, 4,  0 };
        g.s[2] = { xh, xl, 2048, wqr, qr, nullptr, nullptr, 1024, 2048, 8,  0 };
        g.s[3] = { xh, xl, 2048, wkr, kr, nullptr, nullptr, 1024, 2048, 16, 0 };
        gemm_fused<<<dim3(24, 16), 256, 49152>>>(g);
    }

    /* 3. GEMM2: qd @ Wq_up ; kv @ [Wk_up | Wv_up (-> V fp16 perm)] */
    {
        GSegs g; g.n = 3;
        g.s[0] = { qdh, qdl, 512, wqu, qc, nullptr, nullptr, 1024, 512, 0,  0 };
        g.s[1] = { kvh, kvl, 512, wku, kc, nullptr, nullptr, 1024, 512, 8,  0 };
        g.s[2] = { kvh, kvl, 512, wvu, nullptr, Vf, nullptr, 2048, 512, 16, 1 };
        g.s[3] = g.s[0];
        gemm_fused<<<dim3(32, 16), 256, 49152>>>(g);
    }

    /* 4. rope + pack Q/K (single fp16) */
    pack_kernel<<<dim3(TSEQ, NH), 64>>>();

    /* 5. fp16 tensor-core causal attention */
    attn_mma<<<dim3(32, NH), 128, 65536>>>();

    /* 6. GEMM3: O @ Wo -> out */
    {
        GSegs g; g.n = 1;
        g.s[0] = { Oh, Ol, 2048, wo, out, nullptr, nullptr, 2048, 2048, 0, 0 };
        g.s[1] = g.s[0]; g.s[2] = g.s[0]; g.s[3] = g.s[0];
        gemm_fused<<<dim3(16, 16), 256, 49152>>>(g);
    }
}

// round 14
// speedup vs baseline: 1.9409x; 1.2912x over previous
#include <cuda_runtime.h>
#include <cuda_bf16.h>
#include <cuda_fp16.h>
#include <math.h>
#include <stdint.h>

#define TSEQ   2048
#define DMODEL 2048
#define NH     16
#define DHEAD  128
#define DROPE  64
#define DCONT  64
#define SCALE_ATT 0.08838834764831845f  /* 1/sqrt(128) */

/* ------------------------------------------------------------------ */
/* Scratch (device globals)                                            */
/* ------------------------------------------------------------------ */
__device__ float g_qc[TSEQ * 1024];
__device__ float g_qr[TSEQ * 1024];
__device__ float g_kc[TSEQ * 1024];
__device__ float g_kr[TSEQ * 1024];
__device__ float g_cosT[TSEQ * 32];
__device__ float g_sinT[TSEQ * 32];

/* attention operands (fp16), [h][t][d]: all single fp16 */
__device__ __half g_Q[NH * TSEQ * DHEAD];
__device__ __half g_K[NH * TSEQ * DHEAD];
__device__ __half g_V[NH * TSEQ * DHEAD];

/* fp16 GEMM operands */
__device__ __half g_x [TSEQ * 2048];                     /* x single fp16 */
__device__ __half g_qdh[TSEQ * 512],  g_qdl[TSEQ * 512]; /* qd split      */
__device__ __half g_kvh[TSEQ * 512],  g_kvl[TSEQ * 512]; /* kv split      */
__device__ __half g_O [TSEQ * 2048];                     /* O single fp16 */
__device__ __half g_wqd[2048 * 512];
__device__ __half g_wqu[512 * 1024];
__device__ __half g_wqr[2048 * 1024];
__device__ __half g_wkd[2048 * 512];
__device__ __half g_wku[512 * 1024];
__device__ __half g_wvu[512 * 2048];
__device__ __half g_wkr[2048 * 1024];
__device__ __half g_wo [2048 * 2048];

/* ------------------------------------------------------------------ */
/* asm helpers                                                         */
/* ------------------------------------------------------------------ */
#define CPA16(dst, src)                                                    \
    asm volatile("cp.async.cg.shared.global [%0], [%1], 16;"               \
                 :: "r"(dst), "l"(src))
#define CPA_COMMIT() asm volatile("cp.async.commit_group;")
#define CPA_WAIT1()  asm volatile("cp.async.wait_group 1;")
#define CPA_WAIT0()  asm volatile("cp.async.wait_group 0;")

#define LDSM4(r0, r1, r2, r3, addr)                                        \
    asm volatile("ldmatrix.sync.aligned.m8n8.x4.shared.b16 {%0,%1,%2,%3}, [%4];" \
                 : "=r"(r0), "=r"(r1), "=r"(r2), "=r"(r3) : "r"(addr))
#define LDSM4T(r0, r1, r2, r3, addr)                                       \
    asm volatile("ldmatrix.sync.aligned.m8n8.x4.trans.shared.b16 {%0,%1,%2,%3}, [%4];" \
                 : "=r"(r0), "=r"(r1), "=r"(r2), "=r"(r3) : "r"(addr))
#define MMA_F16(c, a, b0, b1)                                              \
    asm volatile("mma.sync.aligned.m16n8k16.row.col.f32.f16.f16.f32 "      \
                 "{%0,%1,%2,%3}, {%4,%5,%6,%7}, {%8,%9}, {%0,%1,%2,%3};"   \
                 : "+f"(c[0]), "+f"(c[1]), "+f"(c[2]), "+f"(c[3])          \
                 : "r"(a[0]), "r"(a[1]), "r"(a[2]), "r"(a[3]),             \
                   "r"(b0), "r"(b1))

__device__ __forceinline__ uint32_t hf2pack(float a, float b)
{
    return (uint32_t)__half_as_ushort(__float2half_rn(a)) |
           ((uint32_t)__half_as_ushort(__float2half_rn(b)) << 16);
}

/* ------------------------------------------------------------------ */
/* RoPE table                                                          */
/* ------------------------------------------------------------------ */
__global__ void __launch_bounds__(256) rope_table()
{
    const int idx = blockIdx.x * 256 + threadIdx.x;
    if (idx >= TSEQ * 32) return;
    const int t = idx >> 5, i = idx & 31;
    const double inv = pow(10000.0, -(double)i / 32.0);
    double sd, cd;
    sincos((double)t * inv, &sd, &cd);
    g_cosT[idx] = (float)cd;
    g_sinT[idx] = (float)sd;
}

/* ------------------------------------------------------------------ */
/* Batched fp32 -> fp16 (hi only)                                      */
/* ------------------------------------------------------------------ */
struct SplitJob { const float* src; __half *h; int n; };
struct SplitJobs { SplitJob j[9]; };

__global__ void __launch_bounds__(256) split_many(SplitJobs js)
{
    const SplitJob J = js.j[blockIdx.y];
    const int i = (blockIdx.x * 256 + threadIdx.x) << 2;
    if (i >= J.n) return;
    float4 v = *(const float4*)(J.src + i);
    uint2 hp;
    hp.x = hf2pack(v.x, v.y);  hp.y = hf2pack(v.z, v.w);
    *(uint2*)(J.h + i) = hp;
}

/* ------------------------------------------------------------------ */
/* Fused multi-segment fp16 tensor-core GEMM.                          */
/* HASLO=1: C = (Ah+Al) @ B (split-A, 2 MMA/frag).                     */
/* HASLO=0: C =  Ah     @ B (single-A, 1 MMA/frag).                    */
/* BM=BN=128, BK=32, 256 threads, 2-stage cp.async, 2 CTAs/SM.         */
/* ------------------------------------------------------------------ */
struct GSeg {
    const __half *Ah, *Al;
    int lda;
    const __half *Bh;
    float* Cf;
    void *Ch, *Cl;             /* fp16 split out; vperm=1 -> single fp16 V perm */
    int N, K, tile0, vperm;
};
struct GSegs { GSeg s[4]; int n; };

#define STAGE_BYTES 24576
#define A_LO_OFF    8192
#define B_HI_OFF    16384

__device__ __forceinline__ uint32_t offA(int r, int c)
{ return (uint32_t)(((r << 2) + (c ^ ((r >> 1) & 3))) << 4); }
__device__ __forceinline__ uint32_t offB(int r, int c)
{ return (uint32_t)(((r << 4) + (c ^ (r & 7))) << 4); }

template<bool HASLO>
__global__ void __launch_bounds__(256, 2) gemm_fused(GSegs segs)
{
    extern __shared__ char dsm[];
    const uint32_t sb = (uint32_t)__cvta_generic_to_shared(dsm);

    const int tid  = threadIdx.x;
    const int lane = tid & 31;
    const int warp = tid >> 5;
    const int wm   = (warp >> 1) << 5;
    const int wn   = (warp & 1) << 6;
    const int bm   = blockIdx.y << 7;

    GSeg sg = segs.s[0];
#pragma unroll
    for (int i = 1; i < 4; i++)
        if (i < segs.n && (int)blockIdx.x >= segs.s[i].tile0) sg = segs.s[i];
    const int bn  = ((int)blockIdx.x - sg.tile0) << 7;
    const int lda = sg.lda, ldb = sg.N, K = sg.K;

    const int ar = tid >> 2, ac = tid & 3;
    const int br = tid >> 3, bc = tid & 7;
    const uint32_t aoff0 = offA(ar, ac), aoff1 = offA(ar + 64, ac);
    const uint32_t boff0 = offB(br, bc), boff1 = offB(br, bc + 8);

    const __half* gAh = sg.Ah + (size_t)(bm + ar) * lda + ac * 8;
    const __half* gAl = HASLO ? sg.Al + (size_t)(bm + ar) * lda + ac * 8 : nullptr;
    const __half* gBh = sg.Bh + (size_t)br * ldb + bn + bc * 8;

    float acc[2][8][4];
#pragma unroll
    for (int mt = 0; mt < 2; mt++)
#pragma unroll
        for (int nt = 0; nt < 8; nt++)
#pragma unroll
            for (int i = 0; i < 4; i++) acc[mt][nt][i] = 0.f;

    const int nk = K >> 5;

    auto load_stage = [&](int st, int k0) {
        const uint32_t s0 = sb + st * STAGE_BYTES;
        const __half* pAh = gAh + k0;
        CPA16(s0 + aoff0, pAh);
        CPA16(s0 + aoff1, pAh + (size_t)64 * lda);
        if (HASLO) {
            const __half* pAl = gAl + k0;
            CPA16(s0 + A_LO_OFF + aoff0, pAl);
            CPA16(s0 + A_LO_OFF + aoff1, pAl + (size_t)64 * lda);
        }
        const __half* pBh = gBh + (size_t)k0 * ldb;
        CPA16(s0 + B_HI_OFF + boff0, pBh);
        CPA16(s0 + B_HI_OFF + boff1, pBh + 64);
    };

    load_stage(0, 0);
    CPA_COMMIT();

    for (int it = 0; it < nk; it++) {
        if (it + 1 < nk) { load_stage((it + 1) & 1, (it + 1) << 5); CPA_COMMIT(); }
        if (it + 1 < nk) CPA_WAIT1(); else CPA_WAIT0();
        __syncthreads();

        const uint32_t s0 = sb + (it & 1) * STAGE_BYTES;
#pragma unroll
        for (int ks = 0; ks < 2; ks++) {
            uint32_t ah[2][4], al_[2][4];
#pragma unroll
            for (int mt = 0; mt < 2; mt++) {
                const int rowA   = wm + (mt << 4) + (lane & 15);
                const int chunkA = (ks << 1) + (lane >> 4);
                const uint32_t ad = s0 + offA(rowA, chunkA);
                LDSM4(ah[mt][0], ah[mt][1], ah[mt][2], ah[mt][3], ad);
                if (HASLO)
                    LDSM4(al_[mt][0], al_[mt][1], al_[mt][2], al_[mt][3],
                          ad + A_LO_OFF);
            }
#pragma unroll
            for (int np = 0; np < 4; np++) {
                const int rowB   = (ks << 4) + (lane & 15);
                const int chunkB = (wn >> 3) + (lane >> 4) + (np << 1);
                const uint32_t bd = s0 + B_HI_OFF + offB(rowB, chunkB);
                uint32_t h0, h1, h2, h3;
                LDSM4T(h0, h1, h2, h3, bd);
#pragma unroll
                for (int mt = 0; mt < 2; mt++) {
                    MMA_F16(acc[mt][2 * np],     ah[mt],  h0, h1);
                    MMA_F16(acc[mt][2 * np + 1], ah[mt],  h2, h3);
                    if (HASLO) {
                        MMA_F16(acc[mt][2 * np],     al_[mt], h0, h1);
                        MMA_F16(acc[mt][2 * np + 1], al_[mt], h2, h3);
                    }
                }
            }
        }
        __syncthreads();
    }

    const int erow = lane >> 2;
    const int ecol = (lane & 3) << 1;
    if (sg.Cf) {
#pragma unroll
        for (int mt = 0; mt < 2; mt++)
#pragma unroll
            for (int nt = 0; nt < 8; nt++) {
                const int r = bm + wm + (mt << 4) + erow;
                const int c = bn + wn + (nt << 3) + ecol;
                *(float2*)(sg.Cf + (size_t)r * ldb + c) =
                    make_float2(acc[mt][nt][0], acc[mt][nt][1]);
                *(float2*)(sg.Cf + (size_t)(r + 8) * ldb + c) =
                    make_float2(acc[mt][nt][2], acc[mt][nt][3]);
            }
    } else if (sg.vperm) {
        __half* Ch = (__half*)sg.Ch;
#pragma unroll
        for (int mt = 0; mt < 2; mt++)
#pragma unroll
            for (int nt = 0; nt < 8; nt++) {
                const int r = bm + wm + (mt << 4) + erow;
                const int c = bn + wn + (nt << 3) + ecol;
#pragma unroll
                for (int hh = 0; hh < 2; hh++) {
                    const float v0 = acc[mt][nt][2 * hh];
                    const float v1 = acc[mt][nt][2 * hh + 1];
                    const int rr = r + 8 * hh;
                    const size_t idx =
                        ((size_t)(c >> 7) * TSEQ + rr) * DHEAD + (c & 127);
                    *(uint32_t*)(Ch + idx) = hf2pack(v0, v1);
                }
            }
    } else {
        __half* Ch = (__half*)sg.Ch;
        __half* Cl = (__half*)sg.Cl;
#pragma unroll
        for (int mt = 0; mt < 2; mt++)
#pragma unroll
            for (int nt = 0; nt < 8; nt++) {
                const int r = bm + wm + (mt << 4) + erow;
                const int c = bn + wn + (nt << 3) + ecol;
#pragma unroll
                for (int hh = 0; hh < 2; hh++) {
                    const float v0 = acc[mt][nt][2 * hh];
                    const float v1 = acc[mt][nt][2 * hh + 1];
                    const float h0 = __half2float(__float2half_rn(v0));
                    const float h1 = __half2float(__float2half_rn(v1));
                    const size_t idx = (size_t)(r + 8 * hh) * ldb + c;
                    *(uint32_t*)(Ch + idx) = hf2pack(v0, v1);
                    *(uint32_t*)(Cl + idx) = hf2pack(v0 - h0, v1 - h1);
                }
            }
    }
}

/* ------------------------------------------------------------------ */
/* Pack + RoPE -> Q (pre-scaled) / K, single fp16 in [h][t][d].        */
/* ------------------------------------------------------------------ */
__global__ void __launch_bounds__(64) pack_kernel()
{
    const int t = blockIdx.x;
    const int h = blockIdx.y;
    const int d2 = threadIdx.x << 1;
    const size_t o = ((size_t)h * TSEQ + t) * DHEAD + d2;

    float q0, q1, k0, k1;
    if (d2 < DCONT) {
        const size_t b = (size_t)t * 1024 + h * DCONT + d2;
        q0 = g_qc[b];     q1 = g_qc[b + 1];
        k0 = g_kc[b];     k1 = g_kc[b + 1];
    } else {
        const int i = d2 - DCONT;
        const int ip = (i < 32) ? i : i - 32;
        const float c0 = g_cosT[t * 32 + ip],     s0 = g_sinT[t * 32 + ip];
        const float c1 = g_cosT[t * 32 + ip + 1], s1 = g_sinT[t * 32 + ip + 1];
        const size_t b = (size_t)t * 1024 + h * DROPE;
        const float qa0 = g_qr[b + ip],      qa1 = g_qr[b + ip + 1];
        const float qb0 = g_qr[b + 32 + ip], qb1 = g_qr[b + 32 + ip + 1];
        const float ka0 = g_kr[b + ip],      ka1 = g_kr[b + ip + 1];
        const float kb0 = g_kr[b + 32 + ip], kb1 = g_kr[b + 32 + ip + 1];
        if (i < 32) {
            q0 = qa0 * c0 - qb0 * s0;  q1 = qa1 * c1 - qb1 * s1;
            k0 = ka0 * c0 - kb0 * s0;  k1 = ka1 * c1 - kb1 * s1;
        } else {
            q0 = qa0 * s0 + qb0 * c0;  q1 = qa1 * s1 + qb1 * c1;
            k0 = ka0 * s0 + kb0 * c0;  k1 = ka1 * s1 + kb1 * c1;
        }
    }
    q0 *= SCALE_ATT; q1 *= SCALE_ATT;

    *(uint32_t*)(g_Q + o) = hf2pack(q0, q1);
    *(uint32_t*)(g_K + o) = hf2pack(k0, k1);
}

/* ------------------------------------------------------------------ */
/* fp16 tensor-core causal flash attention. Single-fp16 everywhere.    */
/* Double-buffered K/V tiles; smem [K0|V0|K1|V1] = 64KB.                */
/* ------------------------------------------------------------------ */
__device__ __forceinline__ uint32_t offV(int r, int c)
{ return (uint32_t)(((r << 4) + (c ^ (r & 7))) << 4); }   /* 16 chunks/row */

__global__ void __launch_bounds__(128) attn_mma()
{
    extern __shared__ char dsm[];
    const uint32_t sb = (uint32_t)__cvta_generic_to_shared(dsm);

    const int h    = blockIdx.y;
    const int qblk = 31 - (int)blockIdx.x;       /* long CTAs first */
    const int qb   = qblk << 6;
    const int tid  = threadIdx.x;
    const int lane = tid & 31;
    const int warp = tid >> 5;
    const int w16  = warp << 4;

    const __half* Qb = g_Q + (size_t)h * TSEQ * DHEAD;
    const __half* Kb = g_K + (size_t)h * TSEQ * DHEAD;
    const __half* Vb = g_V + (size_t)h * TSEQ * DHEAD;

    const int sr = tid >> 4;            /* 0..7  */
    const int sc = tid & 15;            /* 0..15 */

    /* ---- stage Q (64 rows) into buf0, LDSM into regs ---- */
#pragma unroll
    for (int p = 0; p < 8; p++) {
        const int r = sr + (p << 3);
        CPA16(sb + offV(r, sc), Qb + (size_t)(qb + r) * DHEAD + sc * 8);
    }
    CPA_COMMIT(); CPA_WAIT0();
    __syncthreads();

    uint32_t qf[8][4];
#pragma unroll
    for (int ks = 0; ks < 8; ks++) {
        const uint32_t ad = offV(w16 + (lane & 15), (ks << 1) + (lane >> 4));
        LDSM4(qf[ks][0], qf[ks][1], qf[ks][2], qf[ks][3], sb + ad);
    }
    __syncthreads();

    float O[16][4];
#pragma unroll
    for (int nt = 0; nt < 16; nt++)
#pragma unroll
        for (int i = 0; i < 4; i++) O[nt][i] = 0.f;
    float m0 = -1e30f, m1 = -1e30f, l0 = 0.f, l1 = 0.f;

    const int ntiles = qblk + 1;
    const int row0 = qb + w16 + (lane >> 2);
    const int row1 = row0 + 8;

    auto load_kv = [&](int b, int kt) {
        const int kb = kt << 6;
        const uint32_t s0 = sb + b * 32768;
#pragma unroll
        for (int p = 0; p < 8; p++) {
            const int r = sr + (p << 3);
            const size_t gi = (size_t)(kb + r) * DHEAD + sc * 8;
            const uint32_t so = offV(r, sc);
            CPA16(s0 + so,         Kb + gi);
            CPA16(s0 + 16384 + so, Vb + gi);
        }
    };

    load_kv(0, 0); CPA_COMMIT();

    for (int kt = 0; kt < ntiles; kt++) {
        const int kb = kt << 6;
        if (kt + 1 < ntiles) { load_kv((kt + 1) & 1, kt + 1); CPA_COMMIT(); }
        if (kt + 1 < ntiles) CPA_WAIT1(); else CPA_WAIT0();
        __syncthreads();

        const uint32_t kbase = sb + (kt & 1) * 32768;
        const uint32_t vbase = kbase + 16384;

        /* ---- scores S = Q K^T ---- */
        float S[8][4];
#pragma unroll
        for (int nt = 0; nt < 8; nt++)
#pragma unroll
            for (int i = 0; i < 4; i++) S[nt][i] = 0.f;

#pragma unroll
        for (int ntp = 0; ntp < 4; ntp++) {
#pragma unroll
            for (int ks = 0; ks < 8; ks++) {
                const uint32_t ad = offV((ntp << 4) + (lane & 15),
                                         (ks << 1) + (lane >> 4));
                uint32_t k0, k1, k2, k3;
                LDSM4(k0, k1, k2, k3, kbase + ad);
                MMA_F16(S[2 * ntp],     qf[ks], k0, k2);
                MMA_F16(S[2 * ntp + 1], qf[ks], k1, k3);
            }
        }

        /* ---- causal mask on diagonal tile ---- */
        if (kb == qb) {
#pragma unroll
            for (int nt = 0; nt < 8; nt++) {
                const int key = kb + (nt << 3) + ((lane & 3) << 1);
                if (key > row0)     S[nt][0] = -1e30f;
                if (key + 1 > row0) S[nt][1] = -1e30f;
                if (key > row1)     S[nt][2] = -1e30f;
                if (key + 1 > row1) S[nt][3] = -1e30f;
            }
        }

        /* ---- online softmax ---- */
        float mx0 = -1e30f, mx1 = -1e30f;
#pragma unroll
        for (int nt = 0; nt < 8; nt++) {
            mx0 = fmaxf(mx0, fmaxf(S[nt][0], S[nt][1]));
            mx1 = fmaxf(mx1, fmaxf(S[nt][2], S[nt][3]));
        }
        mx0 = fmaxf(mx0, __shfl_xor_sync(0xffffffffu, mx0, 1));
        mx0 = fmaxf(mx0, __shfl_xor_sync(0xffffffffu, mx0, 2));
        mx1 = fmaxf(mx1, __shfl_xor_sync(0xffffffffu, mx1, 1));
        mx1 = fmaxf(mx1, __shfl_xor_sync(0xffffffffu, mx1, 2));

        const float m0n = fmaxf(m0, mx0), m1n = fmaxf(m1, mx1);
        const float a0 = __expf(m0 - m0n), a1 = __expf(m1 - m1n);
        m0 = m0n; m1 = m1n;

        uint32_t aP[4][4];
        float ps0 = 0.f, ps1 = 0.f;
#pragma unroll
        for (int nt = 0; nt < 8; nt++) {
            const float p0 = __expf(S[nt][0] - m0n);
            const float p1 = __expf(S[nt][1] - m0n);
            const float p2 = __expf(S[nt][2] - m1n);
            const float p3 = __expf(S[nt][3] - m1n);
            ps0 += p0 + p1; ps1 += p2 + p3;
            const int kk = nt >> 1;
            const int e  = (nt & 1) << 1;
            aP[kk][e]     = hf2pack(p0, p1);
            aP[kk][e + 1] = hf2pack(p2, p3);
        }
        ps0 += __shfl_xor_sync(0xffffffffu, ps0, 1);
        ps0 += __shfl_xor_sync(0xffffffffu, ps0, 2);
        ps1 += __shfl_xor_sync(0xffffffffu, ps1, 1);
        ps1 += __shfl_xor_sync(0xffffffffu, ps1, 2);
        l0 = l0 * a0 + ps0;
        l1 = l1 * a1 + ps1;

#pragma unroll
        for (int nt = 0; nt < 16; nt++) {
            O[nt][0] *= a0; O[nt][1] *= a0;
            O[nt][2] *= a1; O[nt][3] *= a1;
        }

        /* ---- O += P V ---- */
#pragma unroll
        for (int kk = 0; kk < 4; kk++) {
#pragma unroll
            for (int ntp = 0; ntp < 8; ntp++) {
                const uint32_t ad = offV((kk << 4) + (lane & 15),
                                         (ntp << 1) + (lane >> 4));
                uint32_t v0, v1, v2, v3;
                LDSM4T(v0, v1, v2, v3, vbase + ad);
                MMA_F16(O[2 * ntp],     aP[kk], v0, v1);
                MMA_F16(O[2 * ntp + 1], aP[kk], v2, v3);
            }
        }
        __syncthreads();   /* guard buffer reuse */
    }

    /* ---- epilogue: normalize, write single fp16 [t][h*128+d] ---- */
    const float inv0 = 1.0f / l0, inv1 = 1.0f / l1;
#pragma unroll
    for (int nt = 0; nt < 16; nt++) {
        const int d = (nt << 3) + ((lane & 3) << 1);
        const float v0 = O[nt][0] * inv0, v1 = O[nt][1] * inv0;
        const float v2 = O[nt][2] * inv1, v3 = O[nt][3] * inv1;
        const size_t i0 = (size_t)row0 * DMODEL + h * DHEAD + d;
        const size_t i1 = (size_t)row1 * DMODEL + h * DHEAD + d;
        *(uint32_t*)(g_O + i0) = hf2pack(v0, v1);
        *(uint32_t*)(g_O + i1) = hf2pack(v2, v3);
    }
}

/* ------------------------------------------------------------------ */
extern "C" void kernel_launch(void* const* d_in, const int* in_sizes, int n_in,
                              void* d_out, int out_size)
{
    const float* x        = (const float*)d_in[0];
    const float* Wq_down  = (const float*)d_in[1];
    const float* Wq_up    = (const float*)d_in[2];
    const float* Wq_rope  = (const float*)d_in[3];
    const float* Wkv_down = (const float*)d_in[4];
    const float* Wk_up    = (const float*)d_in[5];
    const float* Wv_up    = (const float*)d_in[6];
    const float* Wk_rope  = (const float*)d_in[7];
    const float* Wo       = (const float*)d_in[8];
    float* out = (float*)d_out;

    float *qc, *qr, *kc, *kr;
    cudaGetSymbolAddress((void**)&qc, g_qc);
    cudaGetSymbolAddress((void**)&qr, g_qr);
    cudaGetSymbolAddress((void**)&kc, g_kc);
    cudaGetSymbolAddress((void**)&kr, g_kr);

    __half *xf, *qdh, *qdl, *kvh, *kvl, *Of, *Vf;
    __half *wqd, *wqu, *wqr, *wkd, *wku, *wvu, *wkr, *wo;
    cudaGetSymbolAddress((void**)&xf, g_x);
    cudaGetSymbolAddress((void**)&qdh, g_qdh); cudaGetSymbolAddress((void**)&qdl, g_qdl);
    cudaGetSymbolAddress((void**)&kvh, g_kvh); cudaGetSymbolAddress((void**)&kvl, g_kvl);
    cudaGetSymbolAddress((void**)&Of, g_O);
    cudaGetSymbolAddress((void**)&Vf, g_V);
    cudaGetSymbolAddress((void**)&wqd, g_wqd); cudaGetSymbolAddress((void**)&wqu, g_wqu);
    cudaGetSymbolAddress((void**)&wqr, g_wqr); cudaGetSymbolAddress((void**)&wkd, g_wkd);
    cudaGetSymbolAddress((void**)&wku, g_wku); cudaGetSymbolAddress((void**)&wvu, g_wvu);
    cudaGetSymbolAddress((void**)&wkr, g_wkr); cudaGetSymbolAddress((void**)&wo,  g_wo);

    cudaFuncSetAttribute(gemm_fused<true>,
                         cudaFuncAttributeMaxDynamicSharedMemorySize, 49152);
    cudaFuncSetAttribute(gemm_fused<false>,
                         cudaFuncAttributeMaxDynamicSharedMemorySize, 49152);
    cudaFuncSetAttribute(attn_mma,
                         cudaFuncAttributeMaxDynamicSharedMemorySize, 65536);

    /* 0. rope table */
    rope_table<<<256, 256>>>();

    /* 1. convert x + weights to fp16 */
    SplitJobs js;
    js.j[0] = { x,        xf,  TSEQ * 2048 };
    js.j[1] = { Wq_down,  wqd, 2048 * 512  };
    js.j[2] = { Wq_up,    wqu, 512 * 1024  };
    js.j[3] = { Wq_rope,  wqr, 2048 * 1024 };
    js.j[4] = { Wkv_down, wkd, 2048 * 512  };
    js.j[5] = { Wk_up,    wku, 512 * 1024  };
    js.j[6] = { Wv_up,    wvu, 512 * 2048  };
    js.j[7] = { Wk_rope,  wkr, 2048 * 1024 };
    js.j[8] = { Wo,       wo,  2048 * 2048 };
    split_many<<<dim3(4096, 9), 256>>>(js);

    /* 2. GEMM1 (single-A): x @ [Wq_down | Wkv_down | Wq_rope | Wk_rope] */
    {
        GSegs g; g.n = 4;
        g.s[0] = { xf, nullptr, 2048, wqd, nullptr, qdh, qdl,  512, 2048, 0,  0 };
        g.s[1] = { xf, nullptr, 2048, wkd, nullptr, kvh, kvl,  512, 2048, 4,  0 };
        g.s[2] = { xf, nullptr, 2048, wqr, qr, nullptr, nullptr, 1024, 2048, 8,  0 };
        g.s[3] = { xf, nullptr, 2048, wkr, kr, nullptr, nullptr, 1024, 2048, 16, 0 };
        gemm_fused<false><<<dim3(24, 16), 256, 49152>>>(g);
    }

    /* 3. GEMM2 (split-A): qd @ Wq_up ; kv @ [Wk_up | Wv_up (-> V perm)] */
    {
        GSegs g; g.n = 3;
        g.s[0] = { qdh, qdl, 512, wqu, qc, nullptr, nullptr, 1024, 512, 0,  0 };
        g.s[1] = { kvh, kvl, 512, wku, kc, nullptr, nullptr, 1024, 512, 8,  0 };
        g.s[2] = { kvh, kvl, 512, wvu, nullptr, Vf, nullptr, 2048, 512, 16, 1 };
        g.s[3] = g.s[0];
        gemm_fused<true><<<dim3(32, 16), 256, 49152>>>(g);
    }

    /* 4. rope + pack Q/K (single fp16) */
    pack_kernel<<<dim3(TSEQ, NH), 64>>>();

    /* 5. fp16 tensor-core causal attention */
    attn_mma<<<dim3(32, NH), 128, 65536>>>();

    /* 6. GEMM3 (single-A): O @ Wo -> out */
    {
        GSegs g; g.n = 1;
        g.s[0] = { Of, nullptr, 2048, wo, out, nullptr, nullptr, 2048, 2048, 0, 0 };
        g.s[1] = g.s[0]; g.s[2] = g.s[0]; g.s[3] = g.s[0];
        gemm_fused<false><<<dim3(16, 16), 256, 49152>>>(g);
    }
}

// round 15
// speedup vs baseline: 2.0543x; 1.0585x over previous
#include <cuda_runtime.h>
#include <cuda_bf16.h>
#include <cuda_fp16.h>
#include <math.h>
#include <stdint.h>

#define TSEQ   2048
#define DMODEL 2048
#define NH     16
#define DHEAD  128
#define DROPE  64
#define DCONT  64
#define SCALE_ATT 0.08838834764831845f  /* 1/sqrt(128) */

/* ------------------------------------------------------------------ */
/* Scratch (device globals)                                            */
/* ------------------------------------------------------------------ */
__device__ float g_qc[TSEQ * 1024];
__device__ float g_qr[TSEQ * 1024];
__device__ float g_kc[TSEQ * 1024];
__device__ float g_kr[TSEQ * 1024];
__device__ float g_cosT[TSEQ * 32];
__device__ float g_sinT[TSEQ * 32];

/* attention operands (fp16), [h][t][d] */
__device__ __half g_Q[NH * TSEQ * DHEAD];
__device__ __half g_K[NH * TSEQ * DHEAD];
__device__ __half g_V[NH * TSEQ * DHEAD];

/* fp16 GEMM operands */
__device__ __half g_x [TSEQ * 2048];
__device__ __half g_qdh[TSEQ * 512],  g_qdl[TSEQ * 512];
__device__ __half g_kvh[TSEQ * 512],  g_kvl[TSEQ * 512];
__device__ __half g_O [TSEQ * 2048];
__device__ __half g_wqd[2048 * 512];
__device__ __half g_wqu[512 * 1024];
__device__ __half g_wqr[2048 * 1024];
__device__ __half g_wkd[2048 * 512];
__device__ __half g_wku[512 * 1024];
__device__ __half g_wvu[512 * 2048];
__device__ __half g_wkr[2048 * 1024];
__device__ __half g_wo [2048 * 2048];

/* ------------------------------------------------------------------ */
/* asm helpers                                                         */
/* ------------------------------------------------------------------ */
#define CPA16(dst, src)                                                    \
    asm volatile("cp.async.cg.shared.global [%0], [%1], 16;"               \
                 :: "r"(dst), "l"(src))
#define CPA_COMMIT() asm volatile("cp.async.commit_group;")
#define CPA_WAIT1()  asm volatile("cp.async.wait_group 1;")
#define CPA_WAIT0()  asm volatile("cp.async.wait_group 0;")

#define LDSM4(r0, r1, r2, r3, addr)                                        \
    asm volatile("ldmatrix.sync.aligned.m8n8.x4.shared.b16 {%0,%1,%2,%3}, [%4];" \
                 : "=r"(r0), "=r"(r1), "=r"(r2), "=r"(r3) : "r"(addr))
#define LDSM4T(r0, r1, r2, r3, addr)                                       \
    asm volatile("ldmatrix.sync.aligned.m8n8.x4.trans.shared.b16 {%0,%1,%2,%3}, [%4];" \
                 : "=r"(r0), "=r"(r1), "=r"(r2), "=r"(r3) : "r"(addr))
#define MMA_F16(c, a, b0, b1)                                              \
    asm volatile("mma.sync.aligned.m16n8k16.row.col.f32.f16.f16.f32 "      \
                 "{%0,%1,%2,%3}, {%4,%5,%6,%7}, {%8,%9}, {%0,%1,%2,%3};"   \
                 : "+f"(c[0]), "+f"(c[1]), "+f"(c[2]), "+f"(c[3])          \
                 : "r"(a[0]), "r"(a[1]), "r"(a[2]), "r"(a[3]),             \
                   "r"(b0), "r"(b1))

__device__ __forceinline__ uint32_t hf2pack(float a, float b)
{
    return (uint32_t)__half_as_ushort(__float2half_rn(a)) |
           ((uint32_t)__half_as_ushort(__float2half_rn(b)) << 16);
}

/* ------------------------------------------------------------------ */
/* RoPE table                                                          */
/* ------------------------------------------------------------------ */
__global__ void __launch_bounds__(256) rope_table()
{
    const int idx = blockIdx.x * 256 + threadIdx.x;
    if (idx >= TSEQ * 32) return;
    const int t = idx >> 5, i = idx & 31;
    const double inv = pow(10000.0, -(double)i / 32.0);
    double sd, cd;
    sincos((double)t * inv, &sd, &cd);
    g_cosT[idx] = (float)cd;
    g_sinT[idx] = (float)sd;
}

/* ------------------------------------------------------------------ */
/* Batched fp32 -> fp16                                                */
/* ------------------------------------------------------------------ */
struct SplitJob { const float* src; __half *h; int n; };
struct SplitJobs { SplitJob j[9]; };

__global__ void __launch_bounds__(256) split_many(SplitJobs js)
{
    const SplitJob J = js.j[blockIdx.y];
    const int i = (blockIdx.x * 256 + threadIdx.x) << 2;
    if (i >= J.n) return;
    float4 v = *(const float4*)(J.src + i);
    uint2 hp;
    hp.x = hf2pack(v.x, v.y);  hp.y = hf2pack(v.z, v.w);
    *(uint2*)(J.h + i) = hp;
}

/* ------------------------------------------------------------------ */
/* Fused multi-segment fp16 tensor-core GEMM, BK=64.                   */
/* HASLO=1: C = (Ah+Al) @ B; HASLO=0: C = Ah @ B.                      */
/* BM=BN=128, 256 threads, 2-stage cp.async, 2 CTAs/SM.                */
/* stage: A 16KB [+ Alo 16KB] + B 16KB.                                */
/* ------------------------------------------------------------------ */
struct GSeg {
    const __half *Ah, *Al;
    int lda;
    const __half *Bh;
    float* Cf;
    void *Ch, *Cl;
    int N, K, tile0, vperm;
};
struct GSegs { GSeg s[4]; int n; };

/* A tile: 128 rows x 8 chunks(16B) = 128x64 fp16 */
__device__ __forceinline__ uint32_t offA64(int r, int c)
{ return (uint32_t)(((r << 3) + (c ^ (r & 7))) << 4); }
/* B tile: 64 rows x 16 chunks(16B) = 64x128 fp16 */
__device__ __forceinline__ uint32_t offB16(int r, int c)
{ return (uint32_t)(((r << 4) + (c ^ (r & 7))) << 4); }

template<bool HASLO>
__global__ void __launch_bounds__(256, 2) gemm_fused(GSegs segs)
{
    constexpr uint32_t A_LO  = 16384;
    constexpr uint32_t B_OFF = HASLO ? 32768 : 16384;
    constexpr uint32_t STAGE = HASLO ? 49152 : 32768;

    extern __shared__ char dsm[];
    const uint32_t sb = (uint32_t)__cvta_generic_to_shared(dsm);

    const int tid  = threadIdx.x;
    const int lane = tid & 31;
    const int warp = tid >> 5;
    const int wm   = (warp >> 1) << 5;
    const int wn   = (warp & 1) << 6;
    const int bm   = blockIdx.y << 7;

    GSeg sg = segs.s[0];
#pragma unroll
    for (int i = 1; i < 4; i++)
        if (i < segs.n && (int)blockIdx.x >= segs.s[i].tile0) sg = segs.s[i];
    const int bn  = ((int)blockIdx.x - sg.tile0) << 7;
    const int lda = sg.lda, ldb = sg.N, K = sg.K;

    /* staging: A 32 rows/pass x 8 chunks (4 passes);
       B 16 rows/pass x 16 chunks (4 passes) */
    const int ar = tid >> 3, ac = tid & 7;
    const int br = tid >> 4, bc = tid & 15;

    const __half* gAh = sg.Ah + (size_t)(bm + ar) * lda + ac * 8;
    const __half* gAl = HASLO ? sg.Al + (size_t)(bm + ar) * lda + ac * 8 : nullptr;
    const __half* gBh = sg.Bh + (size_t)br * ldb + bn + bc * 8;

    float acc[2][8][4];
#pragma unroll
    for (int mt = 0; mt < 2; mt++)
#pragma unroll
        for (int nt = 0; nt < 8; nt++)
#pragma unroll
            for (int i = 0; i < 4; i++) acc[mt][nt][i] = 0.f;

    const int nk = K >> 6;

    auto load_stage = [&](int st, int k0) {
        const uint32_t s0 = sb + st * STAGE;
        const __half* pAh = gAh + k0;
#pragma unroll
        for (int p = 0; p < 4; p++) {
            const uint32_t ao = offA64(ar + (p << 5), ac);
            CPA16(s0 + ao, pAh + (size_t)(p << 5) * lda);
            if (HASLO)
                CPA16(s0 + A_LO + ao, gAl + k0 + (size_t)(p << 5) * lda);
        }
        const __half* pBh = gBh + (size_t)k0 * ldb;
#pragma unroll
        for (int p = 0; p < 4; p++) {
            const uint32_t bo = offB16(br + (p << 4), bc);
            CPA16(s0 + B_OFF + bo, pBh + (size_t)(p << 4) * ldb);
        }
    };

    load_stage(0, 0);
    CPA_COMMIT();

    for (int it = 0; it < nk; it++) {
        if (it + 1 < nk) { load_stage((it + 1) & 1, (it + 1) << 6); CPA_COMMIT(); }
        if (it + 1 < nk) CPA_WAIT1(); else CPA_WAIT0();
        __syncthreads();

        const uint32_t s0 = sb + (it & 1) * STAGE;
#pragma unroll
        for (int ks = 0; ks < 4; ks++) {
            uint32_t ah[2][4], al_[2][4];
#pragma unroll
            for (int mt = 0; mt < 2; mt++) {
                const int rowA   = wm + (mt << 4) + (lane & 15);
                const int chunkA = (ks << 1) + (lane >> 4);
                const uint32_t ad = s0 + offA64(rowA, chunkA);
                LDSM4(ah[mt][0], ah[mt][1], ah[mt][2], ah[mt][3], ad);
                if (HASLO)
                    LDSM4(al_[mt][0], al_[mt][1], al_[mt][2], al_[mt][3],
                          ad + A_LO);
            }
#pragma unroll
            for (int np = 0; np < 4; np++) {
                const int rowB   = (ks << 4) + (lane & 15);
                const int chunkB = (wn >> 3) + (lane >> 4) + (np << 1);
                const uint32_t bd = s0 + B_OFF + offB16(rowB, chunkB);
                uint32_t h0, h1, h2, h3;
                LDSM4T(h0, h1, h2, h3, bd);
#pragma unroll
                for (int mt = 0; mt < 2; mt++) {
                    MMA_F16(acc[mt][2 * np],     ah[mt],  h0, h1);
                    MMA_F16(acc[mt][2 * np + 1], ah[mt],  h2, h3);
                    if (HASLO) {
                        MMA_F16(acc[mt][2 * np],     al_[mt], h0, h1);
                        MMA_F16(acc[mt][2 * np + 1], al_[mt], h2, h3);
                    }
                }
            }
        }
        __syncthreads();
    }

    const int erow = lane >> 2;
    const int ecol = (lane & 3) << 1;
    if (sg.Cf) {
#pragma unroll
        for (int mt = 0; mt < 2; mt++)
#pragma unroll
            for (int nt = 0; nt < 8; nt++) {
                const int r = bm + wm + (mt << 4) + erow;
                const int c = bn + wn + (nt << 3) + ecol;
                *(float2*)(sg.Cf + (size_t)r * ldb + c) =
                    make_float2(acc[mt][nt][0], acc[mt][nt][1]);
                *(float2*)(sg.Cf + (size_t)(r + 8) * ldb + c) =
                    make_float2(acc[mt][nt][2], acc[mt][nt][3]);
            }
    } else if (sg.vperm) {
        __half* Ch = (__half*)sg.Ch;
#pragma unroll
        for (int mt = 0; mt < 2; mt++)
#pragma unroll
            for (int nt = 0; nt < 8; nt++) {
                const int r = bm + wm + (mt << 4) + erow;
                const int c = bn + wn + (nt << 3) + ecol;
#pragma unroll
                for (int hh = 0; hh < 2; hh++) {
                    const float v0 = acc[mt][nt][2 * hh];
                    const float v1 = acc[mt][nt][2 * hh + 1];
                    const int rr = r + 8 * hh;
                    const size_t idx =
                        ((size_t)(c >> 7) * TSEQ + rr) * DHEAD + (c & 127);
                    *(uint32_t*)(Ch + idx) = hf2pack(v0, v1);
                }
            }
    } else {
        __half* Ch = (__half*)sg.Ch;
        __half* Cl = (__half*)sg.Cl;
#pragma unroll
        for (int mt = 0; mt < 2; mt++)
#pragma unroll
            for (int nt = 0; nt < 8; nt++) {
                const int r = bm + wm + (mt << 4) + erow;
                const int c = bn + wn + (nt << 3) + ecol;
#pragma unroll
                for (int hh = 0; hh < 2; hh++) {
                    const float v0 = acc[mt][nt][2 * hh];
                    const float v1 = acc[mt][nt][2 * hh + 1];
                    const float h0 = __half2float(__float2half_rn(v0));
                    const float h1 = __half2float(__float2half_rn(v1));
                    const size_t idx = (size_t)(r + 8 * hh) * ldb + c;
                    *(uint32_t*)(Ch + idx) = hf2pack(v0, v1);
                    *(uint32_t*)(Cl + idx) = hf2pack(v0 - h0, v1 - h1);
                }
            }
    }
}

/* ------------------------------------------------------------------ */
/* Pack + RoPE -> Q (pre-scaled) / K, single fp16 in [h][t][d].        */
/* ------------------------------------------------------------------ */
__global__ void __launch_bounds__(64) pack_kernel()
{
    const int t = blockIdx.x;
    const int h = blockIdx.y;
    const int d2 = threadIdx.x << 1;
    const size_t o = ((size_t)h * TSEQ + t) * DHEAD + d2;

    float q0, q1, k0, k1;
    if (d2 < DCONT) {
        const size_t b = (size_t)t * 1024 + h * DCONT + d2;
        q0 = g_qc[b];     q1 = g_qc[b + 1];
        k0 = g_kc[b];     k1 = g_kc[b + 1];
    } else {
        const int i = d2 - DCONT;
        const int ip = (i < 32) ? i : i - 32;
        const float c0 = g_cosT[t * 32 + ip],     s0 = g_sinT[t * 32 + ip];
        const float c1 = g_cosT[t * 32 + ip + 1], s1 = g_sinT[t * 32 + ip + 1];
        const size_t b = (size_t)t * 1024 + h * DROPE;
        const float qa0 = g_qr[b + ip],      qa1 = g_qr[b + ip + 1];
        const float qb0 = g_qr[b + 32 + ip], qb1 = g_qr[b + 32 + ip + 1];
        const float ka0 = g_kr[b + ip],      ka1 = g_kr[b + ip + 1];
        const float kb0 = g_kr[b + 32 + ip], kb1 = g_kr[b + 32 + ip + 1];
        if (i < 32) {
            q0 = qa0 * c0 - qb0 * s0;  q1 = qa1 * c1 - qb1 * s1;
            k0 = ka0 * c0 - kb0 * s0;  k1 = ka1 * c1 - kb1 * s1;
        } else {
            q0 = qa0 * s0 + qb0 * c0;  q1 = qa1 * s1 + qb1 * c1;
            k0 = ka0 * s0 + kb0 * c0;  k1 = ka1 * s1 + kb1 * c1;
        }
    }
    q0 *= SCALE_ATT; q1 *= SCALE_ATT;

    *(uint32_t*)(g_Q + o) = hf2pack(q0, q1);
    *(uint32_t*)(g_K + o) = hf2pack(k0, k1);
}

/* ------------------------------------------------------------------ */
/* fp16 tensor-core causal flash attention (unchanged from R14).       */
/* ------------------------------------------------------------------ */
__device__ __forceinline__ uint32_t offV(int r, int c)
{ return (uint32_t)(((r << 4) + (c ^ (r & 7))) << 4); }

__global__ void __launch_bounds__(128) attn_mma()
{
    extern __shared__ char dsm[];
    const uint32_t sb = (uint32_t)__cvta_generic_to_shared(dsm);

    const int h    = blockIdx.y;
    const int qblk = 31 - (int)blockIdx.x;
    const int qb   = qblk << 6;
    const int tid  = threadIdx.x;
    const int lane = tid & 31;
    const int warp = tid >> 5;
    const int w16  = warp << 4;

    const __half* Qb = g_Q + (size_t)h * TSEQ * DHEAD;
    const __half* Kb = g_K + (size_t)h * TSEQ * DHEAD;
    const __half* Vb = g_V + (size_t)h * TSEQ * DHEAD;

    const int sr = tid >> 4;
    const int sc = tid & 15;

#pragma unroll
    for (int p = 0; p < 8; p++) {
        const int r = sr + (p << 3);
        CPA16(sb + offV(r, sc), Qb + (size_t)(qb + r) * DHEAD + sc * 8);
    }
    CPA_COMMIT(); CPA_WAIT0();
    __syncthreads();

    uint32_t qf[8][4];
#pragma unroll
    for (int ks = 0; ks < 8; ks++) {
        const uint32_t ad = offV(w16 + (lane & 15), (ks << 1) + (lane >> 4));
        LDSM4(qf[ks][0], qf[ks][1], qf[ks][2], qf[ks][3], sb + ad);
    }
    __syncthreads();

    float O[16][4];
#pragma unroll
    for (int nt = 0; nt < 16; nt++)
#pragma unroll
        for (int i = 0; i < 4; i++) O[nt][i] = 0.f;
    float m0 = -1e30f, m1 = -1e30f, l0 = 0.f, l1 = 0.f;

    const int ntiles = qblk + 1;
    const int row0 = qb + w16 + (lane >> 2);
    const int row1 = row0 + 8;

    auto load_kv = [&](int b, int kt) {
        const int kb = kt << 6;
        const uint32_t s0 = sb + b * 32768;
#pragma unroll
        for (int p = 0; p < 8; p++) {
            const int r = sr + (p << 3);
            const size_t gi = (size_t)(kb + r) * DHEAD + sc * 8;
            const uint32_t so = offV(r, sc);
            CPA16(s0 + so,         Kb + gi);
            CPA16(s0 + 16384 + so, Vb + gi);
        }
    };

    load_kv(0, 0); CPA_COMMIT();

    for (int kt = 0; kt < ntiles; kt++) {
        const int kb = kt << 6;
        if (kt + 1 < ntiles) { load_kv((kt + 1) & 1, kt + 1); CPA_COMMIT(); }
        if (kt + 1 < ntiles) CPA_WAIT1(); else CPA_WAIT0();
        __syncthreads();

        const uint32_t kbase = sb + (kt & 1) * 32768;
        const uint32_t vbase = kbase + 16384;

        float S[8][4];
#pragma unroll
        for (int nt = 0; nt < 8; nt++)
#pragma unroll
            for (int i = 0; i < 4; i++) S[nt][i] = 0.f;

#pragma unroll
        for (int ntp = 0; ntp < 4; ntp++) {
#pragma unroll
            for (int ks = 0; ks < 8; ks++) {
                const uint32_t ad = offV((ntp << 4) + (lane & 15),
                                         (ks << 1) + (lane >> 4));
                uint32_t k0, k1, k2, k3;
                LDSM4(k0, k1, k2, k3, kbase + ad);
                MMA_F16(S[2 * ntp],     qf[ks], k0, k2);
                MMA_F16(S[2 * ntp + 1], qf[ks], k1, k3);
            }
        }

        if (kb == qb) {
#pragma unroll
            for (int nt = 0; nt < 8; nt++) {
                const int key = kb + (nt << 3) + ((lane & 3) << 1);
                if (key > row0)     S[nt][0] = -1e30f;
                if (key + 1 > row0) S[nt][1] = -1e30f;
                if (key > row1)     S[nt][2] = -1e30f;
                if (key + 1 > row1) S[nt][3] = -1e30f;
            }
        }

        float mx0 = -1e30f, mx1 = -1e30f;
#pragma unroll
        for (int nt = 0; nt < 8; nt++) {
            mx0 = fmaxf(mx0, fmaxf(S[nt][0], S[nt][1]));
            mx1 = fmaxf(mx1, fmaxf(S[nt][2], S[nt][3]));
        }
        mx0 = fmaxf(mx0, __shfl_xor_sync(0xffffffffu, mx0, 1));
        mx0 = fmaxf(mx0, __shfl_xor_sync(0xffffffffu, mx0, 2));
        mx1 = fmaxf(mx1, __shfl_xor_sync(0xffffffffu, mx1, 1));
        mx1 = fmaxf(mx1, __shfl_xor_sync(0xffffffffu, mx1, 2));

        const float m0n = fmaxf(m0, mx0), m1n = fmaxf(m1, mx1);
        const float a0 = __expf(m0 - m0n), a1 = __expf(m1 - m1n);
        m0 = m0n; m1 = m1n;

        uint32_t aP[4][4];
        float ps0 = 0.f, ps1 = 0.f;
#pragma unroll
        for (int nt = 0; nt < 8; nt++) {
            const float p0 = __expf(S[nt][0] - m0n);
            const float p1 = __expf(S[nt][1] - m0n);
            const float p2 = __expf(S[nt][2] - m1n);
            const float p3 = __expf(S[nt][3] - m1n);
            ps0 += p0 + p1; ps1 += p2 + p3;
            const int kk = nt >> 1;
            const int e  = (nt & 1) << 1;
            aP[kk][e]     = hf2pack(p0, p1);
            aP[kk][e + 1] = hf2pack(p2, p3);
        }
        ps0 += __shfl_xor_sync(0xffffffffu, ps0, 1);
        ps0 += __shfl_xor_sync(0xffffffffu, ps0, 2);
        ps1 += __shfl_xor_sync(0xffffffffu, ps1, 1);
        ps1 += __shfl_xor_sync(0xffffffffu, ps1, 2);
        l0 = l0 * a0 + ps0;
        l1 = l1 * a1 + ps1;

#pragma unroll
        for (int nt = 0; nt < 16; nt++) {
            O[nt][0] *= a0; O[nt][1] *= a0;
            O[nt][2] *= a1; O[nt][3] *= a1;
        }

#pragma unroll
        for (int kk = 0; kk < 4; kk++) {
#pragma unroll
            for (int ntp = 0; ntp < 8; ntp++) {
                const uint32_t ad = offV((kk << 4) + (lane & 15),
                                         (ntp << 1) + (lane >> 4));
                uint32_t v0, v1, v2, v3;
                LDSM4T(v0, v1, v2, v3, vbase + ad);
                MMA_F16(O[2 * ntp],     aP[kk], v0, v1);
                MMA_F16(O[2 * ntp + 1], aP[kk], v2, v3);
            }
        }
        __syncthreads();
    }

    const float inv0 = 1.0f / l0, inv1 = 1.0f / l1;
#pragma unroll
    for (int nt = 0; nt < 16; nt++) {
        const int d = (nt << 3) + ((lane & 3) << 1);
        const float v0 = O[nt][0] * inv0, v1 = O[nt][1] * inv0;
        const float v2 = O[nt][2] * inv1, v3 = O[nt][3] * inv1;
        const size_t i0 = (size_t)row0 * DMODEL + h * DHEAD + d;
        const size_t i1 = (size_t)row1 * DMODEL + h * DHEAD + d;
        *(uint32_t*)(g_O + i0) = hf2pack(v0, v1);
        *(uint32_t*)(g_O + i1) = hf2pack(v2, v3);
    }
}

/* ------------------------------------------------------------------ */
extern "C" void kernel_launch(void* const* d_in, const int* in_sizes, int n_in,
                              void* d_out, int out_size)
{
    const float* x        = (const float*)d_in[0];
    const float* Wq_down  = (const float*)d_in[1];
    const float* Wq_up    = (const float*)d_in[2];
    const float* Wq_rope  = (const float*)d_in[3];
    const float* Wkv_down = (const float*)d_in[4];
    const float* Wk_up    = (const float*)d_in[5];
    const float* Wv_up    = (const float*)d_in[6];
    const float* Wk_rope  = (const float*)d_in[7];
    const float* Wo       = (const float*)d_in[8];
    float* out = (float*)d_out;

    float *qc, *qr, *kc, *kr;
    cudaGetSymbolAddress((void**)&qc, g_qc);
    cudaGetSymbolAddress((void**)&qr, g_qr);
    cudaGetSymbolAddress((void**)&kc, g_kc);
    cudaGetSymbolAddress((void**)&kr, g_kr);

    __half *xf, *qdh, *qdl, *kvh, *kvl, *Of, *Vf;
    __half *wqd, *wqu, *wqr, *wkd, *wku, *wvu, *wkr, *wo;
    cudaGetSymbolAddress((void**)&xf, g_x);
    cudaGetSymbolAddress((void**)&qdh, g_qdh); cudaGetSymbolAddress((void**)&qdl, g_qdl);
    cudaGetSymbolAddress((void**)&kvh, g_kvh); cudaGetSymbolAddress((void**)&kvl, g_kvl);
    cudaGetSymbolAddress((void**)&Of, g_O);
    cudaGetSymbolAddress((void**)&Vf, g_V);
    cudaGetSymbolAddress((void**)&wqd, g_wqd); cudaGetSymbolAddress((void**)&wqu, g_wqu);
    cudaGetSymbolAddress((void**)&wqr, g_wqr); cudaGetSymbolAddress((void**)&wkd, g_wkd);
    cudaGetSymbolAddress((void**)&wku, g_wku); cudaGetSymbolAddress((void**)&wvu, g_wvu);
    cudaGetSymbolAddress((void**)&wkr, g_wkr); cudaGetSymbolAddress((void**)&wo,  g_wo);

    cudaFuncSetAttribute(gemm_fused<true>,
                         cudaFuncAttributeMaxDynamicSharedMemorySize, 98304);
    cudaFuncSetAttribute(gemm_fused<false>,
                         cudaFuncAttributeMaxDynamicSharedMemorySize, 65536);
    cudaFuncSetAttribute(attn_mma,
                         cudaFuncAttributeMaxDynamicSharedMemorySize, 65536);

    /* 0. rope table */
    rope_table<<<256, 256>>>();

    /* 1. convert x + weights to fp16 */
    SplitJobs js;
    js.j[0] = { x,        xf,  TSEQ * 2048 };
    js.j[1] = { Wq_down,  wqd, 2048 * 512  };
    js.j[2] = { Wq_up,    wqu, 512 * 1024  };
    js.j[3] = { Wq_rope,  wqr, 2048 * 1024 };
    js.j[4] = { Wkv_down, wkd, 2048 * 512  };
    js.j[5] = { Wk_up,    wku, 512 * 1024  };
    js.j[6] = { Wv_up,    wvu, 512 * 2048  };
    js.j[7] = { Wk_rope,  wkr, 2048 * 1024 };
    js.j[8] = { Wo,       wo,  2048 * 2048 };
    split_many<<<dim3(4096, 9), 256>>>(js);

    /* 2. GEMM1 (single-A, BK=64) */
    {
        GSegs g; g.n = 4;
        g.s[0] = { xf, nullptr, 2048, wqd, nullptr, qdh, qdl,  512, 2048, 0,  0 };
        g.s[1] = { xf, nullptr, 2048, wkd, nullptr, kvh, kvl,  512, 2048, 4,  0 };
        g.s[2] = { xf, nullptr, 2048, wqr, qr, nullptr, nullptr, 1024, 2048, 8,  0 };
        g.s[3] = { xf, nullptr, 2048, wkr, kr, nullptr, nullptr, 1024, 2048, 16, 0 };
        gemm_fused<false><<<dim3(24, 16), 256, 65536>>>(g);
    }

    /* 3. GEMM2 (split-A, BK=64) */
    {
        GSegs g; g.n = 3;
        g.s[0] = { qdh, qdl, 512, wqu, qc, nullptr, nullptr, 1024, 512, 0,  0 };
        g.s[1] = { kvh, kvl, 512, wku, kc, nullptr, nullptr, 1024, 512, 8,  0 };
        g.s[2] = { kvh, kvl, 512, wvu, nullptr, Vf, nullptr, 2048, 512, 16, 1 };
        g.s[3] = g.s[0];
        gemm_fused<true><<<dim3(32, 16), 256, 98304>>>(g);
    }

    /* 4. rope + pack Q/K */
    pack_kernel<<<dim3(TSEQ, NH), 64>>>();

    /* 5. fp16 tensor-core causal attention */
    attn_mma<<<dim3(32, NH), 128, 65536>>>();

    /* 6. GEMM3 (single-A, BK=64) */
    {
        GSegs g; g.n = 1;
        g.s[0] = { Of, nullptr, 2048, wo, out, nullptr, nullptr, 2048, 2048, 0, 0 };
        g.s[1] = g.s[0]; g.s[2] = g.s[0]; g.s[3] = g.s[0];
        gemm_fused<false><<<dim3(16, 16), 256, 65536>>>(g);
    }
}

// round 16
// speedup vs baseline: 2.1023x; 1.0233x over previous
#include <cuda_runtime.h>
#include <cuda_bf16.h>
#include <cuda_fp16.h>
#include <math.h>
#include <stdint.h>

#define TSEQ   2048
#define DMODEL 2048
#define NH     16
#define DHEAD  128
#define DROPE  64
#define DCONT  64
#define SCALE_ATT 0.08838834764831845f  /* 1/sqrt(128) */

/* ------------------------------------------------------------------ */
/* Scratch (device globals)                                            */
/* ------------------------------------------------------------------ */
__device__ float g_cosT[TSEQ * 32];
__device__ float g_sinT[TSEQ * 32];

/* attention operands (fp16), [h][t][d] */
__device__ __half g_Q[NH * TSEQ * DHEAD];
__device__ __half g_K[NH * TSEQ * DHEAD];
__device__ __half g_V[NH * TSEQ * DHEAD];

/* fp16 GEMM operands */
__device__ __half g_x [TSEQ * 2048];
__device__ __half g_qdh[TSEQ * 512],  g_qdl[TSEQ * 512];
__device__ __half g_kvh[TSEQ * 512],  g_kvl[TSEQ * 512];
__device__ __half g_O [TSEQ * 2048];
__device__ __half g_wqd[2048 * 512];
__device__ __half g_wqu[512 * 1024];
__device__ __half g_wqr[2048 * 1024];
__device__ __half g_wkd[2048 * 512];
__device__ __half g_wku[512 * 1024];
__device__ __half g_wvu[512 * 2048];
__device__ __half g_wkr[2048 * 1024];
__device__ __half g_wo [2048 * 2048];

/* ------------------------------------------------------------------ */
/* asm helpers                                                         */
/* ------------------------------------------------------------------ */
#define CPA16(dst, src)                                                    \
    asm volatile("cp.async.cg.shared.global [%0], [%1], 16;"               \
                 :: "r"(dst), "l"(src))
#define CPA_COMMIT() asm volatile("cp.async.commit_group;")
#define CPA_WAIT2()  asm volatile("cp.async.wait_group 2;")
#define CPA_WAIT1()  asm volatile("cp.async.wait_group 1;")
#define CPA_WAIT0()  asm volatile("cp.async.wait_group 0;")

#define LDSM4(r0, r1, r2, r3, addr)                                        \
    asm volatile("ldmatrix.sync.aligned.m8n8.x4.shared.b16 {%0,%1,%2,%3}, [%4];" \
                 : "=r"(r0), "=r"(r1), "=r"(r2), "=r"(r3) : "r"(addr))
#define LDSM4T(r0, r1, r2, r3, addr)                                       \
    asm volatile("ldmatrix.sync.aligned.m8n8.x4.trans.shared.b16 {%0,%1,%2,%3}, [%4];" \
                 : "=r"(r0), "=r"(r1), "=r"(r2), "=r"(r3) : "r"(addr))
#define MMA_F16(c, a, b0, b1)                                              \
    asm volatile("mma.sync.aligned.m16n8k16.row.col.f32.f16.f16.f32 "      \
                 "{%0,%1,%2,%3}, {%4,%5,%6,%7}, {%8,%9}, {%0,%1,%2,%3};"   \
                 : "+f"(c[0]), "+f"(c[1]), "+f"(c[2]), "+f"(c[3])          \
                 : "r"(a[0]), "r"(a[1]), "r"(a[2]), "r"(a[3]),             \
                   "r"(b0), "r"(b1))

__device__ __forceinline__ uint32_t hf2pack(float a, float b)
{
    return (uint32_t)__half_as_ushort(__float2half_rn(a)) |
           ((uint32_t)__half_as_ushort(__float2half_rn(b)) << 16);
}

/* ------------------------------------------------------------------ */
/* RoPE table                                                          */
/* ------------------------------------------------------------------ */
__global__ void __launch_bounds__(256) rope_table()
{
    const int idx = blockIdx.x * 256 + threadIdx.x;
    if (idx >= TSEQ * 32) return;
    const int t = idx >> 5, i = idx & 31;
    const double inv = pow(10000.0, -(double)i / 32.0);
    double sd, cd;
    sincos((double)t * inv, &sd, &cd);
    g_cosT[idx] = (float)cd;
    g_sinT[idx] = (float)sd;
}

/* ------------------------------------------------------------------ */
/* Batched fp32 -> fp16                                                */
/* ------------------------------------------------------------------ */
struct SplitJob { const float* src; __half *h; int n; };
struct SplitJobs { SplitJob j[9]; };

__global__ void __launch_bounds__(256) split_many(SplitJobs js)
{
    const SplitJob J = js.j[blockIdx.y];
    const int i = (blockIdx.x * 256 + threadIdx.x) << 2;
    if (i >= J.n) return;
    float4 v = *(const float4*)(J.src + i);
    uint2 hp;
    hp.x = hf2pack(v.x, v.y);  hp.y = hf2pack(v.z, v.w);
    *(uint2*)(J.h + i) = hp;
}

/* ------------------------------------------------------------------ */
/* Fused multi-segment fp16 tensor-core GEMM, BK=64.                   */
/* HASLO=1: C=(Ah+Al)@B, 2-stage.  HASLO=0: C=Ah@B, 3-stage.           */
/* Epilogue modes: 0=fp32, 1=fp16 hi/lo split, 2=content-perm,         */
/*                 3=rope-perm (in-register RoPE).                     */
/* ------------------------------------------------------------------ */
struct GSeg {
    const __half *Ah, *Al;
    int lda;
    const __half *Bh;
    float* Cf;                /* mode 0 */
    __half *Ch, *Cl;          /* mode 1 */
    __half *Dp;               /* mode 2/3 dst (Q/K/V) */
    float scale;
    int N, K, tile0, mode, dshift;
};
struct GSegs { GSeg s[4]; int n; };

/* A tile: 128 rows x 8 chunks(16B) = 128x64 fp16 */
__device__ __forceinline__ uint32_t offA64(int r, int c)
{ return (uint32_t)(((r << 3) + (c ^ (r & 7))) << 4); }
/* B tile: 64 rows x 16 chunks(16B) = 64x128 fp16 */
__device__ __forceinline__ uint32_t offB16(int r, int c)
{ return (uint32_t)(((r << 4) + (c ^ (r & 7))) << 4); }

template<bool HASLO>
__global__ void __launch_bounds__(256, 2) gemm_fused(GSegs segs)
{
    constexpr int      NSTG  = HASLO ? 2 : 3;
    constexpr uint32_t A_LO  = 16384;
    constexpr uint32_t B_OFF = HASLO ? 32768 : 16384;
    constexpr uint32_t STAGE = HASLO ? 49152 : 32768;

    extern __shared__ char dsm[];
    const uint32_t sb = (uint32_t)__cvta_generic_to_shared(dsm);

    const int tid  = threadIdx.x;
    const int lane = tid & 31;
    const int warp = tid >> 5;
    const int wm   = (warp >> 1) << 5;
    const int wn   = (warp & 1) << 6;
    const int bm   = blockIdx.y << 7;

    GSeg sg = segs.s[0];
#pragma unroll
    for (int i = 1; i < 4; i++)
        if (i < segs.n && (int)blockIdx.x >= segs.s[i].tile0) sg = segs.s[i];
    const int bn  = ((int)blockIdx.x - sg.tile0) << 7;
    const int lda = sg.lda, ldb = sg.N, K = sg.K;

    const int ar = tid >> 3, ac = tid & 7;
    const int br = tid >> 4, bc = tid & 15;

    const __half* gAh = sg.Ah + (size_t)(bm + ar) * lda + ac * 8;
    const __half* gAl = HASLO ? sg.Al + (size_t)(bm + ar) * lda + ac * 8 : nullptr;
    const __half* gBh = sg.Bh + (size_t)br * ldb + bn + bc * 8;

    float acc[2][8][4];
#pragma unroll
    for (int mt = 0; mt < 2; mt++)
#pragma unroll
        for (int nt = 0; nt < 8; nt++)
#pragma unroll
            for (int i = 0; i < 4; i++) acc[mt][nt][i] = 0.f;

    const int nk = K >> 6;

    auto load_stage = [&](int st, int k0) {
        const uint32_t s0 = sb + st * STAGE;
        const __half* pAh = gAh + k0;
#pragma unroll
        for (int p = 0; p < 4; p++) {
            const uint32_t ao = offA64(ar + (p << 5), ac);
            CPA16(s0 + ao, pAh + (size_t)(p << 5) * lda);
            if (HASLO)
                CPA16(s0 + A_LO + ao, gAl + k0 + (size_t)(p << 5) * lda);
        }
        const __half* pBh = gBh + (size_t)k0 * ldb;
#pragma unroll
        for (int p = 0; p < 4; p++) {
            const uint32_t bo = offB16(br + (p << 4), bc);
            CPA16(s0 + B_OFF + bo, pBh + (size_t)(p << 4) * ldb);
        }
    };

    load_stage(0, 0);
    CPA_COMMIT();
    if (!HASLO && nk > 1) { load_stage(1, 64); CPA_COMMIT(); }

    for (int it = 0; it < nk; it++) {
        if (it + NSTG - 1 < nk && (HASLO || it > 0 || NSTG == 2)) {
            /* for 3-stage, stages 0,1 preloaded; start loading at it=0 -> stage 2 */
        }
        if (HASLO) {
            if (it + 1 < nk) { load_stage((it + 1) & 1, (it + 1) << 6); CPA_COMMIT(); }
            if (it + 1 < nk) CPA_WAIT1(); else CPA_WAIT0();
        } else {
            if (it + 2 < nk) { load_stage((it + 2) % 3, (it + 2) << 6); CPA_COMMIT(); }
            if (it + 2 < nk)      CPA_WAIT2();
            else if (it + 1 < nk) CPA_WAIT1();
            else                  CPA_WAIT0();
        }
        __syncthreads();

        const uint32_t s0 = sb + (it % NSTG) * STAGE;
#pragma unroll
        for (int ks = 0; ks < 4; ks++) {
            uint32_t ah[2][4], al_[2][4];
#pragma unroll
            for (int mt = 0; mt < 2; mt++) {
                const int rowA   = wm + (mt << 4) + (lane & 15);
                const int chunkA = (ks << 1) + (lane >> 4);
                const uint32_t ad = s0 + offA64(rowA, chunkA);
                LDSM4(ah[mt][0], ah[mt][1], ah[mt][2], ah[mt][3], ad);
                if (HASLO)
                    LDSM4(al_[mt][0], al_[mt][1], al_[mt][2], al_[mt][3],
                          ad + A_LO);
            }
#pragma unroll
            for (int np = 0; np < 4; np++) {
                const int rowB   = (ks << 4) + (lane & 15);
                const int chunkB = (wn >> 3) + (lane >> 4) + (np << 1);
                const uint32_t bd = s0 + B_OFF + offB16(rowB, chunkB);
                uint32_t h0, h1, h2, h3;
                LDSM4T(h0, h1, h2, h3, bd);
#pragma unroll
                for (int mt = 0; mt < 2; mt++) {
                    MMA_F16(acc[mt][2 * np],     ah[mt],  h0, h1);
                    MMA_F16(acc[mt][2 * np + 1], ah[mt],  h2, h3);
                    if (HASLO) {
                        MMA_F16(acc[mt][2 * np],     al_[mt], h0, h1);
                        MMA_F16(acc[mt][2 * np + 1], al_[mt], h2, h3);
                    }
                }
            }
        }
        __syncthreads();
    }

    const int erow = lane >> 2;
    const int ecol = (lane & 3) << 1;

    if (sg.mode == 0) {
#pragma unroll
        for (int mt = 0; mt < 2; mt++)
#pragma unroll
            for (int nt = 0; nt < 8; nt++) {
                const int r = bm + wm + (mt << 4) + erow;
                const int c = bn + wn + (nt << 3) + ecol;
                *(float2*)(sg.Cf + (size_t)r * ldb + c) =
                    make_float2(acc[mt][nt][0], acc[mt][nt][1]);
                *(float2*)(sg.Cf + (size_t)(r + 8) * ldb + c) =
                    make_float2(acc[mt][nt][2], acc[mt][nt][3]);
            }
    } else if (sg.mode == 1) {
#pragma unroll
        for (int mt = 0; mt < 2; mt++)
#pragma unroll
            for (int nt = 0; nt < 8; nt++) {
                const int r = bm + wm + (mt << 4) + erow;
                const int c = bn + wn + (nt << 3) + ecol;
#pragma unroll
                for (int hh = 0; hh < 2; hh++) {
                    const float v0 = acc[mt][nt][2 * hh];
                    const float v1 = acc[mt][nt][2 * hh + 1];
                    const float h0 = __half2float(__float2half_rn(v0));
                    const float h1 = __half2float(__float2half_rn(v1));
                    const size_t idx = (size_t)(r + 8 * hh) * ldb + c;
                    *(uint32_t*)(sg.Ch + idx) = hf2pack(v0, v1);
                    *(uint32_t*)(sg.Cl + idx) = hf2pack(v0 - h0, v1 - h1);
                }
            }
    } else if (sg.mode == 2) {
        /* content-perm: head = c>>dshift, d = c & mask, dst [h][t][128] */
        const int ds = sg.dshift, msk = (1 << ds) - 1;
        const float sc = sg.scale;
#pragma unroll
        for (int mt = 0; mt < 2; mt++)
#pragma unroll
            for (int nt = 0; nt < 8; nt++) {
                const int c = bn + wn + (nt << 3) + ecol;
                const int hd = c >> ds, d = c & msk;
#pragma unroll
                for (int hh = 0; hh < 2; hh++) {
                    const int r = bm + wm + (mt << 4) + erow + 8 * hh;
                    const float v0 = acc[mt][nt][2 * hh] * sc;
                    const float v1 = acc[mt][nt][2 * hh + 1] * sc;
                    const size_t idx = ((size_t)hd * TSEQ + r) * DHEAD + d;
                    *(uint32_t*)(sg.Dp + idx) = hf2pack(v0, v1);
                }
            }
    } else {
        /* rope-perm: pairs (nt, nt+4); j = c&63 < 32; dst d = 64+j / 96+j */
        const float sc = sg.scale;
#pragma unroll
        for (int mt = 0; mt < 2; mt++)
#pragma unroll
            for (int nt = 0; nt < 4; nt++) {
                const int c  = bn + wn + (nt << 3) + ecol;
                const int hd = c >> 6, j = c & 63;   /* j in [0,30] even */
#pragma unroll
                for (int hh = 0; hh < 2; hh++) {
                    const int r = bm + wm + (mt << 4) + erow + 8 * hh;
                    const float x1a = acc[mt][nt][2 * hh];
                    const float x1b = acc[mt][nt][2 * hh + 1];
                    const float x2a = acc[mt][nt + 4][2 * hh];
                    const float x2b = acc[mt][nt + 4][2 * hh + 1];
                    const float c0 = g_cosT[r * 32 + j];
                    const float s0 = g_sinT[r * 32 + j];
                    const float c1 = g_cosT[r * 32 + j + 1];
                    const float s1 = g_sinT[r * 32 + j + 1];
                    const float o1a = (x1a * c0 - x2a * s0) * sc;
                    const float o1b = (x1b * c1 - x2b * s1) * sc;
                    const float o2a = (x1a * s0 + x2a * c0) * sc;
                    const float o2b = (x1b * s1 + x2b * c1) * sc;
                    const size_t base = ((size_t)hd * TSEQ + r) * DHEAD;
                    *(uint32_t*)(sg.Dp + base + 64 + j) = hf2pack(o1a, o1b);
                    *(uint32_t*)(sg.Dp + base + 96 + j) = hf2pack(o2a, o2b);
                }
            }
    }
}

/* ------------------------------------------------------------------ */
/* fp16 tensor-core causal flash attention (unchanged from R15).       */
/* ------------------------------------------------------------------ */
__device__ __forceinline__ uint32_t offV(int r, int c)
{ return (uint32_t)(((r << 4) + (c ^ (r & 7))) << 4); }

__global__ void __launch_bounds__(128) attn_mma()
{
    extern __shared__ char dsm[];
    const uint32_t sb = (uint32_t)__cvta_generic_to_shared(dsm);

    const int h    = blockIdx.y;
    const int qblk = 31 - (int)blockIdx.x;
    const int qb   = qblk << 6;
    const int tid  = threadIdx.x;
    const int lane = tid & 31;
    const int warp = tid >> 5;
    const int w16  = warp << 4;

    const __half* Qb = g_Q + (size_t)h * TSEQ * DHEAD;
    const __half* Kb = g_K + (size_t)h * TSEQ * DHEAD;
    const __half* Vb = g_V + (size_t)h * TSEQ * DHEAD;

    const int sr = tid >> 4;
    const int sc = tid & 15;

#pragma unroll
    for (int p = 0; p < 8; p++) {
        const int r = sr + (p << 3);
        CPA16(sb + offV(r, sc), Qb + (size_t)(qb + r) * DHEAD + sc * 8);
    }
    CPA_COMMIT(); CPA_WAIT0();
    __syncthreads();

    uint32_t qf[8][4];
#pragma unroll
    for (int ks = 0; ks < 8; ks++) {
        const uint32_t ad = offV(w16 + (lane & 15), (ks << 1) + (lane >> 4));
        LDSM4(qf[ks][0], qf[ks][1], qf[ks][2], qf[ks][3], sb + ad);
    }
    __syncthreads();

    float O[16][4];
#pragma unroll
    for (int nt = 0; nt < 16; nt++)
#pragma unroll
        for (int i = 0; i < 4; i++) O[nt][i] = 0.f;
    float m0 = -1e30f, m1 = -1e30f, l0 = 0.f, l1 = 0.f;

    const int ntiles = qblk + 1;
    const int row0 = qb + w16 + (lane >> 2);
    const int row1 = row0 + 8;

    auto load_kv = [&](int b, int kt) {
        const int kb = kt << 6;
        const uint32_t s0 = sb + b * 32768;
#pragma unroll
        for (int p = 0; p < 8; p++) {
            const int r = sr + (p << 3);
            const size_t gi = (size_t)(kb + r) * DHEAD + sc * 8;
            const uint32_t so = offV(r, sc);
            CPA16(s0 + so,         Kb + gi);
            CPA16(s0 + 16384 + so, Vb + gi);
        }
    };

    load_kv(0, 0); CPA_COMMIT();

    for (int kt = 0; kt < ntiles; kt++) {
        const int kb = kt << 6;
        if (kt + 1 < ntiles) { load_kv((kt + 1) & 1, kt + 1); CPA_COMMIT(); }
        if (kt + 1 < ntiles) CPA_WAIT1(); else CPA_WAIT0();
        __syncthreads();

        const uint32_t kbase = sb + (kt & 1) * 32768;
        const uint32_t vbase = kbase + 16384;

        float S[8][4];
#pragma unroll
        for (int nt = 0; nt < 8; nt++)
#pragma unroll
            for (int i = 0; i < 4; i++) S[nt][i] = 0.f;

#pragma unroll
        for (int ntp = 0; ntp < 4; ntp++) {
#pragma unroll
            for (int ks = 0; ks < 8; ks++) {
                const uint32_t ad = offV((ntp << 4) + (lane & 15),
                                         (ks << 1) + (lane >> 4));
                uint32_t k0, k1, k2, k3;
                LDSM4(k0, k1, k2, k3, kbase + ad);
                MMA_F16(S[2 * ntp],     qf[ks], k0, k2);
                MMA_F16(S[2 * ntp + 1], qf[ks], k1, k3);
            }
        }

        if (kb == qb) {
#pragma unroll
            for (int nt = 0; nt < 8; nt++) {
                const int key = kb + (nt << 3) + ((lane & 3) << 1);
                if (key > row0)     S[nt][0] = -1e30f;
                if (key + 1 > row0) S[nt][1] = -1e30f;
                if (key > row1)     S[nt][2] = -1e30f;
                if (key + 1 > row1) S[nt][3] = -1e30f;
            }
        }

        float mx0 = -1e30f, mx1 = -1e30f;
#pragma unroll
        for (int nt = 0; nt < 8; nt++) {
            mx0 = fmaxf(mx0, fmaxf(S[nt][0], S[nt][1]));
            mx1 = fmaxf(mx1, fmaxf(S[nt][2], S[nt][3]));
        }
        mx0 = fmaxf(mx0, __shfl_xor_sync(0xffffffffu, mx0, 1));
        mx0 = fmaxf(mx0, __shfl_xor_sync(0xffffffffu, mx0, 2));
        mx1 = fmaxf(mx1, __shfl_xor_sync(0xffffffffu, mx1, 1));
        mx1 = fmaxf(mx1, __shfl_xor_sync(0xffffffffu, mx1, 2));

        const float m0n = fmaxf(m0, mx0), m1n = fmaxf(m1, mx1);
        const float a0 = __expf(m0 - m0n), a1 = __expf(m1 - m1n);
        m0 = m0n; m1 = m1n;

        uint32_t aP[4][4];
        float ps0 = 0.f, ps1 = 0.f;
#pragma unroll
        for (int nt = 0; nt < 8; nt++) {
            const float p0 = __expf(S[nt][0] - m0n);
            const float p1 = __expf(S[nt][1] - m0n);
            const float p2 = __expf(S[nt][2] - m1n);
            const float p3 = __expf(S[nt][3] - m1n);
            ps0 += p0 + p1; ps1 += p2 + p3;
            const int kk = nt >> 1;
            const int e  = (nt & 1) << 1;
            aP[kk][e]     = hf2pack(p0, p1);
            aP[kk][e + 1] = hf2pack(p2, p3);
        }
        ps0 += __shfl_xor_sync(0xffffffffu, ps0, 1);
        ps0 += __shfl_xor_sync(0xffffffffu, ps0, 2);
        ps1 += __shfl_xor_sync(0xffffffffu, ps1, 1);
        ps1 += __shfl_xor_sync(0xffffffffu, ps1, 2);
        l0 = l0 * a0 + ps0;
        l1 = l1 * a1 + ps1;

#pragma unroll
        for (int nt = 0; nt < 16; nt++) {
            O[nt][0] *= a0; O[nt][1] *= a0;
            O[nt][2] *= a1; O[nt][3] *= a1;
        }

#pragma unroll
        for (int kk = 0; kk < 4; kk++) {
#pragma unroll
            for (int ntp = 0; ntp < 8; ntp++) {
                const uint32_t ad = offV((kk << 4) + (lane & 15),
                                         (ntp << 1) + (lane >> 4));
                uint32_t v0, v1, v2, v3;
                LDSM4T(v0, v1, v2, v3, vbase + ad);
                MMA_F16(O[2 * ntp],     aP[kk], v0, v1);
                MMA_F16(O[2 * ntp + 1], aP[kk], v2, v3);
            }
        }
        __syncthreads();
    }

    const float inv0 = 1.0f / l0, inv1 = 1.0f / l1;
#pragma unroll
    for (int nt = 0; nt < 16; nt++) {
        const int d = (nt << 3) + ((lane & 3) << 1);
        const float v0 = O[nt][0] * inv0, v1 = O[nt][1] * inv0;
        const float v2 = O[nt][2] * inv1, v3 = O[nt][3] * inv1;
        const size_t i0 = (size_t)row0 * DMODEL + h * DHEAD + d;
        const size_t i1 = (size_t)row1 * DMODEL + h * DHEAD + d;
        *(uint32_t*)(g_O + i0) = hf2pack(v0, v1);
        *(uint32_t*)(g_O + i1) = hf2pack(v2, v3);
    }
}

/* ------------------------------------------------------------------ */
extern "C" void kernel_launch(void* const* d_in, const int* in_sizes, int n_in,
                              void* d_out, int out_size)
{
    const float* x        = (const float*)d_in[0];
    const float* Wq_down  = (const float*)d_in[1];
    const float* Wq_up    = (const float*)d_in[2];
    const float* Wq_rope  = (const float*)d_in[3];
    const float* Wkv_down = (const float*)d_in[4];
    const float* Wk_up    = (const float*)d_in[5];
    const float* Wv_up    = (const float*)d_in[6];
    const float* Wk_rope  = (const float*)d_in[7];
    const float* Wo       = (const float*)d_in[8];
    float* out = (float*)d_out;

    __half *xf, *qdh, *qdl, *kvh, *kvl, *Of, *Qf, *Kf, *Vf;
    __half *wqd, *wqu, *wqr, *wkd, *wku, *wvu, *wkr, *wo;
    cudaGetSymbolAddress((void**)&xf, g_x);
    cudaGetSymbolAddress((void**)&qdh, g_qdh); cudaGetSymbolAddress((void**)&qdl, g_qdl);
    cudaGetSymbolAddress((void**)&kvh, g_kvh); cudaGetSymbolAddress((void**)&kvl, g_kvl);
    cudaGetSymbolAddress((void**)&Of, g_O);
    cudaGetSymbolAddress((void**)&Qf, g_Q);
    cudaGetSymbolAddress((void**)&Kf, g_K);
    cudaGetSymbolAddress((void**)&Vf, g_V);
    cudaGetSymbolAddress((void**)&wqd, g_wqd); cudaGetSymbolAddress((void**)&wqu, g_wqu);
    cudaGetSymbolAddress((void**)&wqr, g_wqr); cudaGetSymbolAddress((void**)&wkd, g_wkd);
    cudaGetSymbolAddress((void**)&wku, g_wku); cudaGetSymbolAddress((void**)&wvu, g_wvu);
    cudaGetSymbolAddress((void**)&wkr, g_wkr); cudaGetSymbolAddress((void**)&wo,  g_wo);

    cudaFuncSetAttribute(gemm_fused<true>,
                         cudaFuncAttributeMaxDynamicSharedMemorySize, 98304);
    cudaFuncSetAttribute(gemm_fused<false>,
                         cudaFuncAttributeMaxDynamicSharedMemorySize, 98304);
    cudaFuncSetAttribute(attn_mma,
                         cudaFuncAttributeMaxDynamicSharedMemorySize, 65536);

    /* 0. rope table (needed by GEMM1 epilogue) */
    rope_table<<<256, 256>>>();

    /* 1. convert x + weights to fp16 */
    SplitJobs js;
    js.j[0] = { x,        xf,  TSEQ * 2048 };
    js.j[1] = { Wq_down,  wqd, 2048 * 512  };
    js.j[2] = { Wq_up,    wqu, 512 * 1024  };
    js.j[3] = { Wq_rope,  wqr, 2048 * 1024 };
    js.j[4] = { Wkv_down, wkd, 2048 * 512  };
    js.j[5] = { Wk_up,    wku, 512 * 1024  };
    js.j[6] = { Wv_up,    wvu, 512 * 2048  };
    js.j[7] = { Wk_rope,  wkr, 2048 * 1024 };
    js.j[8] = { Wo,       wo,  2048 * 2048 };
    split_many<<<dim3(4096, 9), 256>>>(js);

    /* 2. GEMM1 (single-A, 3-stage): qd/kv split; qr/kr rope->Q/K */
    {
        GSegs g; g.n = 4;
        g.s[0] = { xf, nullptr, 2048, wqd, nullptr, qdh, qdl, nullptr,
                   1.f,  512, 2048, 0,  1, 0 };
        g.s[1] = { xf, nullptr, 2048, wkd, nullptr, kvh, kvl, nullptr,
                   1.f,  512, 2048, 4,  1, 0 };
        g.s[2] = { xf, nullptr, 2048, wqr, nullptr, nullptr, nullptr, Qf,
                   SCALE_ATT, 1024, 2048, 8,  3, 6 };
        g.s[3] = { xf, nullptr, 2048, wkr, nullptr, nullptr, nullptr, Kf,
                   1.f, 1024, 2048, 16, 3, 6 };
        gemm_fused<false><<<dim3(24, 16), 256, 98304>>>(g);
    }

    /* 3. GEMM2 (split-A, 2-stage): qc->Q, kc->K, vu->V */
    {
        GSegs g; g.n = 3;
        g.s[0] = { qdh, qdl, 512, wqu, nullptr, nullptr, nullptr, Qf,
                   SCALE_ATT, 1024, 512, 0,  2, 6 };
        g.s[1] = { kvh, kvl, 512, wku, nullptr, nullptr, nullptr, Kf,
                   1.f, 1024, 512, 8,  2, 6 };
        g.s[2] = { kvh, kvl, 512, wvu, nullptr, nullptr, nullptr, Vf,
                   1.f, 2048, 512, 16, 2, 7 };
        g.s[3] = g.s[0];
        gemm_fused<true><<<dim3(32, 16), 256, 98304>>>(g);
    }

    /* 4. fp16 tensor-core causal attention */
    attn_mma<<<dim3(32, NH), 128, 65536>>>();

    /* 5. GEMM3 (single-A, 3-stage): O @ Wo -> out (fp32) */
    {
        GSegs g; g.n = 1;
        g.s[0] = { Of, nullptr, 2048, wo, out, nullptr, nullptr, nullptr,
                   1.f, 2048, 2048, 0, 0, 0 };
        g.s[1] = g.s[0]; g.s[2] = g.s[0]; g.s[3] = g.s[0];
        gemm_fused<false><<<dim3(16, 16), 256, 98304>>>(g);
    }
}

// round 17
// speedup vs baseline: 2.2776x; 1.0834x over previous
#include <cuda_runtime.h>
#include <cuda_bf16.h>
#include <cuda_fp16.h>
#include <math.h>
#include <stdint.h>

#define TSEQ   2048
#define DMODEL 2048
#define NH     16
#define DHEAD  128
#define DROPE  64
#define DCONT  64
#define SCALE_ATT 0.08838834764831845f  /* 1/sqrt(128) */

/* ------------------------------------------------------------------ */
/* Scratch (device globals)                                            */
/* ------------------------------------------------------------------ */
__device__ float g_cosT[TSEQ * 32];
__device__ float g_sinT[TSEQ * 32];

/* attention operands (fp16), [h][t][d] */
__device__ __half g_Q[NH * TSEQ * DHEAD];
__device__ __half g_K[NH * TSEQ * DHEAD];
__device__ __half g_V[NH * TSEQ * DHEAD];

/* fp16 GEMM operands (all single fp16) */
__device__ __half g_x [TSEQ * 2048];
__device__ __half g_qd[TSEQ * 512];
__device__ __half g_kv[TSEQ * 512];
__device__ __half g_O [TSEQ * 2048];
__device__ __half g_wqd[2048 * 512];
__device__ __half g_wqu[512 * 1024];
__device__ __half g_wqr[2048 * 1024];
__device__ __half g_wkd[2048 * 512];
__device__ __half g_wku[512 * 1024];
__device__ __half g_wvu[512 * 2048];
__device__ __half g_wkr[2048 * 1024];
__device__ __half g_wo [2048 * 2048];

/* ------------------------------------------------------------------ */
/* asm helpers                                                         */
/* ------------------------------------------------------------------ */
#define CPA16(dst, src)                                                    \
    asm volatile("cp.async.cg.shared.global [%0], [%1], 16;"               \
                 :: "r"(dst), "l"(src))
#define CPA_COMMIT() asm volatile("cp.async.commit_group;")
#define CPA_WAIT2()  asm volatile("cp.async.wait_group 2;")
#define CPA_WAIT1()  asm volatile("cp.async.wait_group 1;")
#define CPA_WAIT0()  asm volatile("cp.async.wait_group 0;")

#define LDSM4(r0, r1, r2, r3, addr)                                        \
    asm volatile("ldmatrix.sync.aligned.m8n8.x4.shared.b16 {%0,%1,%2,%3}, [%4];" \
                 : "=r"(r0), "=r"(r1), "=r"(r2), "=r"(r3) : "r"(addr))
#define LDSM4T(r0, r1, r2, r3, addr)                                       \
    asm volatile("ldmatrix.sync.aligned.m8n8.x4.trans.shared.b16 {%0,%1,%2,%3}, [%4];" \
                 : "=r"(r0), "=r"(r1), "=r"(r2), "=r"(r3) : "r"(addr))
#define MMA_F16(c, a, b0, b1)                                              \
    asm volatile("mma.sync.aligned.m16n8k16.row.col.f32.f16.f16.f32 "      \
                 "{%0,%1,%2,%3}, {%4,%5,%6,%7}, {%8,%9}, {%0,%1,%2,%3};"   \
                 : "+f"(c[0]), "+f"(c[1]), "+f"(c[2]), "+f"(c[3])          \
                 : "r"(a[0]), "r"(a[1]), "r"(a[2]), "r"(a[3]),             \
                   "r"(b0), "r"(b1))

__device__ __forceinline__ uint32_t hf2pack(float a, float b)
{
    return (uint32_t)__half_as_ushort(__float2half_rn(a)) |
           ((uint32_t)__half_as_ushort(__float2half_rn(b)) << 16);
}

/* ------------------------------------------------------------------ */
/* RoPE table                                                          */
/* ------------------------------------------------------------------ */
__global__ void __launch_bounds__(256) rope_table()
{
    const int idx = blockIdx.x * 256 + threadIdx.x;
    if (idx >= TSEQ * 32) return;
    const int t = idx >> 5, i = idx & 31;
    const double inv = pow(10000.0, -(double)i / 32.0);
    double sd, cd;
    sincos((double)t * inv, &sd, &cd);
    g_cosT[idx] = (float)cd;
    g_sinT[idx] = (float)sd;
}

/* ------------------------------------------------------------------ */
/* Batched fp32 -> fp16                                                */
/* ------------------------------------------------------------------ */
struct SplitJob { const float* src; __half *h; int n; };
struct SplitJobs { SplitJob j[9]; };

__global__ void __launch_bounds__(256) split_many(SplitJobs js)
{
    const SplitJob J = js.j[blockIdx.y];
    const int i = (blockIdx.x * 256 + threadIdx.x) << 2;
    if (i >= J.n) return;
    float4 v = *(const float4*)(J.src + i);
    uint2 hp;
    hp.x = hf2pack(v.x, v.y);  hp.y = hf2pack(v.z, v.w);
    *(uint2*)(J.h + i) = hp;
}

/* ------------------------------------------------------------------ */
/* Fused multi-segment fp16 tensor-core GEMM, BK=64, single-A.         */
/* BM=BN=128, 256 threads, 3-stage cp.async, 2 CTAs/SM (96KB).         */
/* Epilogue modes: 0=fp32, 1=fp16 plain, 2=content-perm, 3=rope-perm.  */
/* ------------------------------------------------------------------ */
struct GSeg {
    const __half *Ah;
    int lda;
    const __half *Bh;
    float* Cf;                /* mode 0 */
    __half *Ch;               /* mode 1 */
    __half *Dp;               /* mode 2/3 dst (Q/K/V) */
    float scale;
    int N, K, tile0, mode, dshift;
};
struct GSegs { GSeg s[4]; int n; };

#define B_OFF 16384u
#define STAGE 32768u

/* A tile: 128 rows x 8 chunks(16B) = 128x64 fp16 */
__device__ __forceinline__ uint32_t offA64(int r, int c)
{ return (uint32_t)(((r << 3) + (c ^ (r & 7))) << 4); }
/* B tile: 64 rows x 16 chunks(16B) = 64x128 fp16 */
__device__ __forceinline__ uint32_t offB16(int r, int c)
{ return (uint32_t)(((r << 4) + (c ^ (r & 7))) << 4); }

__global__ void __launch_bounds__(256, 2) gemm_fused(GSegs segs)
{
    extern __shared__ char dsm[];
    const uint32_t sb = (uint32_t)__cvta_generic_to_shared(dsm);

    const int tid  = threadIdx.x;
    const int lane = tid & 31;
    const int warp = tid >> 5;
    const int wm   = (warp >> 1) << 5;
    const int wn   = (warp & 1) << 6;
    const int bm   = blockIdx.y << 7;

    GSeg sg = segs.s[0];
#pragma unroll
    for (int i = 1; i < 4; i++)
        if (i < segs.n && (int)blockIdx.x >= segs.s[i].tile0) sg = segs.s[i];
    const int bn  = ((int)blockIdx.x - sg.tile0) << 7;
    const int lda = sg.lda, ldb = sg.N, K = sg.K;

    const int ar = tid >> 3, ac = tid & 7;
    const int br = tid >> 4, bc = tid & 15;

    const __half* gAh = sg.Ah + (size_t)(bm + ar) * lda + ac * 8;
    const __half* gBh = sg.Bh + (size_t)br * ldb + bn + bc * 8;

    float acc[2][8][4];
#pragma unroll
    for (int mt = 0; mt < 2; mt++)
#pragma unroll
        for (int nt = 0; nt < 8; nt++)
#pragma unroll
            for (int i = 0; i < 4; i++) acc[mt][nt][i] = 0.f;

    const int nk = K >> 6;

    auto load_stage = [&](int st, int k0) {
        const uint32_t s0 = sb + st * STAGE;
        const __half* pAh = gAh + k0;
#pragma unroll
        for (int p = 0; p < 4; p++) {
            const uint32_t ao = offA64(ar + (p << 5), ac);
            CPA16(s0 + ao, pAh + (size_t)(p << 5) * lda);
        }
        const __half* pBh = gBh + (size_t)k0 * ldb;
#pragma unroll
        for (int p = 0; p < 4; p++) {
            const uint32_t bo = offB16(br + (p << 4), bc);
            CPA16(s0 + B_OFF + bo, pBh + (size_t)(p << 4) * ldb);
        }
    };

    load_stage(0, 0);
    CPA_COMMIT();
    if (nk > 1) { load_stage(1, 64); CPA_COMMIT(); }

    for (int it = 0; it < nk; it++) {
        if (it + 2 < nk) { load_stage((it + 2) % 3, (it + 2) << 6); CPA_COMMIT(); }
        if (it + 2 < nk)      CPA_WAIT2();
        else if (it + 1 < nk) CPA_WAIT1();
        else                  CPA_WAIT0();
        __syncthreads();

        const uint32_t s0 = sb + (it % 3) * STAGE;
#pragma unroll
        for (int ks = 0; ks < 4; ks++) {
            uint32_t ah[2][4];
#pragma unroll
            for (int mt = 0; mt < 2; mt++) {
                const int rowA   = wm + (mt << 4) + (lane & 15);
                const int chunkA = (ks << 1) + (lane >> 4);
                const uint32_t ad = s0 + offA64(rowA, chunkA);
                LDSM4(ah[mt][0], ah[mt][1], ah[mt][2], ah[mt][3], ad);
            }
#pragma unroll
            for (int np = 0; np < 4; np++) {
                const int rowB   = (ks << 4) + (lane & 15);
                const int chunkB = (wn >> 3) + (lane >> 4) + (np << 1);
                const uint32_t bd = s0 + B_OFF + offB16(rowB, chunkB);
                uint32_t h0, h1, h2, h3;
                LDSM4T(h0, h1, h2, h3, bd);
#pragma unroll
                for (int mt = 0; mt < 2; mt++) {
                    MMA_F16(acc[mt][2 * np],     ah[mt], h0, h1);
                    MMA_F16(acc[mt][2 * np + 1], ah[mt], h2, h3);
                }
            }
        }
        __syncthreads();
    }

    const int erow = lane >> 2;
    const int ecol = (lane & 3) << 1;

    if (sg.mode == 0) {
#pragma unroll
        for (int mt = 0; mt < 2; mt++)
#pragma unroll
            for (int nt = 0; nt < 8; nt++) {
                const int r = bm + wm + (mt << 4) + erow;
                const int c = bn + wn + (nt << 3) + ecol;
                *(float2*)(sg.Cf + (size_t)r * ldb + c) =
                    make_float2(acc[mt][nt][0], acc[mt][nt][1]);
                *(float2*)(sg.Cf + (size_t)(r + 8) * ldb + c) =
                    make_float2(acc[mt][nt][2], acc[mt][nt][3]);
            }
    } else if (sg.mode == 1) {
#pragma unroll
        for (int mt = 0; mt < 2; mt++)
#pragma unroll
            for (int nt = 0; nt < 8; nt++) {
                const int r = bm + wm + (mt << 4) + erow;
                const int c = bn + wn + (nt << 3) + ecol;
#pragma unroll
                for (int hh = 0; hh < 2; hh++) {
                    const float v0 = acc[mt][nt][2 * hh];
                    const float v1 = acc[mt][nt][2 * hh + 1];
                    const size_t idx = (size_t)(r + 8 * hh) * ldb + c;
                    *(uint32_t*)(sg.Ch + idx) = hf2pack(v0, v1);
                }
            }
    } else if (sg.mode == 2) {
        const int ds = sg.dshift, msk = (1 << ds) - 1;
        const float sc = sg.scale;
#pragma unroll
        for (int mt = 0; mt < 2; mt++)
#pragma unroll
            for (int nt = 0; nt < 8; nt++) {
                const int c = bn + wn + (nt << 3) + ecol;
                const int hd = c >> ds, d = c & msk;
#pragma unroll
                for (int hh = 0; hh < 2; hh++) {
                    const int r = bm + wm + (mt << 4) + erow + 8 * hh;
                    const float v0 = acc[mt][nt][2 * hh] * sc;
                    const float v1 = acc[mt][nt][2 * hh + 1] * sc;
                    const size_t idx = ((size_t)hd * TSEQ + r) * DHEAD + d;
                    *(uint32_t*)(sg.Dp + idx) = hf2pack(v0, v1);
                }
            }
    } else {
        /* rope-perm: pairs (nt, nt+4); j = c&63 < 32; dst d = 64+j / 96+j */
        const float sc = sg.scale;
#pragma unroll
        for (int mt = 0; mt < 2; mt++)
#pragma unroll
            for (int nt = 0; nt < 4; nt++) {
                const int c  = bn + wn + (nt << 3) + ecol;
                const int hd = c >> 6, j = c & 63;
#pragma unroll
                for (int hh = 0; hh < 2; hh++) {
                    const int r = bm + wm + (mt << 4) + erow + 8 * hh;
                    const float x1a = acc[mt][nt][2 * hh];
                    const float x1b = acc[mt][nt][2 * hh + 1];
                    const float x2a = acc[mt][nt + 4][2 * hh];
                    const float x2b = acc[mt][nt + 4][2 * hh + 1];
                    const float c0 = g_cosT[r * 32 + j];
                    const float s0 = g_sinT[r * 32 + j];
                    const float c1 = g_cosT[r * 32 + j + 1];
                    const float s1 = g_sinT[r * 32 + j + 1];
                    const float o1a = (x1a * c0 - x2a * s0) * sc;
                    const float o1b = (x1b * c1 - x2b * s1) * sc;
                    const float o2a = (x1a * s0 + x2a * c0) * sc;
                    const float o2b = (x1b * s1 + x2b * c1) * sc;
                    const size_t base = ((size_t)hd * TSEQ + r) * DHEAD;
                    *(uint32_t*)(sg.Dp + base + 64 + j) = hf2pack(o1a, o1b);
                    *(uint32_t*)(sg.Dp + base + 96 + j) = hf2pack(o2a, o2b);
                }
            }
    }
}

/* ------------------------------------------------------------------ */
/* fp16 tensor-core causal flash attention (unchanged).                */
/* ------------------------------------------------------------------ */
__device__ __forceinline__ uint32_t offV(int r, int c)
{ return (uint32_t)(((r << 4) + (c ^ (r & 7))) << 4); }

__global__ void __launch_bounds__(128) attn_mma()
{
    extern __shared__ char dsm[];
    const uint32_t sb = (uint32_t)__cvta_generic_to_shared(dsm);

    const int h    = blockIdx.y;
    const int qblk = 31 - (int)blockIdx.x;
    const int qb   = qblk << 6;
    const int tid  = threadIdx.x;
    const int lane = tid & 31;
    const int warp = tid >> 5;
    const int w16  = warp << 4;

    const __half* Qb = g_Q + (size_t)h * TSEQ * DHEAD;
    const __half* Kb = g_K + (size_t)h * TSEQ * DHEAD;
    const __half* Vb = g_V + (size_t)h * TSEQ * DHEAD;

    const int sr = tid >> 4;
    const int sc = tid & 15;

#pragma unroll
    for (int p = 0; p < 8; p++) {
        const int r = sr + (p << 3);
        CPA16(sb + offV(r, sc), Qb + (size_t)(qb + r) * DHEAD + sc * 8);
    }
    CPA_COMMIT(); CPA_WAIT0();
    __syncthreads();

    uint32_t qf[8][4];
#pragma unroll
    for (int ks = 0; ks < 8; ks++) {
        const uint32_t ad = offV(w16 + (lane & 15), (ks << 1) + (lane >> 4));
        LDSM4(qf[ks][0], qf[ks][1], qf[ks][2], qf[ks][3], sb + ad);
    }
    __syncthreads();

    float O[16][4];
#pragma unroll
    for (int nt = 0; nt < 16; nt++)
#pragma unroll
        for (int i = 0; i < 4; i++) O[nt][i] = 0.f;
    float m0 = -1e30f, m1 = -1e30f, l0 = 0.f, l1 = 0.f;

    const int ntiles = qblk + 1;
    const int row0 = qb + w16 + (lane >> 2);
    const int row1 = row0 + 8;

    auto load_kv = [&](int b, int kt) {
        const int kb = kt << 6;
        const uint32_t s0 = sb + b * 32768;
#pragma unroll
        for (int p = 0; p < 8; p++) {
            const int r = sr + (p << 3);
            const size_t gi = (size_t)(kb + r) * DHEAD + sc * 8;
            const uint32_t so = offV(r, sc);
            CPA16(s0 + so,         Kb + gi);
            CPA16(s0 + 16384 + so, Vb + gi);
        }
    };

    load_kv(0, 0); CPA_COMMIT();

    for (int kt = 0; kt < ntiles; kt++) {
        const int kb = kt << 6;
        if (kt + 1 < ntiles) { load_kv((kt + 1) & 1, kt + 1); CPA_COMMIT(); }
        if (kt + 1 < ntiles) CPA_WAIT1(); else CPA_WAIT0();
        __syncthreads();

        const uint32_t kbase = sb + (kt & 1) * 32768;
        const uint32_t vbase = kbase + 16384;

        float S[8][4];
#pragma unroll
        for (int nt = 0; nt < 8; nt++)
#pragma unroll
            for (int i = 0; i < 4; i++) S[nt][i] = 0.f;

#pragma unroll
        for (int ntp = 0; ntp < 4; ntp++) {
#pragma unroll
            for (int ks = 0; ks < 8; ks++) {
                const uint32_t ad = offV((ntp << 4) + (lane & 15),
                                         (ks << 1) + (lane >> 4));
                uint32_t k0, k1, k2, k3;
                LDSM4(k0, k1, k2, k3, kbase + ad);
                MMA_F16(S[2 * ntp],     qf[ks], k0, k2);
                MMA_F16(S[2 * ntp + 1], qf[ks], k1, k3);
            }
        }

        if (kb == qb) {
#pragma unroll
            for (int nt = 0; nt < 8; nt++) {
                const int key = kb + (nt << 3) + ((lane & 3) << 1);
                if (key > row0)     S[nt][0] = -1e30f;
                if (key + 1 > row0) S[nt][1] = -1e30f;
                if (key > row1)     S[nt][2] = -1e30f;
                if (key + 1 > row1) S[nt][3] = -1e30f;
            }
        }

        float mx0 = -1e30f, mx1 = -1e30f;
#pragma unroll
        for (int nt = 0; nt < 8; nt++) {
            mx0 = fmaxf(mx0, fmaxf(S[nt][0], S[nt][1]));
            mx1 = fmaxf(mx1, fmaxf(S[nt][2], S[nt][3]));
        }
        mx0 = fmaxf(mx0, __shfl_xor_sync(0xffffffffu, mx0, 1));
        mx0 = fmaxf(mx0, __shfl_xor_sync(0xffffffffu, mx0, 2));
        mx1 = fmaxf(mx1, __shfl_xor_sync(0xffffffffu, mx1, 1));
        mx1 = fmaxf(mx1, __shfl_xor_sync(0xffffffffu, mx1, 2));

        const float m0n = fmaxf(m0, mx0), m1n = fmaxf(m1, mx1);
        const float a0 = __expf(m0 - m0n), a1 = __expf(m1 - m1n);
        m0 = m0n; m1 = m1n;

        uint32_t aP[4][4];
        float ps0 = 0.f, ps1 = 0.f;
#pragma unroll
        for (int nt = 0; nt < 8; nt++) {
            const float p0 = __expf(S[nt][0] - m0n);
            const float p1 = __expf(S[nt][1] - m0n);
            const float p2 = __expf(S[nt][2] - m1n);
            const float p3 = __expf(S[nt][3] - m1n);
            ps0 += p0 + p1; ps1 += p2 + p3;
            const int kk = nt >> 1;
            const int e  = (nt & 1) << 1;
            aP[kk][e]     = hf2pack(p0, p1);
            aP[kk][e + 1] = hf2pack(p2, p3);
        }
        ps0 += __shfl_xor_sync(0xffffffffu, ps0, 1);
        ps0 += __shfl_xor_sync(0xffffffffu, ps0, 2);
        ps1 += __shfl_xor_sync(0xffffffffu, ps1, 1);
        ps1 += __shfl_xor_sync(0xffffffffu, ps1, 2);
        l0 = l0 * a0 + ps0;
        l1 = l1 * a1 + ps1;

#pragma unroll
        for (int nt = 0; nt < 16; nt++) {
            O[nt][0] *= a0; O[nt][1] *= a0;
            O[nt][2] *= a1; O[nt][3] *= a1;
        }

#pragma unroll
        for (int kk = 0; kk < 4; kk++) {
#pragma unroll
            for (int ntp = 0; ntp < 8; ntp++) {
                const uint32_t ad = offV((kk << 4) + (lane & 15),
                                         (ntp << 1) + (lane >> 4));
                uint32_t v0, v1, v2, v3;
                LDSM4T(v0, v1, v2, v3, vbase + ad);
                MMA_F16(O[2 * ntp],     aP[kk], v0, v1);
                MMA_F16(O[2 * ntp + 1], aP[kk], v2, v3);
            }
        }
        __syncthreads();
    }

    const float inv0 = 1.0f / l0, inv1 = 1.0f / l1;
#pragma unroll
    for (int nt = 0; nt < 16; nt++) {
        const int d = (nt << 3) + ((lane & 3) << 1);
        const float v0 = O[nt][0] * inv0, v1 = O[nt][1] * inv0;
        const float v2 = O[nt][2] * inv1, v3 = O[nt][3] * inv1;
        const size_t i0 = (size_t)row0 * DMODEL + h * DHEAD + d;
        const size_t i1 = (size_t)row1 * DMODEL + h * DHEAD + d;
        *(uint32_t*)(g_O + i0) = hf2pack(v0, v1);
        *(uint32_t*)(g_O + i1) = hf2pack(v2, v3);
    }
}

/* ------------------------------------------------------------------ */
extern "C" void kernel_launch(void* const* d_in, const int* in_sizes, int n_in,
                              void* d_out, int out_size)
{
    const float* x        = (const float*)d_in[0];
    const float* Wq_down  = (const float*)d_in[1];
    const float* Wq_up    = (const float*)d_in[2];
    const float* Wq_rope  = (const float*)d_in[3];
    const float* Wkv_down = (const float*)d_in[4];
    const float* Wk_up    = (const float*)d_in[5];
    const float* Wv_up    = (const float*)d_in[6];
    const float* Wk_rope  = (const float*)d_in[7];
    const float* Wo       = (const float*)d_in[8];
    float* out = (float*)d_out;

    __half *xf, *qd, *kv, *Of, *Qf, *Kf, *Vf;
    __half *wqd, *wqu, *wqr, *wkd, *wku, *wvu, *wkr, *wo;
    cudaGetSymbolAddress((void**)&xf, g_x);
    cudaGetSymbolAddress((void**)&qd, g_qd);
    cudaGetSymbolAddress((void**)&kv, g_kv);
    cudaGetSymbolAddress((void**)&Of, g_O);
    cudaGetSymbolAddress((void**)&Qf, g_Q);
    cudaGetSymbolAddress((void**)&Kf, g_K);
    cudaGetSymbolAddress((void**)&Vf, g_V);
    cudaGetSymbolAddress((void**)&wqd, g_wqd); cudaGetSymbolAddress((void**)&wqu, g_wqu);
    cudaGetSymbolAddress((void**)&wqr, g_wqr); cudaGetSymbolAddress((void**)&wkd, g_wkd);
    cudaGetSymbolAddress((void**)&wku, g_wku); cudaGetSymbolAddress((void**)&wvu, g_wvu);
    cudaGetSymbolAddress((void**)&wkr, g_wkr); cudaGetSymbolAddress((void**)&wo,  g_wo);

    cudaFuncSetAttribute(gemm_fused,
                         cudaFuncAttributeMaxDynamicSharedMemorySize, 98304);
    cudaFuncSetAttribute(attn_mma,
                         cudaFuncAttributeMaxDynamicSharedMemorySize, 65536);

    /* 0. rope table */
    rope_table<<<256, 256>>>();

    /* 1. convert x + weights to fp16 */
    SplitJobs js;
    js.j[0] = { x,        xf,  TSEQ * 2048 };
    js.j[1] = { Wq_down,  wqd, 2048 * 512  };
    js.j[2] = { Wq_up,    wqu, 512 * 1024  };
    js.j[3] = { Wq_rope,  wqr, 2048 * 1024 };
    js.j[4] = { Wkv_down, wkd, 2048 * 512  };
    js.j[5] = { Wk_up,    wku, 512 * 1024  };
    js.j[6] = { Wv_up,    wvu, 512 * 2048  };
    js.j[7] = { Wk_rope,  wkr, 2048 * 1024 };
    js.j[8] = { Wo,       wo,  2048 * 2048 };
    split_many<<<dim3(4096, 9), 256>>>(js);

    /* 2. GEMM1: qd/kv (fp16 plain) ; qr/kr (rope -> Q/K) */
    {
        GSegs g; g.n = 4;
        g.s[0] = { xf, 2048, wqd, nullptr, qd, nullptr,
                   1.f,  512, 2048, 0,  1, 0 };
        g.s[1] = { xf, 2048, wkd, nullptr, kv, nullptr,
                   1.f,  512, 2048, 4,  1, 0 };
        g.s[2] = { xf, 2048, wqr, nullptr, nullptr, Qf,
                   SCALE_ATT, 1024, 2048, 8,  3, 6 };
        g.s[3] = { xf, 2048, wkr, nullptr, nullptr, Kf,
                   1.f, 1024, 2048, 16, 3, 6 };
        gemm_fused<<<dim3(24, 16), 256, 98304>>>(g);
    }

    /* 3. GEMM2 (single-A now): qc->Q, kc->K, vu->V */
    {
        GSegs g; g.n = 3;
        g.s[0] = { qd, 512, wqu, nullptr, nullptr, Qf,
                   SCALE_ATT, 1024, 512, 0,  2, 6 };
        g.s[1] = { kv, 512, wku, nullptr, nullptr, Kf,
                   1.f, 1024, 512, 8,  2, 6 };
        g.s[2] = { kv, 512, wvu, nullptr, nullptr, Vf,
                   1.f, 2048, 512, 16, 2, 7 };
        g.s[3] = g.s[0];
        gemm_fused<<<dim3(32, 16), 256, 98304>>>(g);
    }

    /* 4. fp16 tensor-core causal attention */
    attn_mma<<<dim3(32, NH), 128, 65536>>>();

    /* 5. GEMM3: O @ Wo -> out (fp32) */
    {
        GSegs g; g.n = 1;
        g.s[0] = { Of, 2048, wo, out, nullptr, nullptr,
                   1.f, 2048, 2048, 0, 0, 0 };
        g.s[1] = g.s[0]; g.s[2] = g.s[0]; g.s[3] = g.s[0];
        gemm_fused<<<dim3(16, 16), 256, 98304>>>(g);
    }
}